// round 2
// baseline (speedup 1.0000x reference)
#include <cuda_runtime.h>
#include <math.h>

#define NANCH 2304
#define NPROP 2000

// ---------------- scratch (device globals; no allocation) ----------------
__device__ float g_feat[64 * 256];
__device__ float g_hrpn[64 * 256];
__device__ float g_scores[NANCH];
__device__ float g_boxes[NANCH * 4];
__device__ int   g_order[NANCH];
__device__ float g_props[NPROP * 4];
__device__ int   g_valid[NPROP];
__device__ float g_flat[NPROP * 3136];
__device__ float g_h1[NPROP * 512];
__device__ float g_h2[NPROP * 512];
__device__ float g_rlogits[NPROP * 2];
__device__ float g_rdeltas[NPROP * 4];
__device__ float g_dets[NPROP * 4];
__device__ float g_dscores[NPROP];
__device__ float g_s2[NPROP];
__device__ int   g_order2[NPROP];
__device__ float g_keep2f[NPROP];
__device__ float g_masks[NPROP * 196];

// ---------------- backbone: conv 3->64, k16 s16 VALID, relu ----------------
__global__ void k_backbone(const float* __restrict__ x, const float* __restrict__ w,
                           const float* __restrict__ b) {
    __shared__ float patch[768];
    int pos = blockIdx.x;              // h*16+w
    int h = pos >> 4, wq = pos & 15;
    int tid = threadIdx.x;             // 64
    for (int k = tid; k < 768; k += 64) {
        int ic = k >> 8, r = k & 255, iy = r >> 4, ix = r & 15;
        patch[k] = x[ic * 65536 + (h * 16 + iy) * 256 + (wq * 16 + ix)];
    }
    __syncthreads();
    int oc = tid;
    const float* wp = w + oc * 768;
    float acc = b[oc];
#pragma unroll 8
    for (int k = 0; k < 768; k++) acc += patch[k] * wp[k];
    g_feat[oc * 256 + pos] = fmaxf(acc, 0.f);
}

// ---------------- rpn conv 3x3 SAME, relu ----------------
__global__ void k_rpnconv(const float* __restrict__ w, const float* __restrict__ b) {
    int pos = blockIdx.x;
    int y = pos >> 4, xq = pos & 15;
    int oc = threadIdx.x;
    float acc = b[oc];
    const float* wp = w + oc * 576;
    for (int ic = 0; ic < 64; ic++) {
        const float* fb = g_feat + ic * 256;
        const float* wb = wp + ic * 9;
#pragma unroll
        for (int ky = 0; ky < 3; ky++) {
            int yy = y + ky - 1;
            if (yy < 0 || yy > 15) continue;
#pragma unroll
            for (int kx = 0; kx < 3; kx++) {
                int xx = xq + kx - 1;
                if (xx < 0 || xx > 15) continue;
                acc += fb[yy * 16 + xx] * wb[ky * 3 + kx];
            }
        }
    }
    g_hrpn[oc * 256 + pos] = fmaxf(acc, 0.f);
}

// -------- rpn heads (1x1), anchors, softmax score, decode, clip --------
__global__ void k_heads1(const float* __restrict__ wc, const float* __restrict__ bc,
                         const float* __restrict__ wb, const float* __restrict__ bb,
                         float* __restrict__ o_logits, float* __restrict__ o_deltas,
                         float* __restrict__ o_anch) {
    int i = blockIdx.x * blockDim.x + threadIdx.x;
    if (i >= NANCH) return;
    int cell = i / 9, a = i % 9;
    float l0 = bc[a * 2], l1 = bc[a * 2 + 1];
    float d0 = bb[a * 4], d1 = bb[a * 4 + 1], d2 = bb[a * 4 + 2], d3 = bb[a * 4 + 3];
    for (int ic = 0; ic < 64; ic++) {
        float f = g_hrpn[ic * 256 + cell];
        l0 += f * wc[(a * 2) * 64 + ic];
        l1 += f * wc[(a * 2 + 1) * 64 + ic];
        d0 += f * wb[(a * 4) * 64 + ic];
        d1 += f * wb[(a * 4 + 1) * 64 + ic];
        d2 += f * wb[(a * 4 + 2) * 64 + ic];
        d3 += f * wb[(a * 4 + 3) * 64 + ic];
    }
    o_logits[i * 2] = l0; o_logits[i * 2 + 1] = l1;
    o_deltas[i * 4] = d0; o_deltas[i * 4 + 1] = d1;
    o_deltas[i * 4 + 2] = d2; o_deltas[i * 4 + 3] = d3;
    float m = fmaxf(l0, l1);
    float e0 = expf(l0 - m), e1 = expf(l1 - m);
    g_scores[i] = e1 / (e0 + e1);

    const float S[3] = {32.f, 64.f, 128.f};
    const float R[3] = {0.5f, 1.f, 2.f};
    int h = cell >> 4, wq = cell & 15;
    float s = S[a / 3], r = R[a % 3];
    float ws = s * sqrtf(r), hs = s / sqrtf(r);
    float cx = (wq + 0.5f) * 16.f, cy = (h + 0.5f) * 16.f;
    float ax1 = cx - ws * 0.5f, ay1 = cy - hs * 0.5f;
    float ax2 = cx + ws * 0.5f, ay2 = cy + hs * 0.5f;
    o_anch[i * 4] = ax1; o_anch[i * 4 + 1] = ay1;
    o_anch[i * 4 + 2] = ax2; o_anch[i * 4 + 3] = ay2;

    float aw = ax2 - ax1, ah = ay2 - ay1;
    float acx = ax1 + 0.5f * aw, acy = ay1 + 0.5f * ah;
    float ncx = acx + d0 * aw, ncy = acy + d1 * ah;
    float nw = aw * expf(d2), nh = ah * expf(d3);
    float bx1 = ncx - 0.5f * nw, by1 = ncy - 0.5f * nh;
    float bx2 = ncx + 0.5f * nw, by2 = ncy + 0.5f * nh;
    g_boxes[i * 4]     = fminf(fmaxf(bx1, 0.f), 255.f);
    g_boxes[i * 4 + 1] = fminf(fmaxf(by1, 0.f), 255.f);
    g_boxes[i * 4 + 2] = fminf(fmaxf(bx2, 0.f), 255.f);
    g_boxes[i * 4 + 3] = fminf(fmaxf(by2, 0.f), 255.f);
}

// -------- single-block bitonic sort: descending value, stable by index --------
template <int SIZE>
__global__ void k_sort(const float* __restrict__ sc, int n, int* __restrict__ ord) {
    __shared__ unsigned long long k[SIZE];
    int tid = threadIdx.x;
    for (int i = tid; i < SIZE; i += 1024) {
        if (i < n) {
            unsigned u = __float_as_uint(sc[i]);
            unsigned o = (u & 0x80000000u) ? ~u : (u | 0x80000000u); // monotonic asc
            k[i] = ((unsigned long long)(~o) << 32) | (unsigned)i;   // desc + idx tiebreak
        } else k[i] = 0xFFFFFFFFFFFFFFFFULL;
    }
    __syncthreads();
    for (int kk = 2; kk <= SIZE; kk <<= 1) {
        for (int j = kk >> 1; j > 0; j >>= 1) {
            for (int i = tid; i < SIZE; i += 1024) {
                int ixj = i ^ j;
                if (ixj > i) {
                    bool up = ((i & kk) == 0);
                    unsigned long long a = k[i], b = k[ixj];
                    if ((a > b) == up) { k[i] = b; k[ixj] = a; }
                }
            }
            __syncthreads();
        }
    }
    for (int i = tid; i < n; i += 1024) ord[i] = (int)(k[i] & 0xFFFFFFFFu);
}

// -------- NMS stage 1 (thr 0.5) + stable kept-first selection of 2000 proposals ----
__global__ void k_nms1(float* __restrict__ o_props) {
    extern __shared__ unsigned char smem_raw[];
    const int n = NANCH;
    float4* b = (float4*)smem_raw;
    float* area = (float*)(b + n);
    int* sk = (int*)(area + n);
    int* src = sk + n;                 // NPROP
    int tid = threadIdx.x;
    for (int i = tid; i < n; i += 1024) {
        int o = g_order[i];
        float4 bb = make_float4(g_boxes[o * 4], g_boxes[o * 4 + 1],
                                g_boxes[o * 4 + 2], g_boxes[o * 4 + 3]);
        b[i] = bb;
        area[i] = fmaxf(bb.z - bb.x, 0.f) * fmaxf(bb.w - bb.y, 0.f);
        sk[i] = 1;
    }
    __syncthreads();
    for (int i = 0; i < n; i++) {
        if (sk[i]) {
            float4 bi = b[i];
            float ai = area[i];
            for (int j = i + 1 + tid; j < n; j += 1024) {
                if (sk[j]) {
                    float xx1 = fmaxf(bi.x, b[j].x), yy1 = fmaxf(bi.y, b[j].y);
                    float xx2 = fminf(bi.z, b[j].z), yy2 = fminf(bi.w, b[j].w);
                    float inter = fmaxf(xx2 - xx1, 0.f) * fmaxf(yy2 - yy1, 0.f);
                    float iou = inter / (ai + area[j] - inter + 1e-8f);
                    if (iou > 0.5f) sk[j] = 0;
                }
            }
        }
        __syncthreads();
    }
    // stable partition on warp 0: kept first (score order), then non-kept
    if (tid < 32) {
        const int CH = n / 32;         // 72
        int beg = tid * CH, end = beg + CH;
        int cnt = 0;
        for (int i = beg; i < end; i++) cnt += sk[i];
        int xsc = cnt;
        for (int off = 1; off < 32; off <<= 1) {
            int v = __shfl_up_sync(0xffffffffu, xsc, off);
            if ((int)tid >= off) xsc += v;
        }
        int excl = xsc - cnt;
        int total = __shfl_sync(0xffffffffu, xsc, 31);
        int kpos = excl;
        int npos = total + (beg - excl);
        for (int i = beg; i < end; i++) {
            int pos = sk[i] ? kpos++ : npos++;
            if (pos < NPROP) src[pos] = i;
        }
    }
    __syncthreads();
    for (int p = tid; p < NPROP; p += 1024) {
        int i = src[p];
        int v = sk[i];
        float4 bb = b[i];
        float px1 = v ? bb.x : 0.f, py1 = v ? bb.y : 0.f;
        float px2 = v ? bb.z : 0.f, py2 = v ? bb.w : 0.f;
        g_props[p * 4] = px1; g_props[p * 4 + 1] = py1;
        g_props[p * 4 + 2] = px2; g_props[p * 4 + 3] = py2;
        o_props[p * 4] = px1; o_props[p * 4 + 1] = py1;
        o_props[p * 4 + 2] = px2; o_props[p * 4 + 3] = py2;
        g_valid[p] = v;
    }
}

// -------- fused per-ROI: crop+bilinear, 2x2 maxpool->flat, mask conv3x3+relu, 1x1 ----
__global__ void k_roi(const float* __restrict__ wm1, const float* __restrict__ bm1,
                      const float* __restrict__ wm2, const float* __restrict__ bm2,
                      float* __restrict__ omask) {
    extern __shared__ unsigned char smem_raw[];
    float* s_crop = (float*)smem_raw;    // 12544
    float* s_m = s_crop + 12544;         // 12544
    float* s_wy = s_m + 12544;           // 14
    float* s_wx = s_wy + 14;             // 14
    int* s_y0 = (int*)(s_wx + 14);
    int* s_y1 = s_y0 + 14;
    int* s_x0 = s_y1 + 14;
    int* s_x1 = s_x0 + 14;
    int p = blockIdx.x, tid = threadIdx.x;

    if (tid < 28) {
        int t = tid % 14;
        float tt = (float)t / 13.0f;
        if (tid < 14) {
            float y1n = g_props[p * 4 + 1] / 255.0f, y2n = g_props[p * 4 + 3] / 255.0f;
            float fy = (y1n + (y2n - y1n) * tt) * 15.0f;
            float y0f = fminf(fmaxf(floorf(fy), 0.f), 15.f);
            int y0 = (int)y0f;
            s_y0[t] = y0; s_y1[t] = min(y0 + 1, 15); s_wy[t] = fy - y0f;
        } else {
            float x1n = g_props[p * 4 + 0] / 255.0f, x2n = g_props[p * 4 + 2] / 255.0f;
            float fx = (x1n + (x2n - x1n) * tt) * 15.0f;
            float x0f = fminf(fmaxf(floorf(fx), 0.f), 15.f);
            int x0 = (int)x0f;
            s_x0[t] = x0; s_x1[t] = min(x0 + 1, 15); s_wx[t] = fx - x0f;
        }
    }
    __syncthreads();

    for (int idx = tid; idx < 12544; idx += 256) {
        int c = idx / 196, r2 = idx % 196, ty = r2 / 14, tx = r2 % 14;
        const float* fb = g_feat + c * 256;
        int y0 = s_y0[ty], y1 = s_y1[ty], x0 = s_x0[tx], x1 = s_x1[tx];
        float wy = s_wy[ty], wx = s_wx[tx];
        float f00 = fb[y0 * 16 + x0], f01 = fb[y0 * 16 + x1];
        float f10 = fb[y1 * 16 + x0], f11 = fb[y1 * 16 + x1];
        float top = f00 * (1.f - wx) + f01 * wx;
        float bot = f10 * (1.f - wx) + f11 * wx;
        s_crop[idx] = top * (1.f - wy) + bot * wy;
    }
    __syncthreads();

    // pool 2x2 -> flat [64*49]
    for (int idx = tid; idx < 64 * 49; idx += 256) {
        int c = idx / 49, r2 = idx % 49, py = r2 / 7, px = r2 % 7;
        const float* cb = s_crop + c * 196 + py * 28 + px * 2;
        float v = fmaxf(fmaxf(cb[0], cb[1]), fmaxf(cb[14], cb[15]));
        g_flat[(size_t)p * 3136 + idx] = v;
    }

    // mask conv 3x3 + relu; one (oc, row) per task, 14-wide register row
    for (int task = tid; task < 896; task += 256) {
        int oc = task / 14, y = task % 14;
        float acc[14];
        float bv = bm1[oc];
#pragma unroll
        for (int xq = 0; xq < 14; xq++) acc[xq] = bv;
        for (int ic = 0; ic < 64; ic++) {
            const float* wb = wm1 + (oc * 64 + ic) * 9;
            const float* cbase = s_crop + ic * 196;
#pragma unroll
            for (int ky = 0; ky < 3; ky++) {
                int yin = y + ky - 1;
                if (yin < 0 || yin > 13) continue;
                const float* row = cbase + yin * 14;
                float r[16];
                r[0] = 0.f; r[15] = 0.f;
#pragma unroll
                for (int j = 0; j < 14; j++) r[j + 1] = row[j];
                float w0 = wb[ky * 3], w1 = wb[ky * 3 + 1], w2 = wb[ky * 3 + 2];
#pragma unroll
                for (int xq = 0; xq < 14; xq++)
                    acc[xq] += r[xq] * w0 + r[xq + 1] * w1 + r[xq + 2] * w2;
            }
        }
        float* mrow = s_m + oc * 196 + y * 14;
#pragma unroll
        for (int xq = 0; xq < 14; xq++) mrow[xq] = fmaxf(acc[xq], 0.f);
    }
    __syncthreads();

    // 1x1 conv 64->1 (mask logits)
    for (int pos = tid; pos < 196; pos += 256) {
        float acc = bm2[0];
#pragma unroll 8
        for (int oc = 0; oc < 64; oc++) acc += s_m[oc * 196 + pos] * wm2[oc];
        omask[(size_t)p * 196 + pos] = acc;
        g_masks[(size_t)p * 196 + pos] = acc;
    }
}

// -------- tiled SGEMM C = relu(A[M,K] x B[K,N] + bias), 64x64x16, 4x4 microtile ----
__global__ void k_gemm_relu(const float* __restrict__ Ax, const float* __restrict__ Bx,
                            const float* __restrict__ bias, float* __restrict__ C,
                            int M, int N, int K) {
    __shared__ float As[16][68];
    __shared__ float Bs[16][64];
    int tid = threadIdx.x;
    int tx = tid & 15, ty = tid >> 4;
    int bm = blockIdx.y * 64, bn = blockIdx.x * 64;
    float acc[4][4];
#pragma unroll
    for (int i = 0; i < 4; i++)
#pragma unroll
        for (int j = 0; j < 4; j++) acc[i][j] = 0.f;

    for (int k0 = 0; k0 < K; k0 += 16) {
#pragma unroll
        for (int i = 0; i < 4; i++) {
            int idx = tid + i * 256;
            int r = idx >> 4, c = idx & 15;
            int row = bm + r;
            As[c][r] = (row < M) ? Ax[(size_t)row * K + k0 + c] : 0.f;
        }
#pragma unroll
        for (int i = 0; i < 4; i++) {
            int idx = tid + i * 256;
            int kr = idx >> 6, col = idx & 63;
            Bs[kr][col] = Bx[(size_t)(k0 + kr) * N + bn + col];
        }
        __syncthreads();
#pragma unroll
        for (int k = 0; k < 16; k++) {
            float4 a4 = *(const float4*)&As[k][ty * 4];
            float4 b4 = *(const float4*)&Bs[k][tx * 4];
            float av[4] = {a4.x, a4.y, a4.z, a4.w};
            float bv[4] = {b4.x, b4.y, b4.z, b4.w};
#pragma unroll
            for (int i2 = 0; i2 < 4; i2++)
#pragma unroll
                for (int j2 = 0; j2 < 4; j2++) acc[i2][j2] += av[i2] * bv[j2];
        }
        __syncthreads();
    }
#pragma unroll
    for (int i2 = 0; i2 < 4; i2++) {
        int row = bm + ty * 4 + i2;
        if (row >= M) continue;
#pragma unroll
        for (int j2 = 0; j2 < 4; j2++) {
            int col = bn + tx * 4 + j2;
            C[(size_t)row * N + col] = fmaxf(acc[i2][j2] + bias[col], 0.f);
        }
    }
}

// -------- rcnn cls/box heads: 6 dot-products of K=512, one warp each --------
__global__ void k_rheads(const float* __restrict__ wrc, const float* __restrict__ brc,
                         const float* __restrict__ wrb, const float* __restrict__ brb,
                         float* __restrict__ o_log, float* __restrict__ o_del) {
    int p = blockIdx.x;
    int w = threadIdx.x >> 5, lane = threadIdx.x & 31;
    const float* hp = g_h2 + (size_t)p * 512;
    float s = 0.f;
    if (w < 2) {
        for (int k = lane; k < 512; k += 32) s += hp[k] * wrc[k * 2 + w];
    } else {
        int j = w - 2;
        for (int k = lane; k < 512; k += 32) s += hp[k] * wrb[k * 4 + j];
    }
    for (int off = 16; off > 0; off >>= 1) s += __shfl_down_sync(0xffffffffu, s, off);
    if (lane == 0) {
        if (w < 2) {
            float v = s + brc[w];
            o_log[p * 2 + w] = v;
            g_rlogits[p * 2 + w] = v;
        } else {
            int j = w - 2;
            float v = s + brb[j];
            o_del[p * 4 + j] = v;
            g_rdeltas[p * 4 + j] = v;
        }
    }
}

// -------- decode stage 2: det scores, dets, s2 --------
__global__ void k_decode2() {
    int p = blockIdx.x * blockDim.x + threadIdx.x;
    if (p >= NPROP) return;
    float l0 = g_rlogits[p * 2], l1 = g_rlogits[p * 2 + 1];
    float m = fmaxf(l0, l1);
    float e0 = expf(l0 - m), e1 = expf(l1 - m);
    float sc = e1 / (e0 + e1);
    g_dscores[p] = sc;
    float x1 = g_props[p * 4], y1 = g_props[p * 4 + 1];
    float x2 = g_props[p * 4 + 2], y2 = g_props[p * 4 + 3];
    float w = x2 - x1, h = y2 - y1;
    float cx = x1 + 0.5f * w, cy = y1 + 0.5f * h;
    float d0 = g_rdeltas[p * 4], d1 = g_rdeltas[p * 4 + 1];
    float d2 = g_rdeltas[p * 4 + 2], d3 = g_rdeltas[p * 4 + 3];
    float ncx = cx + d0 * w, ncy = cy + d1 * h;
    float nw = w * expf(d2), nh = h * expf(d3);
    g_dets[p * 4]     = fminf(fmaxf(ncx - 0.5f * nw, 0.f), 255.f);
    g_dets[p * 4 + 1] = fminf(fmaxf(ncy - 0.5f * nh, 0.f), 255.f);
    g_dets[p * 4 + 2] = fminf(fmaxf(ncx + 0.5f * nw, 0.f), 255.f);
    g_dets[p * 4 + 3] = fminf(fmaxf(ncy + 0.5f * nh, 0.f), 255.f);
    g_s2[p] = g_valid[p] ? sc : -1.0f;
}

// -------- NMS stage 2 (thr 0.3) + final dets/scores/keep2 --------
__global__ void k_nms2(float* __restrict__ o_fdets, float* __restrict__ o_fsc,
                       float* __restrict__ o_keep) {
    extern __shared__ unsigned char smem_raw[];
    const int n = NPROP;
    float4* b = (float4*)smem_raw;
    float* area = (float*)(b + n);
    int* sk = (int*)(area + n);
    int tid = threadIdx.x;
    for (int i = tid; i < n; i += 1024) {
        int o = g_order2[i];
        float4 bb = make_float4(g_dets[o * 4], g_dets[o * 4 + 1],
                                g_dets[o * 4 + 2], g_dets[o * 4 + 3]);
        b[i] = bb;
        area[i] = fmaxf(bb.z - bb.x, 0.f) * fmaxf(bb.w - bb.y, 0.f);
        sk[i] = 1;
    }
    __syncthreads();
    for (int i = 0; i < n; i++) {
        if (sk[i]) {
            float4 bi = b[i];
            float ai = area[i];
            for (int j = i + 1 + tid; j < n; j += 1024) {
                if (sk[j]) {
                    float xx1 = fmaxf(bi.x, b[j].x), yy1 = fmaxf(bi.y, b[j].y);
                    float xx2 = fminf(bi.z, b[j].z), yy2 = fminf(bi.w, b[j].w);
                    float inter = fmaxf(xx2 - xx1, 0.f) * fmaxf(yy2 - yy1, 0.f);
                    float iou = inter / (ai + area[j] - inter + 1e-8f);
                    if (iou > 0.3f) sk[j] = 0;
                }
            }
        }
        __syncthreads();
    }
    for (int r = tid; r < n; r += 1024) {
        int o = g_order2[r];
        int k2 = sk[r] && g_valid[o];
        float kf = k2 ? 1.f : 0.f;
        float4 d = b[r];
        o_fdets[r * 4]     = k2 ? d.x : 0.f;
        o_fdets[r * 4 + 1] = k2 ? d.y : 0.f;
        o_fdets[r * 4 + 2] = k2 ? d.z : 0.f;
        o_fdets[r * 4 + 3] = k2 ? d.w : 0.f;
        o_fsc[r] = k2 ? g_dscores[o] : 0.f;
        if (o_keep) o_keep[r] = kf;
        g_keep2f[r] = kf;
    }
}

// -------- final masks: sigmoid(masks[order2]) * keep2 --------
__global__ void k_fmask(float* __restrict__ o) {
    int r = blockIdx.x, i = threadIdx.x;
    int oi = g_order2[r];
    float v = g_masks[(size_t)oi * 196 + i];
    float sgm = 1.f / (1.f + expf(-v));
    o[(size_t)r * 196 + i] = sgm * g_keep2f[r];
}

// ---------------- host ----------------
extern "C" void kernel_launch(void* const* d_in, const int* in_sizes, int n_in,
                              void* d_out, int out_size) {
    const float* x      = (const float*)d_in[0];
    const float* w_bb   = (const float*)d_in[1];
    const float* b_bb   = (const float*)d_in[2];
    const float* w_rpn  = (const float*)d_in[3];
    const float* b_rpn  = (const float*)d_in[4];
    const float* w_cls  = (const float*)d_in[5];
    const float* b_cls  = (const float*)d_in[6];
    const float* w_box  = (const float*)d_in[7];
    const float* b_box  = (const float*)d_in[8];
    const float* w_fc1  = (const float*)d_in[9];
    const float* b_fc1  = (const float*)d_in[10];
    const float* w_fc2  = (const float*)d_in[11];
    const float* b_fc2  = (const float*)d_in[12];
    const float* w_rcls = (const float*)d_in[13];
    const float* b_rcls = (const float*)d_in[14];
    const float* w_rbox = (const float*)d_in[15];
    const float* b_rbox = (const float*)d_in[16];
    const float* w_m1   = (const float*)d_in[17];
    const float* b_m1   = (const float*)d_in[18];
    const float* w_m2   = (const float*)d_in[19];
    const float* b_m2   = (const float*)d_in[20];
    float* out = (float*)d_out;

    // output offsets (tuple order, flattened)
    const size_t O_RPNL = 0, O_RPND = 4608, O_PROP = 13824, O_ANCH = 21824;
    const size_t O_RLOG = 31040, O_RDEL = 35040, O_RMSK = 43040;
    const size_t O_FDET = 435040, O_FMSK = 443040, O_FSC = 835040, O_KEEP = 837040;

    float *p_scores, *p_s2, *p_flat, *p_h1, *p_h2;
    int *p_order, *p_order2;
    cudaGetSymbolAddress((void**)&p_scores, g_scores);
    cudaGetSymbolAddress((void**)&p_order, g_order);
    cudaGetSymbolAddress((void**)&p_s2, g_s2);
    cudaGetSymbolAddress((void**)&p_order2, g_order2);
    cudaGetSymbolAddress((void**)&p_flat, g_flat);
    cudaGetSymbolAddress((void**)&p_h1, g_h1);
    cudaGetSymbolAddress((void**)&p_h2, g_h2);

    const int SMEM_NMS1 = NANCH * (16 + 4 + 4) + NPROP * 4;     // 63296
    const int SMEM_NMS2 = NPROP * (16 + 4 + 4);                 // 48000
    const int SMEM_ROI  = (12544 * 2 + 28) * 4 + 56 * 4;        // 100688
    cudaFuncSetAttribute(k_roi,  cudaFuncAttributeMaxDynamicSharedMemorySize, SMEM_ROI);
    cudaFuncSetAttribute(k_nms1, cudaFuncAttributeMaxDynamicSharedMemorySize, SMEM_NMS1);
    cudaFuncSetAttribute(k_nms2, cudaFuncAttributeMaxDynamicSharedMemorySize, SMEM_NMS2);

    k_backbone<<<256, 64>>>(x, w_bb, b_bb);
    k_rpnconv<<<256, 64>>>(w_rpn, b_rpn);
    k_heads1<<<18, 128>>>(w_cls, b_cls, w_box, b_box,
                          out + O_RPNL, out + O_RPND, out + O_ANCH);
    k_sort<4096><<<1, 1024>>>(p_scores, NANCH, p_order);
    k_nms1<<<1, 1024, SMEM_NMS1>>>(out + O_PROP);
    k_roi<<<NPROP, 256, SMEM_ROI>>>(w_m1, b_m1, w_m2, b_m2, out + O_RMSK);

    dim3 gfc(512 / 64, (NPROP + 63) / 64);
    k_gemm_relu<<<gfc, 256>>>(p_flat, w_fc1, b_fc1, p_h1, NPROP, 512, 3136);
    k_gemm_relu<<<gfc, 256>>>(p_h1, w_fc2, b_fc2, p_h2, NPROP, 512, 512);
    k_rheads<<<NPROP, 192>>>(w_rcls, b_rcls, w_rbox, b_rbox,
                             out + O_RLOG, out + O_RDEL);
    k_decode2<<<(NPROP + 255) / 256, 256>>>();
    k_sort<2048><<<1, 1024>>>(p_s2, NPROP, p_order2);
    float* o_keep = (out_size >= (int)(O_KEEP + NPROP)) ? (out + O_KEEP) : nullptr;
    k_nms2<<<1, 1024, SMEM_NMS2>>>(out + O_FDET, out + O_FSC, o_keep);
    k_fmask<<<NPROP, 196>>>(out + O_FMSK);
}

// round 3
// speedup vs baseline: 1.5090x; 1.5090x over previous
#include <cuda_runtime.h>
#include <math.h>

#define NANCH 2304
#define NPROP 2000
#define NW1 36
#define NW2 32

// ---------------- scratch (device globals; no allocation) ----------------
__device__ float g_feat[64 * 256];
__device__ float g_hrpn[64 * 256];
__device__ float g_scores[NANCH];
__device__ float g_boxes[NANCH * 4];
__device__ int   g_order[NANCH];
__device__ float g_props[NPROP * 4];
__device__ int   g_valid[NPROP];
__device__ float g_flat[NPROP * 3136];
__device__ float g_h1[NPROP * 512];
__device__ float g_h2[NPROP * 512];
__device__ float g_rlogits[NPROP * 2];
__device__ float g_rdeltas[NPROP * 4];
__device__ float g_dscores[NPROP];
__device__ float g_s2[NPROP];
__device__ int   g_order2[NPROP];
__device__ float g_keep2f[NPROP];
__device__ float g_masks[NPROP * 196];
__device__ float g_wpack[64 * 64 * 12];          // packed mask-conv weights
// NMS scratch
__device__ float4 g_sb1[NANCH];
__device__ float  g_sa1[NANCH];
__device__ unsigned long long g_mask1[(size_t)NANCH * NW1];
__device__ int    g_keep1[NANCH];
__device__ float4 g_sb2[NPROP];
__device__ float  g_sa2[NPROP];
__device__ unsigned long long g_mask2[(size_t)NPROP * NW2];
__device__ int    g_keep2a[NPROP];

// ---------------- backbone: conv 3->64, k16 s16 VALID, relu ----------------
__global__ void k_backbone(const float* __restrict__ x, const float* __restrict__ w,
                           const float* __restrict__ b) {
    __shared__ float patch[768];
    int pos = blockIdx.x;
    int h = pos >> 4, wq = pos & 15;
    int tid = threadIdx.x;
    for (int k = tid; k < 768; k += 64) {
        int ic = k >> 8, r = k & 255, iy = r >> 4, ix = r & 15;
        patch[k] = x[ic * 65536 + (h * 16 + iy) * 256 + (wq * 16 + ix)];
    }
    __syncthreads();
    int oc = tid;
    const float* wp = w + oc * 768;
    float acc = b[oc];
#pragma unroll 8
    for (int k = 0; k < 768; k++) acc += patch[k] * wp[k];
    g_feat[oc * 256 + pos] = fmaxf(acc, 0.f);
}

// ---------------- rpn conv 3x3 SAME, relu ----------------
__global__ void k_rpnconv(const float* __restrict__ w, const float* __restrict__ b) {
    int pos = blockIdx.x;
    int y = pos >> 4, xq = pos & 15;
    int oc = threadIdx.x;
    float acc = b[oc];
    const float* wp = w + oc * 576;
    for (int ic = 0; ic < 64; ic++) {
        const float* fb = g_feat + ic * 256;
        const float* wb = wp + ic * 9;
#pragma unroll
        for (int ky = 0; ky < 3; ky++) {
            int yy = y + ky - 1;
            if (yy < 0 || yy > 15) continue;
#pragma unroll
            for (int kx = 0; kx < 3; kx++) {
                int xx = xq + kx - 1;
                if (xx < 0 || xx > 15) continue;
                acc += fb[yy * 16 + xx] * wb[ky * 3 + kx];
            }
        }
    }
    g_hrpn[oc * 256 + pos] = fmaxf(acc, 0.f);
}

// -------- rpn heads (1x1), anchors, softmax score, decode, clip --------
__global__ void k_heads1(const float* __restrict__ wc, const float* __restrict__ bc,
                         const float* __restrict__ wb, const float* __restrict__ bb,
                         float* __restrict__ o_logits, float* __restrict__ o_deltas,
                         float* __restrict__ o_anch) {
    int i = blockIdx.x * blockDim.x + threadIdx.x;
    if (i >= NANCH) return;
    int cell = i / 9, a = i % 9;
    float l0 = bc[a * 2], l1 = bc[a * 2 + 1];
    float d0 = bb[a * 4], d1 = bb[a * 4 + 1], d2 = bb[a * 4 + 2], d3 = bb[a * 4 + 3];
    for (int ic = 0; ic < 64; ic++) {
        float f = g_hrpn[ic * 256 + cell];
        l0 += f * wc[(a * 2) * 64 + ic];
        l1 += f * wc[(a * 2 + 1) * 64 + ic];
        d0 += f * wb[(a * 4) * 64 + ic];
        d1 += f * wb[(a * 4 + 1) * 64 + ic];
        d2 += f * wb[(a * 4 + 2) * 64 + ic];
        d3 += f * wb[(a * 4 + 3) * 64 + ic];
    }
    o_logits[i * 2] = l0; o_logits[i * 2 + 1] = l1;
    o_deltas[i * 4] = d0; o_deltas[i * 4 + 1] = d1;
    o_deltas[i * 4 + 2] = d2; o_deltas[i * 4 + 3] = d3;
    float m = fmaxf(l0, l1);
    float e0 = expf(l0 - m), e1 = expf(l1 - m);
    g_scores[i] = e1 / (e0 + e1);

    const float S[3] = {32.f, 64.f, 128.f};
    const float R[3] = {0.5f, 1.f, 2.f};
    int h = cell >> 4, wq = cell & 15;
    float s = S[a / 3], r = R[a % 3];
    float ws = s * sqrtf(r), hs = s / sqrtf(r);
    float cx = (wq + 0.5f) * 16.f, cy = (h + 0.5f) * 16.f;
    float ax1 = cx - ws * 0.5f, ay1 = cy - hs * 0.5f;
    float ax2 = cx + ws * 0.5f, ay2 = cy + hs * 0.5f;
    o_anch[i * 4] = ax1; o_anch[i * 4 + 1] = ay1;
    o_anch[i * 4 + 2] = ax2; o_anch[i * 4 + 3] = ay2;

    float aw = ax2 - ax1, ah = ay2 - ay1;
    float acx = ax1 + 0.5f * aw, acy = ay1 + 0.5f * ah;
    float ncx = acx + d0 * aw, ncy = acy + d1 * ah;
    float nw = aw * expf(d2), nh = ah * expf(d3);
    g_boxes[i * 4]     = fminf(fmaxf(ncx - 0.5f * nw, 0.f), 255.f);
    g_boxes[i * 4 + 1] = fminf(fmaxf(ncy - 0.5f * nh, 0.f), 255.f);
    g_boxes[i * 4 + 2] = fminf(fmaxf(ncx + 0.5f * nw, 0.f), 255.f);
    g_boxes[i * 4 + 3] = fminf(fmaxf(ncy + 0.5f * nh, 0.f), 255.f);
}

// -------- pack mask-conv weights: [oc][ic][9] -> [oc][ic][12] (float4-aligned) ----
__global__ void k_packw(const float* __restrict__ w) {
    int i = blockIdx.x * blockDim.x + threadIdx.x;
    if (i >= 64 * 64 * 12) return;
    int pair = i / 12, q = i % 12;
    g_wpack[i] = (q < 9) ? w[pair * 9 + q] : 0.f;
}

// -------- single-block bitonic sort: descending value, stable by index --------
template <int SIZE>
__global__ void k_sort(const float* __restrict__ sc, int n, int* __restrict__ ord) {
    __shared__ unsigned long long k[SIZE];
    int tid = threadIdx.x;
    for (int i = tid; i < SIZE; i += 1024) {
        if (i < n) {
            unsigned u = __float_as_uint(sc[i]);
            unsigned o = (u & 0x80000000u) ? ~u : (u | 0x80000000u);
            k[i] = ((unsigned long long)(~o) << 32) | (unsigned)i;
        } else k[i] = 0xFFFFFFFFFFFFFFFFULL;
    }
    __syncthreads();
    for (int kk = 2; kk <= SIZE; kk <<= 1) {
        for (int j = kk >> 1; j > 0; j >>= 1) {
            for (int i = tid; i < SIZE; i += 1024) {
                int ixj = i ^ j;
                if (ixj > i) {
                    bool up = ((i & kk) == 0);
                    unsigned long long a = k[i], b = k[ixj];
                    if ((a > b) == up) { k[i] = b; k[ixj] = a; }
                }
            }
            __syncthreads();
        }
    }
    for (int i = tid; i < n; i += 1024) ord[i] = (int)(k[i] & 0xFFFFFFFFu);
}

// -------- gather sorted boxes + areas --------
__global__ void k_gather1() {
    int i = blockIdx.x * blockDim.x + threadIdx.x;
    if (i >= NANCH) return;
    int o = g_order[i];
    float4 b = *(const float4*)&g_boxes[o * 4];
    g_sb1[i] = b;
    g_sa1[i] = fmaxf(b.z - b.x, 0.f) * fmaxf(b.w - b.y, 0.f);
}
__global__ void k_gather2(const float* __restrict__ dets) {
    int i = blockIdx.x * blockDim.x + threadIdx.x;
    if (i >= NPROP) return;
    int o = g_order2[i];
    float4 b = *(const float4*)&dets[o * 4];
    g_sb2[i] = b;
    g_sa2[i] = fmaxf(b.z - b.x, 0.f) * fmaxf(b.w - b.y, 0.f);
}

// -------- IoU bitmask matrix: mask[i][cb] bit jj = (i suppresses j=cb*64+jj) ----
template <int N, int NW>
__global__ void k_ioumask(const float4* __restrict__ sb, const float* __restrict__ sa,
                          unsigned long long* __restrict__ mask, float thr) {
    __shared__ float4 cbx[64];
    __shared__ float car[64];
    int rb = blockIdx.y, cb = blockIdx.x;
    int t = threadIdx.x;
    int j0 = cb * 64;
    if (j0 + t < N) { cbx[t] = sb[j0 + t]; car[t] = sa[j0 + t]; }
    __syncthreads();
    int i = rb * 64 + t;
    if (i >= N) return;
    float4 bi = sb[i];
    float ai = sa[i];
    unsigned long long m = 0;
    int jmax = min(64, N - j0);
    for (int jj = 0; jj < jmax; jj++) {
        int j = j0 + jj;
        if (j <= i) continue;
        float xx1 = fmaxf(bi.x, cbx[jj].x), yy1 = fmaxf(bi.y, cbx[jj].y);
        float xx2 = fminf(bi.z, cbx[jj].z), yy2 = fminf(bi.w, cbx[jj].w);
        float inter = fmaxf(xx2 - xx1, 0.f) * fmaxf(yy2 - yy1, 0.f);
        float iou = inter / (ai + car[jj] - inter + 1e-8f);
        if (iou > thr) m |= 1ULL << jj;
    }
    mask[(size_t)i * NW + cb] = m;
}

// -------- serial greedy reduce over bitmasks; one warp, prefetched rows --------
template <int N, int NW, int LPW>
__global__ void k_nmsreduce(const unsigned long long* __restrict__ mask,
                            int* __restrict__ keep) {
    int lane = threadIdx.x;
    unsigned long long rem0 = ~0ULL, rem1 = ~0ULL;
    int w0i = lane * LPW;
    unsigned long long p0 = (w0i < NW) ? mask[w0i] : 0ULL;
    unsigned long long p1 = (LPW == 2 && w0i + 1 < NW) ? mask[w0i + 1] : 0ULL;
    for (int i = 0; i < N; i++) {
        unsigned long long c0 = p0, c1 = p1;
        if (i + 1 < N) {
            size_t base = (size_t)(i + 1) * NW;
            p0 = (w0i < NW) ? mask[base + w0i] : 0ULL;
            if (LPW == 2) p1 = (w0i + 1 < NW) ? mask[base + w0i + 1] : 0ULL;
        }
        int w = i >> 6, b = i & 63;
        int owner = w / LPW, sub = w - owner * LPW;
        unsigned long long val = (LPW == 2 && sub == 1) ? rem1 : rem0;
        unsigned long long rw = __shfl_sync(0xffffffffu, val, owner);
        int kept = (int)((rw >> b) & 1ULL);
        if (kept) { rem0 &= ~c0; if (LPW == 2) rem1 &= ~c1; }
        if (lane == 0) keep[i] = kept;
    }
}

// -------- stable kept-first selection of NPROP proposals --------
__global__ void k_select1(float* __restrict__ o_props) {
    __shared__ int s_src[NPROP];
    int tid = threadIdx.x;
    if (tid < 32) {
        const int CH = NANCH / 32;
        int beg = tid * CH, end = beg + CH;
        int cnt = 0;
        for (int i = beg; i < end; i++) cnt += g_keep1[i];
        int xsc = cnt;
        for (int off = 1; off < 32; off <<= 1) {
            int v = __shfl_up_sync(0xffffffffu, xsc, off);
            if (tid >= off) xsc += v;
        }
        int excl = xsc - cnt;
        int total = __shfl_sync(0xffffffffu, xsc, 31);
        int kpos = excl;
        int npos = total + (beg - excl);
        for (int i = beg; i < end; i++) {
            int pos = g_keep1[i] ? kpos++ : npos++;
            if (pos < NPROP) s_src[pos] = i;
        }
    }
    __syncthreads();
    for (int p = tid; p < NPROP; p += 1024) {
        int i = s_src[p];
        int v = g_keep1[i];
        float4 bb = g_sb1[i];
        float px1 = v ? bb.x : 0.f, py1 = v ? bb.y : 0.f;
        float px2 = v ? bb.z : 0.f, py2 = v ? bb.w : 0.f;
        g_props[p * 4] = px1; g_props[p * 4 + 1] = py1;
        g_props[p * 4 + 2] = px2; g_props[p * 4 + 3] = py2;
        o_props[p * 4] = px1; o_props[p * 4 + 1] = py1;
        o_props[p * 4 + 2] = px2; o_props[p * 4 + 3] = py2;
        g_valid[p] = v;
    }
}

// -------- fused per-ROI: crop+bilinear, maxpool->flat, mask conv (2 oc/thread), 1x1 ----
__global__ void k_roi(const float* __restrict__ bm1,
                      const float* __restrict__ wm2, const float* __restrict__ bm2,
                      float* __restrict__ omask) {
    extern __shared__ unsigned char smem_raw[];
    float* s_crop = (float*)smem_raw;    // 12544
    float* s_m = s_crop + 12544;         // 12544
    float* s_wy = s_m + 12544;
    float* s_wx = s_wy + 14;
    int* s_y0 = (int*)(s_wx + 14);
    int* s_y1 = s_y0 + 14;
    int* s_x0 = s_y1 + 14;
    int* s_x1 = s_x0 + 14;
    int p = blockIdx.x, tid = threadIdx.x;   // 448 threads

    if (tid < 28) {
        int t = tid % 14;
        float tt = (float)t / 13.0f;
        if (tid < 14) {
            float y1n = g_props[p * 4 + 1] / 255.0f, y2n = g_props[p * 4 + 3] / 255.0f;
            float fy = (y1n + (y2n - y1n) * tt) * 15.0f;
            float y0f = fminf(fmaxf(floorf(fy), 0.f), 15.f);
            int y0 = (int)y0f;
            s_y0[t] = y0; s_y1[t] = min(y0 + 1, 15); s_wy[t] = fy - y0f;
        } else {
            float x1n = g_props[p * 4 + 0] / 255.0f, x2n = g_props[p * 4 + 2] / 255.0f;
            float fx = (x1n + (x2n - x1n) * tt) * 15.0f;
            float x0f = fminf(fmaxf(floorf(fx), 0.f), 15.f);
            int x0 = (int)x0f;
            s_x0[t] = x0; s_x1[t] = min(x0 + 1, 15); s_wx[t] = fx - x0f;
        }
    }
    __syncthreads();

    for (int idx = tid; idx < 12544; idx += 448) {
        int c = idx / 196, r2 = idx % 196, ty = r2 / 14, tx = r2 % 14;
        const float* fb = g_feat + c * 256;
        int y0 = s_y0[ty], y1 = s_y1[ty], x0 = s_x0[tx], x1 = s_x1[tx];
        float wy = s_wy[ty], wx = s_wx[tx];
        float f00 = fb[y0 * 16 + x0], f01 = fb[y0 * 16 + x1];
        float f10 = fb[y1 * 16 + x0], f11 = fb[y1 * 16 + x1];
        float top = f00 * (1.f - wx) + f01 * wx;
        float bot = f10 * (1.f - wx) + f11 * wx;
        s_crop[idx] = top * (1.f - wy) + bot * wy;
    }
    __syncthreads();

    // pool 2x2 -> flat [64*49]
    for (int idx = tid; idx < 64 * 49; idx += 448) {
        int c = idx / 49, r2 = idx % 49, py = r2 / 7, px = r2 % 7;
        const float* cb = s_crop + c * 196 + py * 28 + px * 2;
        float v = fmaxf(fmaxf(cb[0], cb[1]), fmaxf(cb[14], cb[15]));
        g_flat[(size_t)p * 3136 + idx] = v;
    }

    // mask conv 3x3 + relu: thread = (oc pair, output row), 14-wide register rows
    {
        int ocp = tid / 14, y = tid % 14;
        int oc0 = ocp * 2, oc1 = oc0 + 1;
        float acc0[14], acc1[14];
        float bv0 = bm1[oc0], bv1 = bm1[oc1];
#pragma unroll
        for (int xq = 0; xq < 14; xq++) { acc0[xq] = bv0; acc1[xq] = bv1; }
        const float4* packA = ((const float4*)g_wpack) + oc0 * 64 * 3;
        const float4* packB = ((const float4*)g_wpack) + oc1 * 64 * 3;
        for (int ic = 0; ic < 64; ic++) {
            float4 A0 = packA[ic * 3], A1 = packA[ic * 3 + 1], A2 = packA[ic * 3 + 2];
            float4 B0 = packB[ic * 3], B1 = packB[ic * 3 + 1], B2 = packB[ic * 3 + 2];
            float wA[9] = {A0.x, A0.y, A0.z, A0.w, A1.x, A1.y, A1.z, A1.w, A2.x};
            float wB[9] = {B0.x, B0.y, B0.z, B0.w, B1.x, B1.y, B1.z, B1.w, B2.x};
            const float* cbase = s_crop + ic * 196;
#pragma unroll
            for (int ky = 0; ky < 3; ky++) {
                int yin = y + ky - 1;
                if (yin < 0 || yin > 13) continue;
                const float* row = cbase + yin * 14;
                float r[16];
                r[0] = 0.f; r[15] = 0.f;
#pragma unroll
                for (int j = 0; j < 14; j++) r[j + 1] = row[j];
                float a0 = wA[ky * 3], a1 = wA[ky * 3 + 1], a2 = wA[ky * 3 + 2];
                float b0 = wB[ky * 3], b1 = wB[ky * 3 + 1], b2 = wB[ky * 3 + 2];
#pragma unroll
                for (int xq = 0; xq < 14; xq++) {
                    acc0[xq] += r[xq] * a0 + r[xq + 1] * a1 + r[xq + 2] * a2;
                    acc1[xq] += r[xq] * b0 + r[xq + 1] * b1 + r[xq + 2] * b2;
                }
            }
        }
        float* m0 = s_m + oc0 * 196 + y * 14;
        float* m1 = s_m + oc1 * 196 + y * 14;
#pragma unroll
        for (int xq = 0; xq < 14; xq++) {
            m0[xq] = fmaxf(acc0[xq], 0.f);
            m1[xq] = fmaxf(acc1[xq], 0.f);
        }
    }
    __syncthreads();

    // 1x1 conv 64->1 (mask logits)
    for (int pos = tid; pos < 196; pos += 448) {
        float acc = bm2[0];
#pragma unroll 8
        for (int oc = 0; oc < 64; oc++) acc += s_m[oc * 196 + pos] * wm2[oc];
        omask[(size_t)p * 196 + pos] = acc;
        g_masks[(size_t)p * 196 + pos] = acc;
    }
}

// -------- SGEMM 64x64x8 tile, 128 threads, 8x4 micro: C = relu(A·B + bias) --------
__global__ void k_gemm64(const float* __restrict__ Ax, const float* __restrict__ Bx,
                         const float* __restrict__ bias, float* __restrict__ C,
                         int M, int N, int K) {
    __shared__ float As[8][72];
    __shared__ float Bs[8][64];
    int tid = threadIdx.x;              // 128
    int tx = tid & 15, ty = tid >> 4;   // ty 0..7
    int bm = blockIdx.y * 64, bn = blockIdx.x * 64;
    float acc[8][4];
#pragma unroll
    for (int i = 0; i < 8; i++)
#pragma unroll
        for (int j = 0; j < 4; j++) acc[i][j] = 0.f;

    int arow = tid >> 1, ac4 = (tid & 1) * 4;
    int bkr = tid >> 4, bc4 = (tid & 15) * 4;
    for (int k0 = 0; k0 < K; k0 += 8) {
        int row = bm + arow;
        float4 av = make_float4(0.f, 0.f, 0.f, 0.f);
        if (row < M) av = *(const float4*)&Ax[(size_t)row * K + k0 + ac4];
        As[ac4 + 0][arow] = av.x;
        As[ac4 + 1][arow] = av.y;
        As[ac4 + 2][arow] = av.z;
        As[ac4 + 3][arow] = av.w;
        float4 bv = *(const float4*)&Bx[(size_t)(k0 + bkr) * N + bn + bc4];
        *(float4*)&Bs[bkr][bc4] = bv;
        __syncthreads();
#pragma unroll
        for (int k = 0; k < 8; k++) {
            float4 a0 = *(const float4*)&As[k][ty * 8];
            float4 a1 = *(const float4*)&As[k][ty * 8 + 4];
            float4 b0 = *(const float4*)&Bs[k][tx * 4];
            float aval[8] = {a0.x, a0.y, a0.z, a0.w, a1.x, a1.y, a1.z, a1.w};
            float bval[4] = {b0.x, b0.y, b0.z, b0.w};
#pragma unroll
            for (int i2 = 0; i2 < 8; i2++)
#pragma unroll
                for (int j2 = 0; j2 < 4; j2++) acc[i2][j2] += aval[i2] * bval[j2];
        }
        __syncthreads();
    }
#pragma unroll
    for (int i2 = 0; i2 < 8; i2++) {
        int row = bm + ty * 8 + i2;
        if (row >= M) continue;
#pragma unroll
        for (int j2 = 0; j2 < 4; j2++) {
            int col = bn + tx * 4 + j2;
            C[(size_t)row * N + col] = fmaxf(acc[i2][j2] + bias[col], 0.f);
        }
    }
}

// -------- rcnn cls/box heads: 6 dot-products of K=512, one warp each --------
__global__ void k_rheads(const float* __restrict__ wrc, const float* __restrict__ brc,
                         const float* __restrict__ wrb, const float* __restrict__ brb,
                         float* __restrict__ o_log, float* __restrict__ o_del) {
    int p = blockIdx.x;
    int w = threadIdx.x >> 5, lane = threadIdx.x & 31;
    const float* hp = g_h2 + (size_t)p * 512;
    float s = 0.f;
    if (w < 2) {
        for (int k = lane; k < 512; k += 32) s += hp[k] * wrc[k * 2 + w];
    } else {
        int j = w - 2;
        for (int k = lane; k < 512; k += 32) s += hp[k] * wrb[k * 4 + j];
    }
    for (int off = 16; off > 0; off >>= 1) s += __shfl_down_sync(0xffffffffu, s, off);
    if (lane == 0) {
        if (w < 2) {
            float v = s + brc[w];
            o_log[p * 2 + w] = v;
            g_rlogits[p * 2 + w] = v;
        } else {
            int j = w - 2;
            float v = s + brb[j];
            o_del[p * 4 + j] = v;
            g_rdeltas[p * 4 + j] = v;
        }
    }
}

// -------- decode stage 2: det scores, dets, s2 --------
__global__ void k_decode2(float* __restrict__ dets) {
    int p = blockIdx.x * blockDim.x + threadIdx.x;
    if (p >= NPROP) return;
    float l0 = g_rlogits[p * 2], l1 = g_rlogits[p * 2 + 1];
    float m = fmaxf(l0, l1);
    float e0 = expf(l0 - m), e1 = expf(l1 - m);
    float sc = e1 / (e0 + e1);
    g_dscores[p] = sc;
    float x1 = g_props[p * 4], y1 = g_props[p * 4 + 1];
    float x2 = g_props[p * 4 + 2], y2 = g_props[p * 4 + 3];
    float w = x2 - x1, h = y2 - y1;
    float cx = x1 + 0.5f * w, cy = y1 + 0.5f * h;
    float d0 = g_rdeltas[p * 4], d1 = g_rdeltas[p * 4 + 1];
    float d2 = g_rdeltas[p * 4 + 2], d3 = g_rdeltas[p * 4 + 3];
    float ncx = cx + d0 * w, ncy = cy + d1 * h;
    float nw = w * expf(d2), nh = h * expf(d3);
    dets[p * 4]     = fminf(fmaxf(ncx - 0.5f * nw, 0.f), 255.f);
    dets[p * 4 + 1] = fminf(fmaxf(ncy - 0.5f * nh, 0.f), 255.f);
    dets[p * 4 + 2] = fminf(fmaxf(ncx + 0.5f * nw, 0.f), 255.f);
    dets[p * 4 + 3] = fminf(fmaxf(ncy + 0.5f * nh, 0.f), 255.f);
    g_s2[p] = g_valid[p] ? sc : -1.0f;
}
__device__ float g_dets[NPROP * 4];

// -------- final dets/scores/keep2 --------
__global__ void k_final2(float* __restrict__ o_fdets, float* __restrict__ o_fsc,
                         float* __restrict__ o_keep) {
    int r = blockIdx.x * blockDim.x + threadIdx.x;
    if (r >= NPROP) return;
    int o = g_order2[r];
    int k2 = g_keep2a[r] && g_valid[o];
    float kf = k2 ? 1.f : 0.f;
    float4 d = g_sb2[r];
    o_fdets[r * 4]     = k2 ? d.x : 0.f;
    o_fdets[r * 4 + 1] = k2 ? d.y : 0.f;
    o_fdets[r * 4 + 2] = k2 ? d.z : 0.f;
    o_fdets[r * 4 + 3] = k2 ? d.w : 0.f;
    o_fsc[r] = k2 ? g_dscores[o] : 0.f;
    if (o_keep) o_keep[r] = kf;
    g_keep2f[r] = kf;
}

// -------- final masks: sigmoid(masks[order2]) * keep2 --------
__global__ void k_fmask(float* __restrict__ o) {
    int r = blockIdx.x, i = threadIdx.x;
    int oi = g_order2[r];
    float v = g_masks[(size_t)oi * 196 + i];
    float sgm = 1.f / (1.f + expf(-v));
    o[(size_t)r * 196 + i] = sgm * g_keep2f[r];
}

// ---------------- host ----------------
extern "C" void kernel_launch(void* const* d_in, const int* in_sizes, int n_in,
                              void* d_out, int out_size) {
    const float* x      = (const float*)d_in[0];
    const float* w_bb   = (const float*)d_in[1];
    const float* b_bb   = (const float*)d_in[2];
    const float* w_rpn  = (const float*)d_in[3];
    const float* b_rpn  = (const float*)d_in[4];
    const float* w_cls  = (const float*)d_in[5];
    const float* b_cls  = (const float*)d_in[6];
    const float* w_box  = (const float*)d_in[7];
    const float* b_box  = (const float*)d_in[8];
    const float* w_fc1  = (const float*)d_in[9];
    const float* b_fc1  = (const float*)d_in[10];
    const float* w_fc2  = (const float*)d_in[11];
    const float* b_fc2  = (const float*)d_in[12];
    const float* w_rcls = (const float*)d_in[13];
    const float* b_rcls = (const float*)d_in[14];
    const float* w_rbox = (const float*)d_in[15];
    const float* b_rbox = (const float*)d_in[16];
    const float* w_m1   = (const float*)d_in[17];
    const float* b_m1   = (const float*)d_in[18];
    const float* w_m2   = (const float*)d_in[19];
    const float* b_m2   = (const float*)d_in[20];
    float* out = (float*)d_out;

    const size_t O_RPNL = 0, O_RPND = 4608, O_PROP = 13824, O_ANCH = 21824;
    const size_t O_RLOG = 31040, O_RDEL = 35040, O_RMSK = 43040;
    const size_t O_FDET = 435040, O_FMSK = 443040, O_FSC = 835040, O_KEEP = 837040;

    float *p_scores, *p_s2, *p_flat, *p_h1, *p_h2, *p_dets;
    int *p_order, *p_order2, *p_keep1, *p_keep2a;
    unsigned long long *p_mask1, *p_mask2;
    cudaGetSymbolAddress((void**)&p_scores, g_scores);
    cudaGetSymbolAddress((void**)&p_order, g_order);
    cudaGetSymbolAddress((void**)&p_s2, g_s2);
    cudaGetSymbolAddress((void**)&p_order2, g_order2);
    cudaGetSymbolAddress((void**)&p_flat, g_flat);
    cudaGetSymbolAddress((void**)&p_h1, g_h1);
    cudaGetSymbolAddress((void**)&p_h2, g_h2);
    cudaGetSymbolAddress((void**)&p_dets, g_dets);
    cudaGetSymbolAddress((void**)&p_keep1, g_keep1);
    cudaGetSymbolAddress((void**)&p_keep2a, g_keep2a);
    cudaGetSymbolAddress((void**)&p_mask1, g_mask1);
    cudaGetSymbolAddress((void**)&p_mask2, g_mask2);

    const int SMEM_ROI = (12544 * 2 + 28) * 4 + 56 * 4;
    cudaFuncSetAttribute(k_roi, cudaFuncAttributeMaxDynamicSharedMemorySize, SMEM_ROI);

    float4* p_sb1; float* p_sa1; float4* p_sb2; float* p_sa2;
    cudaGetSymbolAddress((void**)&p_sb1, g_sb1);
    cudaGetSymbolAddress((void**)&p_sa1, g_sa1);
    cudaGetSymbolAddress((void**)&p_sb2, g_sb2);
    cudaGetSymbolAddress((void**)&p_sa2, g_sa2);

    k_backbone<<<256, 64>>>(x, w_bb, b_bb);
    k_packw<<<(64 * 64 * 12 + 255) / 256, 256>>>(w_m1);
    k_rpnconv<<<256, 64>>>(w_rpn, b_rpn);
    k_heads1<<<18, 128>>>(w_cls, b_cls, w_box, b_box,
                          out + O_RPNL, out + O_RPND, out + O_ANCH);
    k_sort<4096><<<1, 1024>>>(p_scores, NANCH, p_order);
    k_gather1<<<(NANCH + 255) / 256, 256>>>();
    k_ioumask<NANCH, NW1><<<dim3(NW1, NW1), 64>>>(p_sb1, p_sa1, p_mask1, 0.5f);
    k_nmsreduce<NANCH, NW1, 2><<<1, 32>>>(p_mask1, p_keep1);
    k_select1<<<1, 1024>>>(out + O_PROP);
    k_roi<<<NPROP, 448, SMEM_ROI>>>(b_m1, w_m2, b_m2, out + O_RMSK);

    dim3 gfc(512 / 64, (NPROP + 63) / 64);
    k_gemm64<<<gfc, 128>>>(p_flat, w_fc1, b_fc1, p_h1, NPROP, 512, 3136);
    k_gemm64<<<gfc, 128>>>(p_h1, w_fc2, b_fc2, p_h2, NPROP, 512, 512);
    k_rheads<<<NPROP, 192>>>(w_rcls, b_rcls, w_rbox, b_rbox,
                             out + O_RLOG, out + O_RDEL);
    k_decode2<<<(NPROP + 255) / 256, 256>>>(p_dets);
    k_sort<2048><<<1, 1024>>>(p_s2, NPROP, p_order2);
    k_gather2<<<(NPROP + 255) / 256, 256>>>(p_dets);
    k_ioumask<NPROP, NW2><<<dim3(NW2, NW2), 64>>>(p_sb2, p_sa2, p_mask2, 0.3f);
    k_nmsreduce<NPROP, NW2, 1><<<1, 32>>>(p_mask2, p_keep2a);
    float* o_keep = (out_size >= (int)(O_KEEP + NPROP)) ? (out + O_KEEP) : nullptr;
    k_final2<<<(NPROP + 255) / 256, 256>>>(out + O_FDET, out + O_FSC, o_keep);
    k_fmask<<<NPROP, 196>>>(out + O_FMSK);
}

// round 4
// speedup vs baseline: 1.6458x; 1.0906x over previous
#include <cuda_runtime.h>
#include <math.h>

#define NANCH 2304
#define NPROP 2000
#define NW1 36
#define NW2 32

// ---------------- scratch (device globals; no allocation) ----------------
__device__ float g_feat[64 * 256];
__device__ float g_hrpn[64 * 256];
__device__ float g_scores[NANCH];
__device__ float g_boxes[NANCH * 4];
__device__ int   g_order[NANCH];
__device__ float g_props[NPROP * 4];
__device__ int   g_valid[NPROP];
__device__ float g_flat[NPROP * 3136];
__device__ float g_h1[NPROP * 512];
__device__ float g_h2[NPROP * 512];
__device__ float g_rlogits[NPROP * 2];
__device__ float g_rdeltas[NPROP * 4];
__device__ float g_dscores[NPROP];
__device__ float g_s2[NPROP];
__device__ int   g_order2[NPROP];
__device__ float g_keep2f[NPROP];
__device__ float g_masks[NPROP * 196];
__device__ float g_dets[NPROP * 4];
__device__ float g_wpack[64 * 64 * 12];          // packed mask-conv weights
__device__ float g_flatz[3136];                  // canonical zero-box ROI results
__device__ float g_maskz[196];
// NMS scratch
__device__ float4 g_sb1[NANCH];
__device__ float  g_sa1[NANCH];
__device__ unsigned long long g_mask1[(size_t)NANCH * NW1];
__device__ int    g_keep1[NANCH];
__device__ float4 g_sb2[NPROP];
__device__ float  g_sa2[NPROP];
__device__ unsigned long long g_mask2[(size_t)NPROP * NW2];
__device__ int    g_keep2a[NPROP];

// ---------------- backbone: conv 3->64, k16 s16 VALID, relu ----------------
__global__ void k_backbone(const float* __restrict__ x, const float* __restrict__ w,
                           const float* __restrict__ b) {
    __shared__ float patch[768];
    int pos = blockIdx.x;
    int h = pos >> 4, wq = pos & 15;
    int tid = threadIdx.x;
    for (int k = tid; k < 768; k += 64) {
        int ic = k >> 8, r = k & 255, iy = r >> 4, ix = r & 15;
        patch[k] = x[ic * 65536 + (h * 16 + iy) * 256 + (wq * 16 + ix)];
    }
    __syncthreads();
    int oc = tid;
    const float* wp = w + oc * 768;
    float acc = b[oc];
#pragma unroll 8
    for (int k = 0; k < 768; k++) acc += patch[k] * wp[k];
    g_feat[oc * 256 + pos] = fmaxf(acc, 0.f);
}

// ---------------- rpn conv 3x3 SAME, relu ----------------
__global__ void k_rpnconv(const float* __restrict__ w, const float* __restrict__ b) {
    int pos = blockIdx.x;
    int y = pos >> 4, xq = pos & 15;
    int oc = threadIdx.x;
    float acc = b[oc];
    const float* wp = w + oc * 576;
    for (int ic = 0; ic < 64; ic++) {
        const float* fb = g_feat + ic * 256;
        const float* wb = wp + ic * 9;
#pragma unroll
        for (int ky = 0; ky < 3; ky++) {
            int yy = y + ky - 1;
            if (yy < 0 || yy > 15) continue;
#pragma unroll
            for (int kx = 0; kx < 3; kx++) {
                int xx = xq + kx - 1;
                if (xx < 0 || xx > 15) continue;
                acc += fb[yy * 16 + xx] * wb[ky * 3 + kx];
            }
        }
    }
    g_hrpn[oc * 256 + pos] = fmaxf(acc, 0.f);
}

// -------- rpn heads (1x1), anchors, softmax score, decode, clip --------
__global__ void k_heads1(const float* __restrict__ wc, const float* __restrict__ bc,
                         const float* __restrict__ wb, const float* __restrict__ bb,
                         float* __restrict__ o_logits, float* __restrict__ o_deltas,
                         float* __restrict__ o_anch) {
    int i = blockIdx.x * blockDim.x + threadIdx.x;
    if (i >= NANCH) return;
    int cell = i / 9, a = i % 9;
    float l0 = bc[a * 2], l1 = bc[a * 2 + 1];
    float d0 = bb[a * 4], d1 = bb[a * 4 + 1], d2 = bb[a * 4 + 2], d3 = bb[a * 4 + 3];
    for (int ic = 0; ic < 64; ic++) {
        float f = g_hrpn[ic * 256 + cell];
        l0 += f * wc[(a * 2) * 64 + ic];
        l1 += f * wc[(a * 2 + 1) * 64 + ic];
        d0 += f * wb[(a * 4) * 64 + ic];
        d1 += f * wb[(a * 4 + 1) * 64 + ic];
        d2 += f * wb[(a * 4 + 2) * 64 + ic];
        d3 += f * wb[(a * 4 + 3) * 64 + ic];
    }
    o_logits[i * 2] = l0; o_logits[i * 2 + 1] = l1;
    o_deltas[i * 4] = d0; o_deltas[i * 4 + 1] = d1;
    o_deltas[i * 4 + 2] = d2; o_deltas[i * 4 + 3] = d3;
    float m = fmaxf(l0, l1);
    float e0 = expf(l0 - m), e1 = expf(l1 - m);
    g_scores[i] = e1 / (e0 + e1);

    const float S[3] = {32.f, 64.f, 128.f};
    const float R[3] = {0.5f, 1.f, 2.f};
    int h = cell >> 4, wq = cell & 15;
    float s = S[a / 3], r = R[a % 3];
    float ws = s * sqrtf(r), hs = s / sqrtf(r);
    float cx = (wq + 0.5f) * 16.f, cy = (h + 0.5f) * 16.f;
    float ax1 = cx - ws * 0.5f, ay1 = cy - hs * 0.5f;
    float ax2 = cx + ws * 0.5f, ay2 = cy + hs * 0.5f;
    o_anch[i * 4] = ax1; o_anch[i * 4 + 1] = ay1;
    o_anch[i * 4 + 2] = ax2; o_anch[i * 4 + 3] = ay2;

    float aw = ax2 - ax1, ah = ay2 - ay1;
    float acx = ax1 + 0.5f * aw, acy = ay1 + 0.5f * ah;
    float ncx = acx + d0 * aw, ncy = acy + d1 * ah;
    float nw = aw * expf(d2), nh = ah * expf(d3);
    g_boxes[i * 4]     = fminf(fmaxf(ncx - 0.5f * nw, 0.f), 255.f);
    g_boxes[i * 4 + 1] = fminf(fmaxf(ncy - 0.5f * nh, 0.f), 255.f);
    g_boxes[i * 4 + 2] = fminf(fmaxf(ncx + 0.5f * nw, 0.f), 255.f);
    g_boxes[i * 4 + 3] = fminf(fmaxf(ncy + 0.5f * nh, 0.f), 255.f);
}

// -------- pack mask-conv weights: [oc][ic][9] -> [oc][ic][12] (float4-aligned) ----
__global__ void k_packw(const float* __restrict__ w) {
    int i = blockIdx.x * blockDim.x + threadIdx.x;
    if (i >= 64 * 64 * 12) return;
    int pair = i / 12, q = i % 12;
    g_wpack[i] = (q < 9) ? w[pair * 9 + q] : 0.f;
}

// -------- single-block bitonic sort: descending value, stable by index --------
template <int SIZE>
__global__ void k_sort(const float* __restrict__ sc, int n, int* __restrict__ ord) {
    __shared__ unsigned long long k[SIZE];
    int tid = threadIdx.x;
    for (int i = tid; i < SIZE; i += 1024) {
        if (i < n) {
            unsigned u = __float_as_uint(sc[i]);
            unsigned o = (u & 0x80000000u) ? ~u : (u | 0x80000000u);
            k[i] = ((unsigned long long)(~o) << 32) | (unsigned)i;
        } else k[i] = 0xFFFFFFFFFFFFFFFFULL;
    }
    __syncthreads();
    for (int kk = 2; kk <= SIZE; kk <<= 1) {
        for (int j = kk >> 1; j > 0; j >>= 1) {
            for (int i = tid; i < SIZE; i += 1024) {
                int ixj = i ^ j;
                if (ixj > i) {
                    bool up = ((i & kk) == 0);
                    unsigned long long a = k[i], b = k[ixj];
                    if ((a > b) == up) { k[i] = b; k[ixj] = a; }
                }
            }
            __syncthreads();
        }
    }
    for (int i = tid; i < n; i += 1024) ord[i] = (int)(k[i] & 0xFFFFFFFFu);
}

// -------- gather sorted boxes + areas --------
__global__ void k_gather1() {
    int i = blockIdx.x * blockDim.x + threadIdx.x;
    if (i >= NANCH) return;
    int o = g_order[i];
    float4 b = *(const float4*)&g_boxes[o * 4];
    g_sb1[i] = b;
    g_sa1[i] = fmaxf(b.z - b.x, 0.f) * fmaxf(b.w - b.y, 0.f);
}
__global__ void k_gather2(const float* __restrict__ dets) {
    int i = blockIdx.x * blockDim.x + threadIdx.x;
    if (i >= NPROP) return;
    int o = g_order2[i];
    float4 b = *(const float4*)&dets[o * 4];
    g_sb2[i] = b;
    g_sa2[i] = fmaxf(b.z - b.x, 0.f) * fmaxf(b.w - b.y, 0.f);
}

// -------- IoU bitmask matrix --------
template <int N, int NW>
__global__ void k_ioumask(const float4* __restrict__ sb, const float* __restrict__ sa,
                          unsigned long long* __restrict__ mask, float thr) {
    __shared__ float4 cbx[64];
    __shared__ float car[64];
    int rb = blockIdx.y, cb = blockIdx.x;
    int t = threadIdx.x;
    int j0 = cb * 64;
    if (j0 + t < N) { cbx[t] = sb[j0 + t]; car[t] = sa[j0 + t]; }
    __syncthreads();
    int i = rb * 64 + t;
    if (i >= N) return;
    float4 bi = sb[i];
    float ai = sa[i];
    unsigned long long m = 0;
    int jmax = min(64, N - j0);
    for (int jj = 0; jj < jmax; jj++) {
        int j = j0 + jj;
        if (j <= i) continue;
        float xx1 = fmaxf(bi.x, cbx[jj].x), yy1 = fmaxf(bi.y, cbx[jj].y);
        float xx2 = fminf(bi.z, cbx[jj].z), yy2 = fminf(bi.w, cbx[jj].w);
        float inter = fmaxf(xx2 - xx1, 0.f) * fmaxf(yy2 - yy1, 0.f);
        float iou = inter / (ai + car[jj] - inter + 1e-8f);
        if (iou > thr) m |= 1ULL << jj;
    }
    mask[(size_t)i * NW + cb] = m;
}

// -------- serial greedy reduce over bitmasks; one warp, prefetched rows --------
template <int N, int NW, int LPW>
__global__ void k_nmsreduce(const unsigned long long* __restrict__ mask,
                            int* __restrict__ keep) {
    int lane = threadIdx.x;
    unsigned long long rem0 = ~0ULL, rem1 = ~0ULL;
    int w0i = lane * LPW;
    unsigned long long p0 = (w0i < NW) ? mask[w0i] : 0ULL;
    unsigned long long p1 = (LPW == 2 && w0i + 1 < NW) ? mask[w0i + 1] : 0ULL;
    for (int i = 0; i < N; i++) {
        unsigned long long c0 = p0, c1 = p1;
        if (i + 1 < N) {
            size_t base = (size_t)(i + 1) * NW;
            p0 = (w0i < NW) ? mask[base + w0i] : 0ULL;
            if (LPW == 2) p1 = (w0i + 1 < NW) ? mask[base + w0i + 1] : 0ULL;
        }
        int w = i >> 6, b = i & 63;
        int owner = w / LPW, sub = w - owner * LPW;
        unsigned long long val = (LPW == 2 && sub == 1) ? rem1 : rem0;
        unsigned long long rw = __shfl_sync(0xffffffffu, val, owner);
        int kept = (int)((rw >> b) & 1ULL);
        if (kept) { rem0 &= ~c0; if (LPW == 2) rem1 &= ~c1; }
        if (lane == 0) keep[i] = kept;
    }
}

// -------- stable kept-first selection of NPROP proposals --------
__global__ void k_select1(float* __restrict__ o_props) {
    __shared__ int s_src[NPROP];
    int tid = threadIdx.x;
    if (tid < 32) {
        const int CH = NANCH / 32;
        int beg = tid * CH, end = beg + CH;
        int cnt = 0;
        for (int i = beg; i < end; i++) cnt += g_keep1[i];
        int xsc = cnt;
        for (int off = 1; off < 32; off <<= 1) {
            int v = __shfl_up_sync(0xffffffffu, xsc, off);
            if (tid >= off) xsc += v;
        }
        int excl = xsc - cnt;
        int total = __shfl_sync(0xffffffffu, xsc, 31);
        int kpos = excl;
        int npos = total + (beg - excl);
        for (int i = beg; i < end; i++) {
            int pos = g_keep1[i] ? kpos++ : npos++;
            if (pos < NPROP) s_src[pos] = i;
        }
    }
    __syncthreads();
    for (int p = tid; p < NPROP; p += 1024) {
        int i = s_src[p];
        int v = g_keep1[i];
        float4 bb = g_sb1[i];
        float px1 = v ? bb.x : 0.f, py1 = v ? bb.y : 0.f;
        float px2 = v ? bb.z : 0.f, py2 = v ? bb.w : 0.f;
        g_props[p * 4] = px1; g_props[p * 4 + 1] = py1;
        g_props[p * 4 + 2] = px2; g_props[p * 4 + 3] = py2;
        o_props[p * 4] = px1; o_props[p * 4 + 1] = py1;
        o_props[p * 4 + 2] = px2; o_props[p * 4 + 3] = py2;
        g_valid[p] = v;
    }
}

// ===================== ROI body (448 threads) =====================
// smem layout: s_w4[1536 float4] | s_crop[64*224] | s_m[64*196] | misc
#define SMEM_ROI_BYTES (1536 * 16 + (64 * 224 + 64 * 196 + 28) * 4 + 56 * 4 + 16)

__device__ __forceinline__ void roi_body(
    int tid, float bx1, float by1, float bx2, float by2,
    const float* __restrict__ bm1, const float* __restrict__ wm2,
    const float* __restrict__ bm2,
    float* __restrict__ flat_out, float* __restrict__ maskA, float* __restrict__ maskB,
    unsigned char* smem_raw)
{
    float4* s_w4 = (float4*)smem_raw;              // 1536 float4
    float* s_crop = (float*)(s_w4 + 1536);         // 64*224
    float* s_m = s_crop + 64 * 224;                // 64*196
    float* s_wy = s_m + 64 * 196;
    float* s_wx = s_wy + 14;
    int* s_y0 = (int*)(s_wx + 14);
    int* s_y1 = s_y0 + 14;
    int* s_x0 = s_y1 + 14;
    int* s_x1 = s_x0 + 14;

    if (tid < 28) {
        int t = tid % 14;
        float tt = (float)t / 13.0f;
        if (tid < 14) {
            float y1n = by1 / 255.0f, y2n = by2 / 255.0f;
            float fy = (y1n + (y2n - y1n) * tt) * 15.0f;
            float y0f = fminf(fmaxf(floorf(fy), 0.f), 15.f);
            int y0 = (int)y0f;
            s_y0[t] = y0; s_y1[t] = min(y0 + 1, 15); s_wy[t] = fy - y0f;
        } else {
            float x1n = bx1 / 255.0f, x2n = bx2 / 255.0f;
            float fx = (x1n + (x2n - x1n) * tt) * 15.0f;
            float x0f = fminf(fmaxf(floorf(fx), 0.f), 15.f);
            int x0 = (int)x0f;
            s_x0[t] = x0; s_x1[t] = min(x0 + 1, 15); s_wx[t] = fx - x0f;
        }
    }
    __syncthreads();

    // bilinear crop -> s_crop (rows padded to 16)
    for (int idx = tid; idx < 12544; idx += 448) {
        int c = idx / 196, r2 = idx % 196, ty = r2 / 14, tx = r2 % 14;
        const float* fb = g_feat + c * 256;
        int y0 = s_y0[ty], y1 = s_y1[ty], x0 = s_x0[tx], x1 = s_x1[tx];
        float wy = s_wy[ty], wx = s_wx[tx];
        float f00 = fb[y0 * 16 + x0], f01 = fb[y0 * 16 + x1];
        float f10 = fb[y1 * 16 + x0], f11 = fb[y1 * 16 + x1];
        float top = f00 * (1.f - wx) + f01 * wx;
        float bot = f10 * (1.f - wx) + f11 * wx;
        s_crop[c * 224 + ty * 16 + tx] = top * (1.f - wy) + bot * wy;
    }
    __syncthreads();

    // pool 2x2 -> flat [64*49]
    for (int idx = tid; idx < 64 * 49; idx += 448) {
        int c = idx / 49, r2 = idx % 49, py = r2 / 7, px = r2 % 7;
        const float* cb = s_crop + c * 224 + py * 32 + px * 2;
        flat_out[idx] = fmaxf(fmaxf(cb[0], cb[1]), fmaxf(cb[16], cb[17]));
    }

    // mask conv 3x3 + relu: thread = (oc pair, row); weights staged in smem
    int ocp = tid / 14, y = tid % 14;
    int oc0 = ocp * 2, oc1 = oc0 + 1;
    float acc0[14], acc1[14];
    {
        float bv0 = bm1[oc0], bv1 = bm1[oc1];
#pragma unroll
        for (int xq = 0; xq < 14; xq++) { acc0[xq] = bv0; acc1[xq] = bv1; }
    }
    const float4* gw4 = (const float4*)g_wpack;
    for (int ic0 = 0; ic0 < 64; ic0 += 8) {
        __syncthreads();     // protect s_w4 reuse (also covers pool/crop on first iter)
        for (int f = tid; f < 1536; f += 448) {
            int oc = f / 24, rem = f % 24;
            int icl = rem / 3, q = rem % 3;
            s_w4[f] = gw4[(oc * 64 + ic0 + icl) * 3 + q];
        }
        __syncthreads();
#pragma unroll 2
        for (int icl = 0; icl < 8; icl++) {
            const float4* wa = s_w4 + oc0 * 24 + icl * 3;
            const float4* wb = s_w4 + oc1 * 24 + icl * 3;
            float4 A0 = wa[0], A1 = wa[1], A2 = wa[2];
            float4 B0 = wb[0], B1 = wb[1], B2 = wb[2];
            float wAr[9] = {A0.x, A0.y, A0.z, A0.w, A1.x, A1.y, A1.z, A1.w, A2.x};
            float wBr[9] = {B0.x, B0.y, B0.z, B0.w, B1.x, B1.y, B1.z, B1.w, B2.x};
            const float* cbase = s_crop + (ic0 + icl) * 224;
#pragma unroll
            for (int ky = 0; ky < 3; ky++) {
                int yin = y + ky - 1;
                if (yin < 0 || yin > 13) continue;
                const float4* rp = (const float4*)(cbase + yin * 16);
                float4 q0 = rp[0], q1 = rp[1], q2 = rp[2], q3 = rp[3];
                float r[16];
                r[0] = 0.f;
                r[1] = q0.x;  r[2] = q0.y;  r[3] = q0.z;  r[4] = q0.w;
                r[5] = q1.x;  r[6] = q1.y;  r[7] = q1.z;  r[8] = q1.w;
                r[9] = q2.x;  r[10] = q2.y; r[11] = q2.z; r[12] = q2.w;
                r[13] = q3.x; r[14] = q3.y; r[15] = 0.f;
                float a0 = wAr[ky * 3], a1 = wAr[ky * 3 + 1], a2 = wAr[ky * 3 + 2];
                float b0 = wBr[ky * 3], b1 = wBr[ky * 3 + 1], b2 = wBr[ky * 3 + 2];
#pragma unroll
                for (int xq = 0; xq < 14; xq++) {
                    acc0[xq] += r[xq] * a0 + r[xq + 1] * a1 + r[xq + 2] * a2;
                    acc1[xq] += r[xq] * b0 + r[xq + 1] * b1 + r[xq + 2] * b2;
                }
            }
        }
    }
    {
        float* m0 = s_m + oc0 * 196 + y * 14;
        float* m1 = s_m + oc1 * 196 + y * 14;
#pragma unroll
        for (int xq = 0; xq < 14; xq++) {
            m0[xq] = fmaxf(acc0[xq], 0.f);
            m1[xq] = fmaxf(acc1[xq], 0.f);
        }
    }
    __syncthreads();

    // 1x1 conv 64->1 (mask logits)
    for (int pos = tid; pos < 196; pos += 448) {
        float acc = bm2[0];
#pragma unroll 8
        for (int oc = 0; oc < 64; oc++) acc += s_m[oc * 196 + pos] * wm2[oc];
        maskA[pos] = acc;
        maskB[pos] = acc;
    }
}

// canonical zero-box ROI
__global__ void k_roizero(const float* __restrict__ bm1, const float* __restrict__ wm2,
                          const float* __restrict__ bm2) {
    extern __shared__ unsigned char smem_raw[];
    roi_body(threadIdx.x, 0.f, 0.f, 0.f, 0.f, bm1, wm2, bm2,
             g_flatz, g_maskz, g_maskz, smem_raw);
}

// per-proposal ROI (invalid -> copy canonical)
__global__ void k_roi(const float* __restrict__ bm1, const float* __restrict__ wm2,
                      const float* __restrict__ bm2, float* __restrict__ omask) {
    extern __shared__ unsigned char smem_raw[];
    int p = blockIdx.x, tid = threadIdx.x;
    if (!g_valid[p]) {
        float* fo = g_flat + (size_t)p * 3136;
        for (int idx = tid; idx < 3136; idx += 448) fo[idx] = g_flatz[idx];
        for (int pos = tid; pos < 196; pos += 448) {
            float v = g_maskz[pos];
            omask[(size_t)p * 196 + pos] = v;
            g_masks[(size_t)p * 196 + pos] = v;
        }
        return;
    }
    roi_body(tid, g_props[p * 4], g_props[p * 4 + 1], g_props[p * 4 + 2], g_props[p * 4 + 3],
             bm1, wm2, bm2,
             g_flat + (size_t)p * 3136, omask + (size_t)p * 196,
             g_masks + (size_t)p * 196, smem_raw);
}

// -------- SGEMM 64x64x8 tile, 128 threads, 8x4 micro: C = relu(A·B + bias) --------
__global__ void k_gemm64(const float* __restrict__ Ax, const float* __restrict__ Bx,
                         const float* __restrict__ bias, float* __restrict__ C,
                         int M, int N, int K) {
    __shared__ float As[8][72];
    __shared__ float Bs[8][64];
    int tid = threadIdx.x;
    int tx = tid & 15, ty = tid >> 4;
    int bm = blockIdx.y * 64, bn = blockIdx.x * 64;
    float acc[8][4];
#pragma unroll
    for (int i = 0; i < 8; i++)
#pragma unroll
        for (int j = 0; j < 4; j++) acc[i][j] = 0.f;

    int arow = tid >> 1, ac4 = (tid & 1) * 4;
    int bkr = tid >> 4, bc4 = (tid & 15) * 4;
    for (int k0 = 0; k0 < K; k0 += 8) {
        int row = bm + arow;
        float4 av = make_float4(0.f, 0.f, 0.f, 0.f);
        if (row < M) av = *(const float4*)&Ax[(size_t)row * K + k0 + ac4];
        As[ac4 + 0][arow] = av.x;
        As[ac4 + 1][arow] = av.y;
        As[ac4 + 2][arow] = av.z;
        As[ac4 + 3][arow] = av.w;
        float4 bv = *(const float4*)&Bx[(size_t)(k0 + bkr) * N + bn + bc4];
        *(float4*)&Bs[bkr][bc4] = bv;
        __syncthreads();
#pragma unroll
        for (int k = 0; k < 8; k++) {
            float4 a0 = *(const float4*)&As[k][ty * 8];
            float4 a1 = *(const float4*)&As[k][ty * 8 + 4];
            float4 b0 = *(const float4*)&Bs[k][tx * 4];
            float aval[8] = {a0.x, a0.y, a0.z, a0.w, a1.x, a1.y, a1.z, a1.w};
            float bval[4] = {b0.x, b0.y, b0.z, b0.w};
#pragma unroll
            for (int i2 = 0; i2 < 8; i2++)
#pragma unroll
                for (int j2 = 0; j2 < 4; j2++) acc[i2][j2] += aval[i2] * bval[j2];
        }
        __syncthreads();
    }
#pragma unroll
    for (int i2 = 0; i2 < 8; i2++) {
        int row = bm + ty * 8 + i2;
        if (row >= M) continue;
#pragma unroll
        for (int j2 = 0; j2 < 4; j2++) {
            int col = bn + tx * 4 + j2;
            C[(size_t)row * N + col] = fmaxf(acc[i2][j2] + bias[col], 0.f);
        }
    }
}

// -------- rcnn cls/box heads --------
__global__ void k_rheads(const float* __restrict__ wrc, const float* __restrict__ brc,
                         const float* __restrict__ wrb, const float* __restrict__ brb,
                         float* __restrict__ o_log, float* __restrict__ o_del) {
    int p = blockIdx.x;
    int w = threadIdx.x >> 5, lane = threadIdx.x & 31;
    const float* hp = g_h2 + (size_t)p * 512;
    float s = 0.f;
    if (w < 2) {
        for (int k = lane; k < 512; k += 32) s += hp[k] * wrc[k * 2 + w];
    } else {
        int j = w - 2;
        for (int k = lane; k < 512; k += 32) s += hp[k] * wrb[k * 4 + j];
    }
    for (int off = 16; off > 0; off >>= 1) s += __shfl_down_sync(0xffffffffu, s, off);
    if (lane == 0) {
        if (w < 2) {
            float v = s + brc[w];
            o_log[p * 2 + w] = v;
            g_rlogits[p * 2 + w] = v;
        } else {
            int j = w - 2;
            float v = s + brb[j];
            o_del[p * 4 + j] = v;
            g_rdeltas[p * 4 + j] = v;
        }
    }
}

// -------- decode stage 2 --------
__global__ void k_decode2(float* __restrict__ dets) {
    int p = blockIdx.x * blockDim.x + threadIdx.x;
    if (p >= NPROP) return;
    float l0 = g_rlogits[p * 2], l1 = g_rlogits[p * 2 + 1];
    float m = fmaxf(l0, l1);
    float e0 = expf(l0 - m), e1 = expf(l1 - m);
    float sc = e1 / (e0 + e1);
    g_dscores[p] = sc;
    float x1 = g_props[p * 4], y1 = g_props[p * 4 + 1];
    float x2 = g_props[p * 4 + 2], y2 = g_props[p * 4 + 3];
    float w = x2 - x1, h = y2 - y1;
    float cx = x1 + 0.5f * w, cy = y1 + 0.5f * h;
    float d0 = g_rdeltas[p * 4], d1 = g_rdeltas[p * 4 + 1];
    float d2 = g_rdeltas[p * 4 + 2], d3 = g_rdeltas[p * 4 + 3];
    float ncx = cx + d0 * w, ncy = cy + d1 * h;
    float nw = w * expf(d2), nh = h * expf(d3);
    dets[p * 4]     = fminf(fmaxf(ncx - 0.5f * nw, 0.f), 255.f);
    dets[p * 4 + 1] = fminf(fmaxf(ncy - 0.5f * nh, 0.f), 255.f);
    dets[p * 4 + 2] = fminf(fmaxf(ncx + 0.5f * nw, 0.f), 255.f);
    dets[p * 4 + 3] = fminf(fmaxf(ncy + 0.5f * nh, 0.f), 255.f);
    g_s2[p] = g_valid[p] ? sc : -1.0f;
}

// -------- final dets/scores/keep2 --------
__global__ void k_final2(float* __restrict__ o_fdets, float* __restrict__ o_fsc,
                         float* __restrict__ o_keep) {
    int r = blockIdx.x * blockDim.x + threadIdx.x;
    if (r >= NPROP) return;
    int o = g_order2[r];
    int k2 = g_keep2a[r] && g_valid[o];
    float kf = k2 ? 1.f : 0.f;
    float4 d = g_sb2[r];
    o_fdets[r * 4]     = k2 ? d.x : 0.f;
    o_fdets[r * 4 + 1] = k2 ? d.y : 0.f;
    o_fdets[r * 4 + 2] = k2 ? d.z : 0.f;
    o_fdets[r * 4 + 3] = k2 ? d.w : 0.f;
    o_fsc[r] = k2 ? g_dscores[o] : 0.f;
    if (o_keep) o_keep[r] = kf;
    g_keep2f[r] = kf;
}

// -------- final masks --------
__global__ void k_fmask(float* __restrict__ o) {
    int r = blockIdx.x, i = threadIdx.x;
    int oi = g_order2[r];
    float v = g_masks[(size_t)oi * 196 + i];
    float sgm = 1.f / (1.f + expf(-v));
    o[(size_t)r * 196 + i] = sgm * g_keep2f[r];
}

// ---------------- host ----------------
extern "C" void kernel_launch(void* const* d_in, const int* in_sizes, int n_in,
                              void* d_out, int out_size) {
    const float* x      = (const float*)d_in[0];
    const float* w_bb   = (const float*)d_in[1];
    const float* b_bb   = (const float*)d_in[2];
    const float* w_rpn  = (const float*)d_in[3];
    const float* b_rpn  = (const float*)d_in[4];
    const float* w_cls  = (const float*)d_in[5];
    const float* b_cls  = (const float*)d_in[6];
    const float* w_box  = (const float*)d_in[7];
    const float* b_box  = (const float*)d_in[8];
    const float* w_fc1  = (const float*)d_in[9];
    const float* b_fc1  = (const float*)d_in[10];
    const float* w_fc2  = (const float*)d_in[11];
    const float* b_fc2  = (const float*)d_in[12];
    const float* w_rcls = (const float*)d_in[13];
    const float* b_rcls = (const float*)d_in[14];
    const float* w_rbox = (const float*)d_in[15];
    const float* b_rbox = (const float*)d_in[16];
    const float* w_m1   = (const float*)d_in[17];
    const float* b_m1   = (const float*)d_in[18];
    const float* w_m2   = (const float*)d_in[19];
    const float* b_m2   = (const float*)d_in[20];
    float* out = (float*)d_out;

    const size_t O_RPNL = 0, O_RPND = 4608, O_PROP = 13824, O_ANCH = 21824;
    const size_t O_RLOG = 31040, O_RDEL = 35040, O_RMSK = 43040;
    const size_t O_FDET = 435040, O_FMSK = 443040, O_FSC = 835040, O_KEEP = 837040;

    float *p_scores, *p_s2, *p_flat, *p_h1, *p_h2, *p_dets;
    int *p_order, *p_order2, *p_keep1, *p_keep2a;
    unsigned long long *p_mask1, *p_mask2;
    cudaGetSymbolAddress((void**)&p_scores, g_scores);
    cudaGetSymbolAddress((void**)&p_order, g_order);
    cudaGetSymbolAddress((void**)&p_s2, g_s2);
    cudaGetSymbolAddress((void**)&p_order2, g_order2);
    cudaGetSymbolAddress((void**)&p_flat, g_flat);
    cudaGetSymbolAddress((void**)&p_h1, g_h1);
    cudaGetSymbolAddress((void**)&p_h2, g_h2);
    cudaGetSymbolAddress((void**)&p_dets, g_dets);
    cudaGetSymbolAddress((void**)&p_keep1, g_keep1);
    cudaGetSymbolAddress((void**)&p_keep2a, g_keep2a);
    cudaGetSymbolAddress((void**)&p_mask1, g_mask1);
    cudaGetSymbolAddress((void**)&p_mask2, g_mask2);

    cudaFuncSetAttribute(k_roi, cudaFuncAttributeMaxDynamicSharedMemorySize, SMEM_ROI_BYTES);
    cudaFuncSetAttribute(k_roizero, cudaFuncAttributeMaxDynamicSharedMemorySize, SMEM_ROI_BYTES);

    float4* p_sb1; float* p_sa1; float4* p_sb2; float* p_sa2;
    cudaGetSymbolAddress((void**)&p_sb1, g_sb1);
    cudaGetSymbolAddress((void**)&p_sa1, g_sa1);
    cudaGetSymbolAddress((void**)&p_sb2, g_sb2);
    cudaGetSymbolAddress((void**)&p_sa2, g_sa2);

    k_backbone<<<256, 64>>>(x, w_bb, b_bb);
    k_packw<<<(64 * 64 * 12 + 255) / 256, 256>>>(w_m1);
    k_roizero<<<1, 448, SMEM_ROI_BYTES>>>(b_m1, w_m2, b_m2);
    k_rpnconv<<<256, 64>>>(w_rpn, b_rpn);
    k_heads1<<<18, 128>>>(w_cls, b_cls, w_box, b_box,
                          out + O_RPNL, out + O_RPND, out + O_ANCH);
    k_sort<4096><<<1, 1024>>>(p_scores, NANCH, p_order);
    k_gather1<<<(NANCH + 255) / 256, 256>>>();
    k_ioumask<NANCH, NW1><<<dim3(NW1, NW1), 64>>>(p_sb1, p_sa1, p_mask1, 0.5f);
    k_nmsreduce<NANCH, NW1, 2><<<1, 32>>>(p_mask1, p_keep1);
    k_select1<<<1, 1024>>>(out + O_PROP);
    k_roi<<<NPROP, 448, SMEM_ROI_BYTES>>>(b_m1, w_m2, b_m2, out + O_RMSK);

    dim3 gfc(512 / 64, (NPROP + 63) / 64);
    k_gemm64<<<gfc, 128>>>(p_flat, w_fc1, b_fc1, p_h1, NPROP, 512, 3136);
    k_gemm64<<<gfc, 128>>>(p_h1, w_fc2, b_fc2, p_h2, NPROP, 512, 512);
    k_rheads<<<NPROP, 192>>>(w_rcls, b_rcls, w_rbox, b_rbox,
                             out + O_RLOG, out + O_RDEL);
    k_decode2<<<(NPROP + 255) / 256, 256>>>(p_dets);
    k_sort<2048><<<1, 1024>>>(p_s2, NPROP, p_order2);
    k_gather2<<<(NPROP + 255) / 256, 256>>>(p_dets);
    k_ioumask<NPROP, NW2><<<dim3(NW2, NW2), 64>>>(p_sb2, p_sa2, p_mask2, 0.3f);
    k_nmsreduce<NPROP, NW2, 1><<<1, 32>>>(p_mask2, p_keep2a);
    float* o_keep = (out_size >= (int)(O_KEEP + NPROP)) ? (out + O_KEEP) : nullptr;
    k_final2<<<(NPROP + 255) / 256, 256>>>(out + O_FDET, out + O_FSC, o_keep);
    k_fmask<<<NPROP, 196>>>(out + O_FMSK);
}

// round 5
// speedup vs baseline: 2.2344x; 1.3576x over previous
#include <cuda_runtime.h>
#include <math.h>

#define NANCH 2304
#define NPROP 2000
#define NW1 36
#define NW2 32

// ---------------- scratch (device globals; no allocation) ----------------
__device__ float g_feat[64 * 256];
__device__ float g_hrpn[64 * 256];
__device__ float g_scores[NANCH];
__device__ float g_boxes[NANCH * 4];
__device__ int   g_order[NANCH];
__device__ float g_props[NPROP * 4];
__device__ int   g_valid[NPROP];
__device__ float g_flat[NPROP * 3136];
__device__ float g_h1[NPROP * 512];
__device__ float g_h2[NPROP * 512];
__device__ float g_rlogits[NPROP * 2];
__device__ float g_rdeltas[NPROP * 4];
__device__ float g_dscores[NPROP];
__device__ float g_s2[NPROP];
__device__ int   g_order2[NPROP];
__device__ float g_keep2f[NPROP];
__device__ float g_masks[NPROP * 196];
__device__ float g_dets[NPROP * 4];
__device__ float g_wt[9 * 64 * 64];              // mask-conv weights [slab][ic][oc], tf32-rounded
__device__ float g_flatz[3136];                  // canonical zero-box ROI results
__device__ float g_maskz[196];
// NMS scratch
__device__ float4 g_sb1[NANCH];
__device__ float  g_sa1[NANCH];
__device__ unsigned long long g_mask1[(size_t)NANCH * NW1];
__device__ int    g_keep1[NANCH];
__device__ float4 g_sb2[NPROP];
__device__ float  g_sa2[NPROP];
__device__ unsigned long long g_mask2[(size_t)NPROP * NW2];
__device__ int    g_keep2a[NPROP];

__device__ __forceinline__ float to_tf32(float x) {
    unsigned u;
    asm("cvt.rna.tf32.f32 %0, %1;" : "=r"(u) : "f"(x));
    return __uint_as_float(u);
}
__device__ __forceinline__ void mma_tf32(float* c, const unsigned* a,
                                         unsigned b0, unsigned b1) {
    asm volatile(
        "mma.sync.aligned.m16n8k8.row.col.f32.tf32.tf32.f32 "
        "{%0,%1,%2,%3},{%4,%5,%6,%7},{%8,%9},{%0,%1,%2,%3};"
        : "+f"(c[0]), "+f"(c[1]), "+f"(c[2]), "+f"(c[3])
        : "r"(a[0]), "r"(a[1]), "r"(a[2]), "r"(a[3]), "r"(b0), "r"(b1));
}

// ---------------- backbone: conv 3->64, k16 s16 VALID, relu (split-K x4) ------
__global__ void k_backbone(const float* __restrict__ x, const float* __restrict__ w,
                           const float* __restrict__ b) {
    __shared__ float patch[768];
    __shared__ float part[256];
    int pos = blockIdx.x;
    int h = pos >> 4, wq = pos & 15;
    int tid = threadIdx.x;     // 256
    for (int k = tid; k < 768; k += 256) {
        int ic = k >> 8, r = k & 255, iy = r >> 4, ix = r & 15;
        patch[k] = x[ic * 65536 + (h * 16 + iy) * 256 + (wq * 16 + ix)];
    }
    __syncthreads();
    int oc = tid & 63, ch = tid >> 6;
    const float* wp = w + oc * 768 + ch * 192;
    const float* pp = patch + ch * 192;
    float a0 = 0.f, a1 = 0.f;
#pragma unroll 8
    for (int k = 0; k < 192; k += 2) { a0 += pp[k] * wp[k]; a1 += pp[k + 1] * wp[k + 1]; }
    part[tid] = a0 + a1;
    __syncthreads();
    if (tid < 64) {
        float s = b[tid] + part[tid] + part[tid + 64] + part[tid + 128] + part[tid + 192];
        g_feat[tid * 256 + pos] = fmaxf(s, 0.f);
    }
}

// ---------------- rpn conv 3x3 SAME, relu (split-K x4) ----------------
__global__ void k_rpnconv(const float* __restrict__ w, const float* __restrict__ b) {
    __shared__ float part[256];
    int pos = blockIdx.x;
    int y = pos >> 4, xq = pos & 15;
    int tid = threadIdx.x;     // 256
    int oc = tid & 63, ch = tid >> 6;
    float acc = 0.f;
    for (int icl = 0; icl < 16; icl++) {
        int ic = ch * 16 + icl;
        const float* fb = g_feat + ic * 256;
        const float* wb = w + oc * 576 + ic * 9;
#pragma unroll
        for (int ky = 0; ky < 3; ky++) {
            int yy = y + ky - 1;
            if (yy < 0 || yy > 15) continue;
#pragma unroll
            for (int kx = 0; kx < 3; kx++) {
                int xx = xq + kx - 1;
                if (xx < 0 || xx > 15) continue;
                acc += fb[yy * 16 + xx] * wb[ky * 3 + kx];
            }
        }
    }
    part[tid] = acc;
    __syncthreads();
    if (tid < 64) {
        float s = b[tid] + part[tid] + part[tid + 64] + part[tid + 128] + part[tid + 192];
        g_hrpn[tid * 256 + pos] = fmaxf(s, 0.f);
    }
}

// -------- rpn heads (1x1), anchors, softmax score, decode, clip --------
__global__ void k_heads1(const float* __restrict__ wc, const float* __restrict__ bc,
                         const float* __restrict__ wb, const float* __restrict__ bb,
                         float* __restrict__ o_logits, float* __restrict__ o_deltas,
                         float* __restrict__ o_anch) {
    int i = blockIdx.x * blockDim.x + threadIdx.x;
    if (i >= NANCH) return;
    int cell = i / 9, a = i % 9;
    float l0 = bc[a * 2], l1 = bc[a * 2 + 1];
    float d0 = bb[a * 4], d1 = bb[a * 4 + 1], d2 = bb[a * 4 + 2], d3 = bb[a * 4 + 3];
    for (int ic = 0; ic < 64; ic++) {
        float f = g_hrpn[ic * 256 + cell];
        l0 += f * wc[(a * 2) * 64 + ic];
        l1 += f * wc[(a * 2 + 1) * 64 + ic];
        d0 += f * wb[(a * 4) * 64 + ic];
        d1 += f * wb[(a * 4 + 1) * 64 + ic];
        d2 += f * wb[(a * 4 + 2) * 64 + ic];
        d3 += f * wb[(a * 4 + 3) * 64 + ic];
    }
    o_logits[i * 2] = l0; o_logits[i * 2 + 1] = l1;
    o_deltas[i * 4] = d0; o_deltas[i * 4 + 1] = d1;
    o_deltas[i * 4 + 2] = d2; o_deltas[i * 4 + 3] = d3;
    float m = fmaxf(l0, l1);
    float e0 = expf(l0 - m), e1 = expf(l1 - m);
    g_scores[i] = e1 / (e0 + e1);

    const float S[3] = {32.f, 64.f, 128.f};
    const float R[3] = {0.5f, 1.f, 2.f};
    int h = cell >> 4, wq = cell & 15;
    float s = S[a / 3], r = R[a % 3];
    float ws = s * sqrtf(r), hs = s / sqrtf(r);
    float cx = (wq + 0.5f) * 16.f, cy = (h + 0.5f) * 16.f;
    float ax1 = cx - ws * 0.5f, ay1 = cy - hs * 0.5f;
    float ax2 = cx + ws * 0.5f, ay2 = cy + hs * 0.5f;
    o_anch[i * 4] = ax1; o_anch[i * 4 + 1] = ay1;
    o_anch[i * 4 + 2] = ax2; o_anch[i * 4 + 3] = ay2;

    float aw = ax2 - ax1, ah = ay2 - ay1;
    float acx = ax1 + 0.5f * aw, acy = ay1 + 0.5f * ah;
    float ncx = acx + d0 * aw, ncy = acy + d1 * ah;
    float nw = aw * expf(d2), nh = ah * expf(d3);
    g_boxes[i * 4]     = fminf(fmaxf(ncx - 0.5f * nw, 0.f), 255.f);
    g_boxes[i * 4 + 1] = fminf(fmaxf(ncy - 0.5f * nh, 0.f), 255.f);
    g_boxes[i * 4 + 2] = fminf(fmaxf(ncx + 0.5f * nw, 0.f), 255.f);
    g_boxes[i * 4 + 3] = fminf(fmaxf(ncy + 0.5f * nh, 0.f), 255.f);
}

// -------- pack mask-conv weights: [oc][ic][9] -> [slab][ic][oc], tf32-rounded ----
__global__ void k_packwt(const float* __restrict__ w) {
    int i = blockIdx.x * blockDim.x + threadIdx.x;
    if (i >= 9 * 64 * 64) return;
    int slab = i >> 12, r = i & 4095, ic = r >> 6, oc = r & 63;
    g_wt[i] = to_tf32(w[oc * 576 + ic * 9 + slab]);
}

// -------- single-block bitonic sort: descending value, stable by index --------
template <int SIZE>
__global__ void k_sort(const float* __restrict__ sc, int n, int* __restrict__ ord) {
    __shared__ unsigned long long k[SIZE];
    int tid = threadIdx.x;
    for (int i = tid; i < SIZE; i += 1024) {
        if (i < n) {
            unsigned u = __float_as_uint(sc[i]);
            unsigned o = (u & 0x80000000u) ? ~u : (u | 0x80000000u);
            k[i] = ((unsigned long long)(~o) << 32) | (unsigned)i;
        } else k[i] = 0xFFFFFFFFFFFFFFFFULL;
    }
    __syncthreads();
    for (int kk = 2; kk <= SIZE; kk <<= 1) {
        for (int j = kk >> 1; j > 0; j >>= 1) {
            for (int i = tid; i < SIZE; i += 1024) {
                int ixj = i ^ j;
                if (ixj > i) {
                    bool up = ((i & kk) == 0);
                    unsigned long long a = k[i], b = k[ixj];
                    if ((a > b) == up) { k[i] = b; k[ixj] = a; }
                }
            }
            __syncthreads();
        }
    }
    for (int i = tid; i < n; i += 1024) ord[i] = (int)(k[i] & 0xFFFFFFFFu);
}

// -------- gather sorted boxes + areas --------
__global__ void k_gather1() {
    int i = blockIdx.x * blockDim.x + threadIdx.x;
    if (i >= NANCH) return;
    int o = g_order[i];
    float4 b = *(const float4*)&g_boxes[o * 4];
    g_sb1[i] = b;
    g_sa1[i] = fmaxf(b.z - b.x, 0.f) * fmaxf(b.w - b.y, 0.f);
}
__global__ void k_gather2(const float* __restrict__ dets) {
    int i = blockIdx.x * blockDim.x + threadIdx.x;
    if (i >= NPROP) return;
    int o = g_order2[i];
    float4 b = *(const float4*)&dets[o * 4];
    g_sb2[i] = b;
    g_sa2[i] = fmaxf(b.z - b.x, 0.f) * fmaxf(b.w - b.y, 0.f);
}

// -------- IoU bitmask matrix --------
template <int N, int NW>
__global__ void k_ioumask(const float4* __restrict__ sb, const float* __restrict__ sa,
                          unsigned long long* __restrict__ mask, float thr) {
    __shared__ float4 cbx[64];
    __shared__ float car[64];
    int rb = blockIdx.y, cb = blockIdx.x;
    int t = threadIdx.x;
    int j0 = cb * 64;
    if (j0 + t < N) { cbx[t] = sb[j0 + t]; car[t] = sa[j0 + t]; }
    __syncthreads();
    int i = rb * 64 + t;
    if (i >= N) return;
    float4 bi = sb[i];
    float ai = sa[i];
    unsigned long long m = 0;
    int jmax = min(64, N - j0);
    for (int jj = 0; jj < jmax; jj++) {
        int j = j0 + jj;
        if (j <= i) continue;
        float xx1 = fmaxf(bi.x, cbx[jj].x), yy1 = fmaxf(bi.y, cbx[jj].y);
        float xx2 = fminf(bi.z, cbx[jj].z), yy2 = fminf(bi.w, cbx[jj].w);
        float inter = fmaxf(xx2 - xx1, 0.f) * fmaxf(yy2 - yy1, 0.f);
        float iou = inter / (ai + car[jj] - inter + 1e-8f);
        if (iou > thr) m |= 1ULL << jj;
    }
    mask[(size_t)i * NW + cb] = m;
}

// -------- serial greedy reduce over bitmasks; one warp, prefetched rows --------
template <int N, int NW, int LPW>
__global__ void k_nmsreduce(const unsigned long long* __restrict__ mask,
                            int* __restrict__ keep) {
    int lane = threadIdx.x;
    unsigned long long rem0 = ~0ULL, rem1 = ~0ULL;
    int w0i = lane * LPW;
    unsigned long long p0 = (w0i < NW) ? mask[w0i] : 0ULL;
    unsigned long long p1 = (LPW == 2 && w0i + 1 < NW) ? mask[w0i + 1] : 0ULL;
    for (int i = 0; i < N; i++) {
        unsigned long long c0 = p0, c1 = p1;
        if (i + 1 < N) {
            size_t base = (size_t)(i + 1) * NW;
            p0 = (w0i < NW) ? mask[base + w0i] : 0ULL;
            if (LPW == 2) p1 = (w0i + 1 < NW) ? mask[base + w0i + 1] : 0ULL;
        }
        int w = i >> 6, b = i & 63;
        int owner = w / LPW, sub = w - owner * LPW;
        unsigned long long val = (LPW == 2 && sub == 1) ? rem1 : rem0;
        unsigned long long rw = __shfl_sync(0xffffffffu, val, owner);
        int kept = (int)((rw >> b) & 1ULL);
        if (kept) { rem0 &= ~c0; if (LPW == 2) rem1 &= ~c1; }
        if (lane == 0) keep[i] = kept;
    }
}

// -------- stable kept-first selection of NPROP proposals --------
__global__ void k_select1(float* __restrict__ o_props) {
    __shared__ int s_src[NPROP];
    int tid = threadIdx.x;
    if (tid < 32) {
        const int CH = NANCH / 32;
        int beg = tid * CH, end = beg + CH;
        int cnt = 0;
        for (int i = beg; i < end; i++) cnt += g_keep1[i];
        int xsc = cnt;
        for (int off = 1; off < 32; off <<= 1) {
            int v = __shfl_up_sync(0xffffffffu, xsc, off);
            if (tid >= off) xsc += v;
        }
        int excl = xsc - cnt;
        int total = __shfl_sync(0xffffffffu, xsc, 31);
        int kpos = excl;
        int npos = total + (beg - excl);
        for (int i = beg; i < end; i++) {
            int pos = g_keep1[i] ? kpos++ : npos++;
            if (pos < NPROP) s_src[pos] = i;
        }
    }
    __syncthreads();
    for (int p = tid; p < NPROP; p += 1024) {
        int i = s_src[p];
        int v = g_keep1[i];
        float4 bb = g_sb1[i];
        float px1 = v ? bb.x : 0.f, py1 = v ? bb.y : 0.f;
        float px2 = v ? bb.z : 0.f, py2 = v ? bb.w : 0.f;
        g_props[p * 4] = px1; g_props[p * 4 + 1] = py1;
        g_props[p * 4 + 2] = px2; g_props[p * 4 + 3] = py2;
        o_props[p * 4] = px1; o_props[p * 4 + 1] = py1;
        o_props[p * 4 + 2] = px2; o_props[p * 4 + 3] = py2;
        g_valid[p] = v;
    }
}

// ===================== ROI body: tf32 MMA implicit GEMM =====================
// smem floats: cropH[16*16*68] | wslab[64*68] | w2[64] | b1[64] | grid[84]
#define CROPH_F (16 * 16 * 68)
#define WSLAB_F (64 * 68)
#define SMEM_ROI_BYTES ((CROPH_F + WSLAB_F + 64 + 64 + 96) * 4)

__device__ __forceinline__ void roi_body(
    int tid, float bx1, float by1, float bx2, float by2,
    const float* __restrict__ bm1, const float* __restrict__ wm2,
    const float* __restrict__ bm2,
    float* __restrict__ flat_out, float* __restrict__ maskA, float* __restrict__ maskB,
    float* smem)
{
    float* s_crop = smem;                    // [yH][xH][68]
    float* s_w = s_crop + CROPH_F;           // [ic][68]
    float* s_w2 = s_w + WSLAB_F;
    float* s_b1 = s_w2 + 64;
    float* s_wy = s_b1 + 64;
    float* s_wx = s_wy + 14;
    int* s_y0 = (int*)(s_wx + 14);
    int* s_y1 = s_y0 + 14;
    int* s_x0 = s_y1 + 14;
    int* s_x1 = s_x0 + 14;

    int lane = tid & 31, wrp = tid >> 5;     // 8 warps

    if (tid < 28) {
        int t = tid % 14;
        float tt = (float)t / 13.0f;
        if (tid < 14) {
            float y1n = by1 / 255.0f, y2n = by2 / 255.0f;
            float fy = (y1n + (y2n - y1n) * tt) * 15.0f;
            float y0f = fminf(fmaxf(floorf(fy), 0.f), 15.f);
            int y0 = (int)y0f;
            s_y0[t] = y0; s_y1[t] = min(y0 + 1, 15); s_wy[t] = fy - y0f;
        } else {
            float x1n = bx1 / 255.0f, x2n = bx2 / 255.0f;
            float fx = (x1n + (x2n - x1n) * tt) * 15.0f;
            float x0f = fminf(fmaxf(floorf(fx), 0.f), 15.f);
            int x0 = (int)x0f;
            s_x0[t] = x0; s_x1[t] = min(x0 + 1, 15); s_wx[t] = fx - x0f;
        }
    }
    if (tid >= 32 && tid < 96) {
        int c = tid - 32;
        s_w2[c] = wm2[c];
        s_b1[c] = bm1[c];
    }
    // zero cropH (borders + ic pad)
    for (int idx = tid; idx < CROPH_F; idx += 256) s_crop[idx] = 0.f;
    __syncthreads();

    // bilinear crop (fp32) -> cropH[(ty+1)][(tx+1)][c]
    for (int idx = tid; idx < 12544; idx += 256) {
        int c = idx / 196, r2 = idx % 196, ty = r2 / 14, tx = r2 % 14;
        const float* fb = g_feat + c * 256;
        int y0 = s_y0[ty], y1 = s_y1[ty], x0 = s_x0[tx], x1 = s_x1[tx];
        float wy = s_wy[ty], wx = s_wx[tx];
        float f00 = fb[y0 * 16 + x0], f01 = fb[y0 * 16 + x1];
        float f10 = fb[y1 * 16 + x0], f11 = fb[y1 * 16 + x1];
        float top = f00 * (1.f - wx) + f01 * wx;
        float bot = f10 * (1.f - wx) + f11 * wx;
        s_crop[((ty + 1) * 16 + (tx + 1)) * 68 + c] = top * (1.f - wy) + bot * wy;
    }
    __syncthreads();

    // pool 2x2 -> flat [64*49] (from fp32 crop — bit-exact with fp32 pipeline)
    for (int idx = tid; idx < 64 * 49; idx += 256) {
        int c = idx / 49, r2 = idx % 49, py = r2 / 7, px = r2 % 7;
        float v00 = s_crop[((2 * py + 1) * 16 + 2 * px + 1) * 68 + c];
        float v01 = s_crop[((2 * py + 1) * 16 + 2 * px + 2) * 68 + c];
        float v10 = s_crop[((2 * py + 2) * 16 + 2 * px + 1) * 68 + c];
        float v11 = s_crop[((2 * py + 2) * 16 + 2 * px + 2) * 68 + c];
        flat_out[idx] = fmaxf(fmaxf(v00, v01), fmaxf(v10, v11));
    }
    __syncthreads();

    // round crop to tf32 in place (masks path only from here on)
    for (int idx = tid; idx < CROPH_F; idx += 256) s_crop[idx] = to_tf32(s_crop[idx]);

    // per-thread A-row bases: warp owns m-tiles 2w,2w+1 (rows 32w..32w+31)
    int g = lane >> 2, q = lane & 3;
    int pb[2][2];
#pragma unroll
    for (int mt = 0; mt < 2; mt++)
#pragma unroll
        for (int hh = 0; hh < 2; hh++) {
            int p = wrp * 32 + mt * 16 + g + hh * 8;
            if (p < 196) {
                int y = p / 14, xx = p % 14;
                pb[mt][hh] = (y * 16 + xx) * 68;
            } else pb[mt][hh] = 0;
        }

    float c[2][8][4];
#pragma unroll
    for (int mt = 0; mt < 2; mt++)
#pragma unroll
        for (int nt = 0; nt < 8; nt++)
#pragma unroll
            for (int j = 0; j < 4; j++) c[mt][nt][j] = 0.f;

    for (int slab = 0; slab < 9; slab++) {
        __syncthreads();
        for (int f = tid; f < 4096; f += 256) {
            int ic = f >> 6, oc = f & 63;
            s_w[ic * 68 + oc] = g_wt[slab * 4096 + f];
        }
        __syncthreads();
        int ky = slab / 3, kx = slab % 3;
        int off = (ky * 16 + kx) * 68;
#pragma unroll 2
        for (int icT = 0; icT < 8; icT++) {
            int ab = off + icT * 8 + q;
            unsigned a[2][4];
#pragma unroll
            for (int mt = 0; mt < 2; mt++) {
                a[mt][0] = __float_as_uint(s_crop[pb[mt][0] + ab]);
                a[mt][1] = __float_as_uint(s_crop[pb[mt][1] + ab]);
                a[mt][2] = __float_as_uint(s_crop[pb[mt][0] + ab + 4]);
                a[mt][3] = __float_as_uint(s_crop[pb[mt][1] + ab + 4]);
            }
            int brow = (icT * 8 + q) * 68 + g;
#pragma unroll
            for (int nt = 0; nt < 8; nt++) {
                unsigned b0 = __float_as_uint(s_w[brow + nt * 8]);
                unsigned b1 = __float_as_uint(s_w[brow + nt * 8 + 4 * 68]);
                mma_tf32(c[0][nt], a[0], b0, b1);
                mma_tf32(c[1][nt], a[1], b0, b1);
            }
        }
    }

    // bias + relu + 1x1 conv, all in registers; reduce across 4-lane row group
    float part[2][2] = {{0.f, 0.f}, {0.f, 0.f}};
#pragma unroll
    for (int nt = 0; nt < 8; nt++) {
        int col0 = nt * 8 + q * 2, col1 = col0 + 1;
        float bA = s_b1[col0], bB = s_b1[col1];
        float w20 = s_w2[col0], w21 = s_w2[col1];
#pragma unroll
        for (int mt = 0; mt < 2; mt++) {
            part[mt][0] += fmaxf(c[mt][nt][0] + bA, 0.f) * w20
                         + fmaxf(c[mt][nt][1] + bB, 0.f) * w21;
            part[mt][1] += fmaxf(c[mt][nt][2] + bA, 0.f) * w20
                         + fmaxf(c[mt][nt][3] + bB, 0.f) * w21;
        }
    }
    float b2 = bm2[0];
#pragma unroll
    for (int mt = 0; mt < 2; mt++)
#pragma unroll
        for (int hh = 0; hh < 2; hh++) {
            float v = part[mt][hh];
            v += __shfl_xor_sync(0xffffffffu, v, 1);
            v += __shfl_xor_sync(0xffffffffu, v, 2);
            int p = wrp * 32 + mt * 16 + g + hh * 8;
            if (q == 0 && p < 196) {
                float logit = b2 + v;
                maskA[p] = logit;
                maskB[p] = logit;
            }
        }
}

// canonical zero-box ROI
__global__ void __launch_bounds__(256, 2)
k_roizero(const float* __restrict__ bm1, const float* __restrict__ wm2,
          const float* __restrict__ bm2) {
    extern __shared__ float smem_f[];
    roi_body(threadIdx.x, 0.f, 0.f, 0.f, 0.f, bm1, wm2, bm2,
             g_flatz, g_maskz, g_maskz, smem_f);
}

// per-proposal ROI (invalid -> copy canonical)
__global__ void __launch_bounds__(256, 2)
k_roi(const float* __restrict__ bm1, const float* __restrict__ wm2,
      const float* __restrict__ bm2, float* __restrict__ omask) {
    extern __shared__ float smem_f[];
    int p = blockIdx.x, tid = threadIdx.x;
    if (!g_valid[p]) {
        float* fo = g_flat + (size_t)p * 3136;
        for (int idx = tid; idx < 3136; idx += 256) fo[idx] = g_flatz[idx];
        for (int pos = tid; pos < 196; pos += 256) {
            float v = g_maskz[pos];
            omask[(size_t)p * 196 + pos] = v;
            g_masks[(size_t)p * 196 + pos] = v;
        }
        return;
    }
    roi_body(tid, g_props[p * 4], g_props[p * 4 + 1], g_props[p * 4 + 2], g_props[p * 4 + 3],
             bm1, wm2, bm2,
             g_flat + (size_t)p * 3136, omask + (size_t)p * 196,
             g_masks + (size_t)p * 196, smem_f);
}

// -------- SGEMM 64x64x8 tile, 128 threads, 8x4 micro: C = relu(A·B + bias) --------
__global__ void k_gemm64(const float* __restrict__ Ax, const float* __restrict__ Bx,
                         const float* __restrict__ bias, float* __restrict__ C,
                         int M, int N, int K) {
    __shared__ float As[8][72];
    __shared__ float Bs[8][64];
    int tid = threadIdx.x;
    int tx = tid & 15, ty = tid >> 4;
    int bm = blockIdx.y * 64, bn = blockIdx.x * 64;
    float acc[8][4];
#pragma unroll
    for (int i = 0; i < 8; i++)
#pragma unroll
        for (int j = 0; j < 4; j++) acc[i][j] = 0.f;

    int arow = tid >> 1, ac4 = (tid & 1) * 4;
    int bkr = tid >> 4, bc4 = (tid & 15) * 4;
    for (int k0 = 0; k0 < K; k0 += 8) {
        int row = bm + arow;
        float4 av = make_float4(0.f, 0.f, 0.f, 0.f);
        if (row < M) av = *(const float4*)&Ax[(size_t)row * K + k0 + ac4];
        As[ac4 + 0][arow] = av.x;
        As[ac4 + 1][arow] = av.y;
        As[ac4 + 2][arow] = av.z;
        As[ac4 + 3][arow] = av.w;
        float4 bv = *(const float4*)&Bx[(size_t)(k0 + bkr) * N + bn + bc4];
        *(float4*)&Bs[bkr][bc4] = bv;
        __syncthreads();
#pragma unroll
        for (int k = 0; k < 8; k++) {
            float4 a0 = *(const float4*)&As[k][ty * 8];
            float4 a1 = *(const float4*)&As[k][ty * 8 + 4];
            float4 b0 = *(const float4*)&Bs[k][tx * 4];
            float aval[8] = {a0.x, a0.y, a0.z, a0.w, a1.x, a1.y, a1.z, a1.w};
            float bval[4] = {b0.x, b0.y, b0.z, b0.w};
#pragma unroll
            for (int i2 = 0; i2 < 8; i2++)
#pragma unroll
                for (int j2 = 0; j2 < 4; j2++) acc[i2][j2] += aval[i2] * bval[j2];
        }
        __syncthreads();
    }
#pragma unroll
    for (int i2 = 0; i2 < 8; i2++) {
        int row = bm + ty * 8 + i2;
        if (row >= M) continue;
#pragma unroll
        for (int j2 = 0; j2 < 4; j2++) {
            int col = bn + tx * 4 + j2;
            C[(size_t)row * N + col] = fmaxf(acc[i2][j2] + bias[col], 0.f);
        }
    }
}

// -------- rcnn cls/box heads --------
__global__ void k_rheads(const float* __restrict__ wrc, const float* __restrict__ brc,
                         const float* __restrict__ wrb, const float* __restrict__ brb,
                         float* __restrict__ o_log, float* __restrict__ o_del) {
    int p = blockIdx.x;
    int w = threadIdx.x >> 5, lane = threadIdx.x & 31;
    const float* hp = g_h2 + (size_t)p * 512;
    float s = 0.f;
    if (w < 2) {
        for (int k = lane; k < 512; k += 32) s += hp[k] * wrc[k * 2 + w];
    } else {
        int j = w - 2;
        for (int k = lane; k < 512; k += 32) s += hp[k] * wrb[k * 4 + j];
    }
    for (int off = 16; off > 0; off >>= 1) s += __shfl_down_sync(0xffffffffu, s, off);
    if (lane == 0) {
        if (w < 2) {
            float v = s + brc[w];
            o_log[p * 2 + w] = v;
            g_rlogits[p * 2 + w] = v;
        } else {
            int j = w - 2;
            float v = s + brb[j];
            o_del[p * 4 + j] = v;
            g_rdeltas[p * 4 + j] = v;
        }
    }
}

// -------- decode stage 2 --------
__global__ void k_decode2(float* __restrict__ dets) {
    int p = blockIdx.x * blockDim.x + threadIdx.x;
    if (p >= NPROP) return;
    float l0 = g_rlogits[p * 2], l1 = g_rlogits[p * 2 + 1];
    float m = fmaxf(l0, l1);
    float e0 = expf(l0 - m), e1 = expf(l1 - m);
    float sc = e1 / (e0 + e1);
    g_dscores[p] = sc;
    float x1 = g_props[p * 4], y1 = g_props[p * 4 + 1];
    float x2 = g_props[p * 4 + 2], y2 = g_props[p * 4 + 3];
    float w = x2 - x1, h = y2 - y1;
    float cx = x1 + 0.5f * w, cy = y1 + 0.5f * h;
    float d0 = g_rdeltas[p * 4], d1 = g_rdeltas[p * 4 + 1];
    float d2 = g_rdeltas[p * 4 + 2], d3 = g_rdeltas[p * 4 + 3];
    float ncx = cx + d0 * w, ncy = cy + d1 * h;
    float nw = w * expf(d2), nh = h * expf(d3);
    dets[p * 4]     = fminf(fmaxf(ncx - 0.5f * nw, 0.f), 255.f);
    dets[p * 4 + 1] = fminf(fmaxf(ncy - 0.5f * nh, 0.f), 255.f);
    dets[p * 4 + 2] = fminf(fmaxf(ncx + 0.5f * nw, 0.f), 255.f);
    dets[p * 4 + 3] = fminf(fmaxf(ncy + 0.5f * nh, 0.f), 255.f);
    g_s2[p] = g_valid[p] ? sc : -1.0f;
}

// -------- final dets/scores/keep2 --------
__global__ void k_final2(float* __restrict__ o_fdets, float* __restrict__ o_fsc,
                         float* __restrict__ o_keep) {
    int r = blockIdx.x * blockDim.x + threadIdx.x;
    if (r >= NPROP) return;
    int o = g_order2[r];
    int k2 = g_keep2a[r] && g_valid[o];
    float kf = k2 ? 1.f : 0.f;
    float4 d = g_sb2[r];
    o_fdets[r * 4]     = k2 ? d.x : 0.f;
    o_fdets[r * 4 + 1] = k2 ? d.y : 0.f;
    o_fdets[r * 4 + 2] = k2 ? d.z : 0.f;
    o_fdets[r * 4 + 3] = k2 ? d.w : 0.f;
    o_fsc[r] = k2 ? g_dscores[o] : 0.f;
    if (o_keep) o_keep[r] = kf;
    g_keep2f[r] = kf;
}

// -------- final masks --------
__global__ void k_fmask(float* __restrict__ o) {
    int r = blockIdx.x, i = threadIdx.x;
    int oi = g_order2[r];
    float v = g_masks[(size_t)oi * 196 + i];
    float sgm = 1.f / (1.f + expf(-v));
    o[(size_t)r * 196 + i] = sgm * g_keep2f[r];
}

// ---------------- host ----------------
extern "C" void kernel_launch(void* const* d_in, const int* in_sizes, int n_in,
                              void* d_out, int out_size) {
    const float* x      = (const float*)d_in[0];
    const float* w_bb   = (const float*)d_in[1];
    const float* b_bb   = (const float*)d_in[2];
    const float* w_rpn  = (const float*)d_in[3];
    const float* b_rpn  = (const float*)d_in[4];
    const float* w_cls  = (const float*)d_in[5];
    const float* b_cls  = (const float*)d_in[6];
    const float* w_box  = (const float*)d_in[7];
    const float* b_box  = (const float*)d_in[8];
    const float* w_fc1  = (const float*)d_in[9];
    const float* b_fc1  = (const float*)d_in[10];
    const float* w_fc2  = (const float*)d_in[11];
    const float* b_fc2  = (const float*)d_in[12];
    const float* w_rcls = (const float*)d_in[13];
    const float* b_rcls = (const float*)d_in[14];
    const float* w_rbox = (const float*)d_in[15];
    const float* b_rbox = (const float*)d_in[16];
    const float* w_m1   = (const float*)d_in[17];
    const float* b_m1   = (const float*)d_in[18];
    const float* w_m2   = (const float*)d_in[19];
    const float* b_m2   = (const float*)d_in[20];
    float* out = (float*)d_out;

    const size_t O_RPNL = 0, O_RPND = 4608, O_PROP = 13824, O_ANCH = 21824;
    const size_t O_RLOG = 31040, O_RDEL = 35040, O_RMSK = 43040;
    const size_t O_FDET = 435040, O_FMSK = 443040, O_FSC = 835040, O_KEEP = 837040;

    float *p_scores, *p_s2, *p_flat, *p_h1, *p_h2, *p_dets;
    int *p_order, *p_order2, *p_keep1, *p_keep2a;
    unsigned long long *p_mask1, *p_mask2;
    cudaGetSymbolAddress((void**)&p_scores, g_scores);
    cudaGetSymbolAddress((void**)&p_order, g_order);
    cudaGetSymbolAddress((void**)&p_s2, g_s2);
    cudaGetSymbolAddress((void**)&p_order2, g_order2);
    cudaGetSymbolAddress((void**)&p_flat, g_flat);
    cudaGetSymbolAddress((void**)&p_h1, g_h1);
    cudaGetSymbolAddress((void**)&p_h2, g_h2);
    cudaGetSymbolAddress((void**)&p_dets, g_dets);
    cudaGetSymbolAddress((void**)&p_keep1, g_keep1);
    cudaGetSymbolAddress((void**)&p_keep2a, g_keep2a);
    cudaGetSymbolAddress((void**)&p_mask1, g_mask1);
    cudaGetSymbolAddress((void**)&p_mask2, g_mask2);

    cudaFuncSetAttribute(k_roi, cudaFuncAttributeMaxDynamicSharedMemorySize, SMEM_ROI_BYTES);
    cudaFuncSetAttribute(k_roizero, cudaFuncAttributeMaxDynamicSharedMemorySize, SMEM_ROI_BYTES);

    float4* p_sb1; float* p_sa1; float4* p_sb2; float* p_sa2;
    cudaGetSymbolAddress((void**)&p_sb1, g_sb1);
    cudaGetSymbolAddress((void**)&p_sa1, g_sa1);
    cudaGetSymbolAddress((void**)&p_sb2, g_sb2);
    cudaGetSymbolAddress((void**)&p_sa2, g_sa2);

    k_backbone<<<256, 256>>>(x, w_bb, b_bb);
    k_packwt<<<(9 * 64 * 64 + 255) / 256, 256>>>(w_m1);
    k_roizero<<<1, 256, SMEM_ROI_BYTES>>>(b_m1, w_m2, b_m2);
    k_rpnconv<<<256, 256>>>(w_rpn, b_rpn);
    k_heads1<<<18, 128>>>(w_cls, b_cls, w_box, b_box,
                          out + O_RPNL, out + O_RPND, out + O_ANCH);
    k_sort<4096><<<1, 1024>>>(p_scores, NANCH, p_order);
    k_gather1<<<(NANCH + 255) / 256, 256>>>();
    k_ioumask<NANCH, NW1><<<dim3(NW1, NW1), 64>>>(p_sb1, p_sa1, p_mask1, 0.5f);
    k_nmsreduce<NANCH, NW1, 2><<<1, 32>>>(p_mask1, p_keep1);
    k_select1<<<1, 1024>>>(out + O_PROP);
    k_roi<<<NPROP, 256, SMEM_ROI_BYTES>>>(b_m1, w_m2, b_m2, out + O_RMSK);

    dim3 gfc(512 / 64, (NPROP + 63) / 64);
    k_gemm64<<<gfc, 128>>>(p_flat, w_fc1, b_fc1, p_h1, NPROP, 512, 3136);
    k_gemm64<<<gfc, 128>>>(p_h1, w_fc2, b_fc2, p_h2, NPROP, 512, 512);
    k_rheads<<<NPROP, 192>>>(w_rcls, b_rcls, w_rbox, b_rbox,
                             out + O_RLOG, out + O_RDEL);
    k_decode2<<<(NPROP + 255) / 256, 256>>>(p_dets);
    k_sort<2048><<<1, 1024>>>(p_s2, NPROP, p_order2);
    k_gather2<<<(NPROP + 255) / 256, 256>>>(p_dets);
    k_ioumask<NPROP, NW2><<<dim3(NW2, NW2), 64>>>(p_sb2, p_sa2, p_mask2, 0.3f);
    k_nmsreduce<NPROP, NW2, 1><<<1, 32>>>(p_mask2, p_keep2a);
    float* o_keep = (out_size >= (int)(O_KEEP + NPROP)) ? (out + O_KEEP) : nullptr;
    k_final2<<<(NPROP + 255) / 256, 256>>>(out + O_FDET, out + O_FSC, o_keep);
    k_fmask<<<NPROP, 196>>>(out + O_FMSK);
}

// round 6
// speedup vs baseline: 2.8106x; 1.2579x over previous
#include <cuda_runtime.h>
#include <math.h>

#define NANCH 2304
#define NPROP 2000
#define NW1 36
#define NW2 32

// ---------------- scratch (device globals; no allocation) ----------------
__device__ float g_feat[64 * 256];
__device__ float g_featT[256 * 64];              // [y][x][c] for vectorized crop
__device__ float g_hrpn[64 * 256];
__device__ float g_scores[NANCH];
__device__ float g_boxes[NANCH * 4];
__device__ int   g_order[NANCH];
__device__ float g_props[NPROP * 4];
__device__ int   g_valid[NPROP];
__device__ float g_flat[NPROP * 3136];
__device__ float g_h1[NPROP * 512];
__device__ float g_h2[NPROP * 512];
__device__ float g_rlogits[NPROP * 2];
__device__ float g_rdeltas[NPROP * 4];
__device__ float g_dscores[NPROP];
__device__ float g_s2[NPROP];
__device__ int   g_order2[NPROP];
__device__ float g_keep2f[NPROP];
__device__ float g_masks[NPROP * 196];
__device__ float g_dets[NPROP * 4];
__device__ float g_wt[9 * 64 * 64];              // mask-conv weights [slab][ic][oc], tf32
__device__ float g_flatz[3136];                  // canonical zero-box ROI results
__device__ float g_maskz[196];
// NMS scratch
__device__ float4 g_sb1[NANCH];
__device__ float  g_sa1[NANCH];
__device__ unsigned long long g_mask1[(size_t)NANCH * NW1];
__device__ int    g_keep1[NANCH];
__device__ float4 g_sb2[NPROP];
__device__ float  g_sa2[NPROP];
__device__ unsigned long long g_mask2[(size_t)NPROP * NW2];
__device__ int    g_keep2a[NPROP];

__device__ __forceinline__ float to_tf32(float x) {
    unsigned u;
    asm("cvt.rna.tf32.f32 %0, %1;" : "=r"(u) : "f"(x));
    return __uint_as_float(u);
}
__device__ __forceinline__ void mma_tf32(float* c, const unsigned* a,
                                         unsigned b0, unsigned b1) {
    asm volatile(
        "mma.sync.aligned.m16n8k8.row.col.f32.tf32.tf32.f32 "
        "{%0,%1,%2,%3},{%4,%5,%6,%7},{%8,%9},{%0,%1,%2,%3};"
        : "+f"(c[0]), "+f"(c[1]), "+f"(c[2]), "+f"(c[3])
        : "r"(a[0]), "r"(a[1]), "r"(a[2]), "r"(a[3]), "r"(b0), "r"(b1));
}

// ---------------- backbone: conv 3->64, k16 s16 VALID, relu (split-K x4) ------
__global__ void k_backbone(const float* __restrict__ x, const float* __restrict__ w,
                           const float* __restrict__ b) {
    __shared__ float patch[768];
    __shared__ float part[256];
    int pos = blockIdx.x;
    int h = pos >> 4, wq = pos & 15;
    int tid = threadIdx.x;     // 256
    for (int k = tid; k < 768; k += 256) {
        int ic = k >> 8, r = k & 255, iy = r >> 4, ix = r & 15;
        patch[k] = x[ic * 65536 + (h * 16 + iy) * 256 + (wq * 16 + ix)];
    }
    __syncthreads();
    int oc = tid & 63, ch = tid >> 6;
    const float* wp = w + oc * 768 + ch * 192;
    const float* pp = patch + ch * 192;
    float a0 = 0.f, a1 = 0.f;
#pragma unroll 8
    for (int k = 0; k < 192; k += 2) { a0 += pp[k] * wp[k]; a1 += pp[k + 1] * wp[k + 1]; }
    part[tid] = a0 + a1;
    __syncthreads();
    if (tid < 64) {
        float s = b[tid] + part[tid] + part[tid + 64] + part[tid + 128] + part[tid + 192];
        float v = fmaxf(s, 0.f);
        g_feat[tid * 256 + pos] = v;
        g_featT[pos * 64 + tid] = v;
    }
}

// ---------------- rpn conv 3x3 SAME, relu (split-K x4, dual acc) ----------------
__global__ void k_rpnconv(const float* __restrict__ w, const float* __restrict__ b) {
    __shared__ float part[256];
    int pos = blockIdx.x;
    int y = pos >> 4, xq = pos & 15;
    int tid = threadIdx.x;     // 256
    int oc = tid & 63, ch = tid >> 6;
    float acc0 = 0.f, acc1 = 0.f;
    for (int icl = 0; icl < 16; icl += 2) {
        int ic = ch * 16 + icl;
        const float* fb0 = g_feat + ic * 256;
        const float* fb1 = fb0 + 256;
        const float* wb0 = w + oc * 576 + ic * 9;
        const float* wb1 = wb0 + 9;
#pragma unroll
        for (int ky = 0; ky < 3; ky++) {
            int yy = y + ky - 1;
            if (yy < 0 || yy > 15) continue;
#pragma unroll
            for (int kx = 0; kx < 3; kx++) {
                int xx = xq + kx - 1;
                if (xx < 0 || xx > 15) continue;
                acc0 += fb0[yy * 16 + xx] * wb0[ky * 3 + kx];
                acc1 += fb1[yy * 16 + xx] * wb1[ky * 3 + kx];
            }
        }
    }
    part[tid] = acc0 + acc1;
    __syncthreads();
    if (tid < 64) {
        float s = b[tid] + part[tid] + part[tid + 64] + part[tid + 128] + part[tid + 192];
        g_hrpn[tid * 256 + pos] = fmaxf(s, 0.f);
    }
}

// -------- rpn heads (1x1), anchors, softmax score, decode, clip --------
__global__ void k_heads1(const float* __restrict__ wc, const float* __restrict__ bc,
                         const float* __restrict__ wb, const float* __restrict__ bb,
                         float* __restrict__ o_logits, float* __restrict__ o_deltas,
                         float* __restrict__ o_anch) {
    int i = blockIdx.x * blockDim.x + threadIdx.x;
    if (i >= NANCH) return;
    int cell = i / 9, a = i % 9;
    float l0 = bc[a * 2], l1 = bc[a * 2 + 1];
    float d0 = bb[a * 4], d1 = bb[a * 4 + 1], d2 = bb[a * 4 + 2], d3 = bb[a * 4 + 3];
    for (int ic = 0; ic < 64; ic++) {
        float f = g_hrpn[ic * 256 + cell];
        l0 += f * wc[(a * 2) * 64 + ic];
        l1 += f * wc[(a * 2 + 1) * 64 + ic];
        d0 += f * wb[(a * 4) * 64 + ic];
        d1 += f * wb[(a * 4 + 1) * 64 + ic];
        d2 += f * wb[(a * 4 + 2) * 64 + ic];
        d3 += f * wb[(a * 4 + 3) * 64 + ic];
    }
    o_logits[i * 2] = l0; o_logits[i * 2 + 1] = l1;
    o_deltas[i * 4] = d0; o_deltas[i * 4 + 1] = d1;
    o_deltas[i * 4 + 2] = d2; o_deltas[i * 4 + 3] = d3;
    float m = fmaxf(l0, l1);
    float e0 = expf(l0 - m), e1 = expf(l1 - m);
    g_scores[i] = e1 / (e0 + e1);

    const float S[3] = {32.f, 64.f, 128.f};
    const float R[3] = {0.5f, 1.f, 2.f};
    int h = cell >> 4, wq = cell & 15;
    float s = S[a / 3], r = R[a % 3];
    float ws = s * sqrtf(r), hs = s / sqrtf(r);
    float cx = (wq + 0.5f) * 16.f, cy = (h + 0.5f) * 16.f;
    float ax1 = cx - ws * 0.5f, ay1 = cy - hs * 0.5f;
    float ax2 = cx + ws * 0.5f, ay2 = cy + hs * 0.5f;
    o_anch[i * 4] = ax1; o_anch[i * 4 + 1] = ay1;
    o_anch[i * 4 + 2] = ax2; o_anch[i * 4 + 3] = ay2;

    float aw = ax2 - ax1, ah = ay2 - ay1;
    float acx = ax1 + 0.5f * aw, acy = ay1 + 0.5f * ah;
    float ncx = acx + d0 * aw, ncy = acy + d1 * ah;
    float nw = aw * expf(d2), nh = ah * expf(d3);
    g_boxes[i * 4]     = fminf(fmaxf(ncx - 0.5f * nw, 0.f), 255.f);
    g_boxes[i * 4 + 1] = fminf(fmaxf(ncy - 0.5f * nh, 0.f), 255.f);
    g_boxes[i * 4 + 2] = fminf(fmaxf(ncx + 0.5f * nw, 0.f), 255.f);
    g_boxes[i * 4 + 3] = fminf(fmaxf(ncy + 0.5f * nh, 0.f), 255.f);
}

// -------- pack mask-conv weights: [oc][ic][9] -> [slab][ic][oc], tf32-rounded ----
__global__ void k_packwt(const float* __restrict__ w) {
    int i = blockIdx.x * blockDim.x + threadIdx.x;
    if (i >= 9 * 64 * 64) return;
    int slab = i >> 12, r = i & 4095, ic = r >> 6, oc = r & 63;
    g_wt[i] = to_tf32(w[oc * 576 + ic * 9 + slab]);
}

// -------- single-block bitonic sort: descending value, stable by index --------
template <int SIZE>
__global__ void k_sort(const float* __restrict__ sc, int n, int* __restrict__ ord) {
    __shared__ unsigned long long k[SIZE];
    int tid = threadIdx.x;
    for (int i = tid; i < SIZE; i += 1024) {
        if (i < n) {
            unsigned u = __float_as_uint(sc[i]);
            unsigned o = (u & 0x80000000u) ? ~u : (u | 0x80000000u);
            k[i] = ((unsigned long long)(~o) << 32) | (unsigned)i;
        } else k[i] = 0xFFFFFFFFFFFFFFFFULL;
    }
    __syncthreads();
    for (int kk = 2; kk <= SIZE; kk <<= 1) {
        for (int j = kk >> 1; j > 0; j >>= 1) {
            for (int i = tid; i < SIZE; i += 1024) {
                int ixj = i ^ j;
                if (ixj > i) {
                    bool up = ((i & kk) == 0);
                    unsigned long long a = k[i], b = k[ixj];
                    if ((a > b) == up) { k[i] = b; k[ixj] = a; }
                }
            }
            __syncthreads();
        }
    }
    for (int i = tid; i < n; i += 1024) ord[i] = (int)(k[i] & 0xFFFFFFFFu);
}

// -------- gather sorted boxes + areas --------
__global__ void k_gather1() {
    int i = blockIdx.x * blockDim.x + threadIdx.x;
    if (i >= NANCH) return;
    int o = g_order[i];
    float4 b = *(const float4*)&g_boxes[o * 4];
    g_sb1[i] = b;
    g_sa1[i] = fmaxf(b.z - b.x, 0.f) * fmaxf(b.w - b.y, 0.f);
}
__global__ void k_gather2(const float* __restrict__ dets) {
    int i = blockIdx.x * blockDim.x + threadIdx.x;
    if (i >= NPROP) return;
    int o = g_order2[i];
    float4 b = *(const float4*)&dets[o * 4];
    g_sb2[i] = b;
    g_sa2[i] = fmaxf(b.z - b.x, 0.f) * fmaxf(b.w - b.y, 0.f);
}

// -------- IoU bitmask matrix --------
template <int N, int NW>
__global__ void k_ioumask(const float4* __restrict__ sb, const float* __restrict__ sa,
                          unsigned long long* __restrict__ mask, float thr) {
    __shared__ float4 cbx[64];
    __shared__ float car[64];
    int rb = blockIdx.y, cb = blockIdx.x;
    int t = threadIdx.x;
    int j0 = cb * 64;
    if (j0 + t < N) { cbx[t] = sb[j0 + t]; car[t] = sa[j0 + t]; }
    __syncthreads();
    int i = rb * 64 + t;
    if (i >= N) return;
    float4 bi = sb[i];
    float ai = sa[i];
    unsigned long long m = 0;
    int jmax = min(64, N - j0);
    for (int jj = 0; jj < jmax; jj++) {
        int j = j0 + jj;
        if (j <= i) continue;
        float xx1 = fmaxf(bi.x, cbx[jj].x), yy1 = fmaxf(bi.y, cbx[jj].y);
        float xx2 = fminf(bi.z, cbx[jj].z), yy2 = fminf(bi.w, cbx[jj].w);
        float inter = fmaxf(xx2 - xx1, 0.f) * fmaxf(yy2 - yy1, 0.f);
        float iou = inter / (ai + car[jj] - inter + 1e-8f);
        if (iou > thr) m |= 1ULL << jj;
    }
    mask[(size_t)i * NW + cb] = m;
}

// -------- chunked exact greedy reduce over bitmasks; one warp --------
template <int N, int NW>
__global__ void k_nmsreduce(const unsigned long long* __restrict__ mask,
                            int* __restrict__ keep) {
    __shared__ unsigned long long s_blk[64];
    int lane = threadIdx.x;                      // 32
    unsigned long long remv0 = 0ULL, remv1 = 0ULL;   // lane owns words lane, lane+32
    const int NC = (N + 63) / 64;
    for (int cb = 0; cb < NC; cb++) {
        int j0 = cb * 64;
        int jmax = min(64, N - j0);
        for (int t = lane; t < jmax; t += 32)
            s_blk[t] = mask[(size_t)(j0 + t) * NW + cb];
        __syncwarp();
        int owner = cb & 31;
        unsigned long long r = __shfl_sync(0xffffffffu, (cb < 32) ? remv0 : remv1, owner);
        unsigned long long kept = 0ULL;
        if (lane == 0) {
#pragma unroll 4
            for (int jj = 0; jj < jmax; jj++) {
                if (!((r >> jj) & 1ULL)) {
                    kept |= 1ULL << jj;
                    r |= s_blk[jj];
                }
            }
        }
        kept = __shfl_sync(0xffffffffu, kept, 0);
        r = __shfl_sync(0xffffffffu, r, 0);
        if (lane == owner) { if (cb < 32) remv0 = r; else remv1 = r; }
        for (int t = lane; t < jmax; t += 32)
            keep[j0 + t] = (int)((kept >> t) & 1ULL);
        // parallel OR of kept rows into words > cb
        int w1 = lane, w2 = lane + 32;
        bool u1 = (w1 > cb) && (w1 < NW), u2 = (w2 > cb) && (w2 < NW);
        for (int jj = 0; jj < jmax; jj++) {
            if ((kept >> jj) & 1ULL) {
                const unsigned long long* row = mask + (size_t)(j0 + jj) * NW;
                if (u1) remv0 |= row[w1];
                if (u2) remv1 |= row[w2];
            }
        }
        __syncwarp();
    }
}

// -------- stable kept-first selection of NPROP proposals --------
__global__ void k_select1(float* __restrict__ o_props) {
    __shared__ int s_src[NPROP];
    int tid = threadIdx.x;
    if (tid < 32) {
        const int CH = NANCH / 32;
        int beg = tid * CH, end = beg + CH;
        int cnt = 0;
        for (int i = beg; i < end; i++) cnt += g_keep1[i];
        int xsc = cnt;
        for (int off = 1; off < 32; off <<= 1) {
            int v = __shfl_up_sync(0xffffffffu, xsc, off);
            if (tid >= off) xsc += v;
        }
        int excl = xsc - cnt;
        int total = __shfl_sync(0xffffffffu, xsc, 31);
        int kpos = excl;
        int npos = total + (beg - excl);
        for (int i = beg; i < end; i++) {
            int pos = g_keep1[i] ? kpos++ : npos++;
            if (pos < NPROP) s_src[pos] = i;
        }
    }
    __syncthreads();
    for (int p = tid; p < NPROP; p += 1024) {
        int i = s_src[p];
        int v = g_keep1[i];
        float4 bb = g_sb1[i];
        float px1 = v ? bb.x : 0.f, py1 = v ? bb.y : 0.f;
        float px2 = v ? bb.z : 0.f, py2 = v ? bb.w : 0.f;
        g_props[p * 4] = px1; g_props[p * 4 + 1] = py1;
        g_props[p * 4 + 2] = px2; g_props[p * 4 + 3] = py2;
        o_props[p * 4] = px1; o_props[p * 4 + 1] = py1;
        o_props[p * 4 + 2] = px2; o_props[p * 4 + 3] = py2;
        g_valid[p] = v;
    }
}

// ===================== ROI body: tf32 MMA implicit GEMM =====================
#define CROPH_F (16 * 16 * 68)
#define WSLAB_F (64 * 68)
#define SMEM_ROI_BYTES ((CROPH_F + WSLAB_F + 64 + 64 + 96) * 4)

__device__ __forceinline__ void roi_body(
    int tid, float bx1, float by1, float bx2, float by2,
    const float* __restrict__ bm1, const float* __restrict__ wm2,
    const float* __restrict__ bm2,
    float* __restrict__ flat_out, float* __restrict__ maskA, float* __restrict__ maskB,
    float* smem)
{
    float* s_crop = smem;                    // [yH][xH][68]
    float* s_w = s_crop + CROPH_F;           // [ic][68]
    float* s_w2 = s_w + WSLAB_F;
    float* s_b1 = s_w2 + 64;
    float* s_wy = s_b1 + 64;
    float* s_wx = s_wy + 14;
    int* s_y0 = (int*)(s_wx + 14);
    int* s_y1 = s_y0 + 14;
    int* s_x0 = s_y1 + 14;
    int* s_x1 = s_x0 + 14;

    int lane = tid & 31, wrp = tid >> 5;     // 8 warps

    if (tid < 28) {
        int t = tid % 14;
        float tt = (float)t / 13.0f;
        if (tid < 14) {
            float y1n = by1 / 255.0f, y2n = by2 / 255.0f;
            float fy = (y1n + (y2n - y1n) * tt) * 15.0f;
            float y0f = fminf(fmaxf(floorf(fy), 0.f), 15.f);
            int y0 = (int)y0f;
            s_y0[t] = y0; s_y1[t] = min(y0 + 1, 15); s_wy[t] = fy - y0f;
        } else {
            float x1n = bx1 / 255.0f, x2n = bx2 / 255.0f;
            float fx = (x1n + (x2n - x1n) * tt) * 15.0f;
            float x0f = fminf(fmaxf(floorf(fx), 0.f), 15.f);
            int x0 = (int)x0f;
            s_x0[t] = x0; s_x1[t] = min(x0 + 1, 15); s_wx[t] = fx - x0f;
        }
    }
    if (tid >= 32 && tid < 96) {
        int c = tid - 32;
        s_w2[c] = wm2[c];
        s_b1[c] = bm1[c];
    }
    // zero cropH (borders + ic pad), float4
    for (int idx = tid; idx < CROPH_F / 4; idx += 256)
        ((float4*)s_crop)[idx] = make_float4(0.f, 0.f, 0.f, 0.f);
    __syncthreads();

    // bilinear crop (fp32), 4 channels per thread-iter via featT [y][x][c]
    const float4* ft4 = (const float4*)g_featT;
    for (int idx = tid; idx < 3136; idx += 256) {
        int pos = idx >> 4, c4 = idx & 15;
        int ty = pos / 14, tx = pos - ty * 14;
        int y0 = s_y0[ty], y1 = s_y1[ty], x0 = s_x0[tx], x1 = s_x1[tx];
        float wy = s_wy[ty], wx = s_wx[tx];
        float4 f00 = ft4[(y0 * 16 + x0) * 16 + c4];
        float4 f01 = ft4[(y0 * 16 + x1) * 16 + c4];
        float4 f10 = ft4[(y1 * 16 + x0) * 16 + c4];
        float4 f11 = ft4[(y1 * 16 + x1) * 16 + c4];
        float4 v;
        {
            float top = f00.x * (1.f - wx) + f01.x * wx;
            float bot = f10.x * (1.f - wx) + f11.x * wx;
            v.x = top * (1.f - wy) + bot * wy;
        }
        {
            float top = f00.y * (1.f - wx) + f01.y * wx;
            float bot = f10.y * (1.f - wx) + f11.y * wx;
            v.y = top * (1.f - wy) + bot * wy;
        }
        {
            float top = f00.z * (1.f - wx) + f01.z * wx;
            float bot = f10.z * (1.f - wx) + f11.z * wx;
            v.z = top * (1.f - wy) + bot * wy;
        }
        {
            float top = f00.w * (1.f - wx) + f01.w * wx;
            float bot = f10.w * (1.f - wx) + f11.w * wx;
            v.w = top * (1.f - wy) + bot * wy;
        }
        *(float4*)&s_crop[((ty + 1) * 16 + (tx + 1)) * 68 + c4 * 4] = v;
    }
    __syncthreads();

    // pool 2x2 -> flat [64*49] (fp32 crop — bit-exact with fp32 pipeline)
    for (int idx = tid; idx < 784; idx += 256) {
        int pos = idx >> 4, c4 = idx & 15;
        int py = pos / 7, px = pos - py * 7;
        const float4* r0a = (const float4*)&s_crop[((2 * py + 1) * 16 + 2 * px + 1) * 68 + c4 * 4];
        const float4* r0b = (const float4*)&s_crop[((2 * py + 1) * 16 + 2 * px + 2) * 68 + c4 * 4];
        const float4* r1a = (const float4*)&s_crop[((2 * py + 2) * 16 + 2 * px + 1) * 68 + c4 * 4];
        const float4* r1b = (const float4*)&s_crop[((2 * py + 2) * 16 + 2 * px + 2) * 68 + c4 * 4];
        float4 a = *r0a, b = *r0b, c = *r1a, d = *r1b;
        int base = pos;  // py*7+px
        flat_out[(c4 * 4 + 0) * 49 + base] = fmaxf(fmaxf(a.x, b.x), fmaxf(c.x, d.x));
        flat_out[(c4 * 4 + 1) * 49 + base] = fmaxf(fmaxf(a.y, b.y), fmaxf(c.y, d.y));
        flat_out[(c4 * 4 + 2) * 49 + base] = fmaxf(fmaxf(a.z, b.z), fmaxf(c.z, d.z));
        flat_out[(c4 * 4 + 3) * 49 + base] = fmaxf(fmaxf(a.w, b.w), fmaxf(c.w, d.w));
    }
    __syncthreads();

    // round crop to tf32 in place (masks path only), float4
    for (int idx = tid; idx < CROPH_F / 4; idx += 256) {
        float4 v = ((float4*)s_crop)[idx];
        v.x = to_tf32(v.x); v.y = to_tf32(v.y); v.z = to_tf32(v.z); v.w = to_tf32(v.w);
        ((float4*)s_crop)[idx] = v;
    }

    // per-thread A-row bases: warp owns m-tiles 2w,2w+1 (rows 32w..32w+31)
    int g = lane >> 2, q = lane & 3;
    int pb[2][2];
#pragma unroll
    for (int mt = 0; mt < 2; mt++)
#pragma unroll
        for (int hh = 0; hh < 2; hh++) {
            int p = wrp * 32 + mt * 16 + g + hh * 8;
            if (p < 196) {
                int y = p / 14, xx = p % 14;
                pb[mt][hh] = (y * 16 + xx) * 68;
            } else pb[mt][hh] = 0;
        }

    float c[2][8][4];
#pragma unroll
    for (int mt = 0; mt < 2; mt++)
#pragma unroll
        for (int nt = 0; nt < 8; nt++)
#pragma unroll
            for (int j = 0; j < 4; j++) c[mt][nt][j] = 0.f;

    for (int slab = 0; slab < 9; slab++) {
        __syncthreads();
        for (int f = tid; f < 4096; f += 256) {
            int ic = f >> 6, oc = f & 63;
            s_w[ic * 68 + oc] = g_wt[slab * 4096 + f];
        }
        __syncthreads();
        int ky = slab / 3, kx = slab % 3;
        int off = (ky * 16 + kx) * 68;
#pragma unroll 2
        for (int icT = 0; icT < 8; icT++) {
            int ab = off + icT * 8 + q;
            unsigned a[2][4];
#pragma unroll
            for (int mt = 0; mt < 2; mt++) {
                a[mt][0] = __float_as_uint(s_crop[pb[mt][0] + ab]);
                a[mt][1] = __float_as_uint(s_crop[pb[mt][1] + ab]);
                a[mt][2] = __float_as_uint(s_crop[pb[mt][0] + ab + 4]);
                a[mt][3] = __float_as_uint(s_crop[pb[mt][1] + ab + 4]);
            }
            int brow = (icT * 8 + q) * 68 + g;
#pragma unroll
            for (int nt = 0; nt < 8; nt++) {
                unsigned b0 = __float_as_uint(s_w[brow + nt * 8]);
                unsigned b1 = __float_as_uint(s_w[brow + nt * 8 + 4 * 68]);
                mma_tf32(c[0][nt], a[0], b0, b1);
                mma_tf32(c[1][nt], a[1], b0, b1);
            }
        }
    }

    // bias + relu + 1x1 conv in registers; reduce across 4-lane row group
    float part[2][2] = {{0.f, 0.f}, {0.f, 0.f}};
#pragma unroll
    for (int nt = 0; nt < 8; nt++) {
        int col0 = nt * 8 + q * 2, col1 = col0 + 1;
        float bA = s_b1[col0], bB = s_b1[col1];
        float w20 = s_w2[col0], w21 = s_w2[col1];
#pragma unroll
        for (int mt = 0; mt < 2; mt++) {
            part[mt][0] += fmaxf(c[mt][nt][0] + bA, 0.f) * w20
                         + fmaxf(c[mt][nt][1] + bB, 0.f) * w21;
            part[mt][1] += fmaxf(c[mt][nt][2] + bA, 0.f) * w20
                         + fmaxf(c[mt][nt][3] + bB, 0.f) * w21;
        }
    }
    float b2 = bm2[0];
#pragma unroll
    for (int mt = 0; mt < 2; mt++)
#pragma unroll
        for (int hh = 0; hh < 2; hh++) {
            float v = part[mt][hh];
            v += __shfl_xor_sync(0xffffffffu, v, 1);
            v += __shfl_xor_sync(0xffffffffu, v, 2);
            int p = wrp * 32 + mt * 16 + g + hh * 8;
            if (q == 0 && p < 196) {
                float logit = b2 + v;
                maskA[p] = logit;
                maskB[p] = logit;
            }
        }
}

// canonical zero-box ROI
__global__ void __launch_bounds__(256, 2)
k_roizero(const float* __restrict__ bm1, const float* __restrict__ wm2,
          const float* __restrict__ bm2) {
    extern __shared__ float smem_f[];
    roi_body(threadIdx.x, 0.f, 0.f, 0.f, 0.f, bm1, wm2, bm2,
             g_flatz, g_maskz, g_maskz, smem_f);
}

// per-proposal ROI (invalid -> copy canonical)
__global__ void __launch_bounds__(256, 2)
k_roi(const float* __restrict__ bm1, const float* __restrict__ wm2,
      const float* __restrict__ bm2, float* __restrict__ omask) {
    extern __shared__ float smem_f[];
    int p = blockIdx.x, tid = threadIdx.x;
    if (!g_valid[p]) {
        float* fo = g_flat + (size_t)p * 3136;
        for (int idx = tid; idx < 784; idx += 256)
            ((float4*)fo)[idx] = ((const float4*)g_flatz)[idx];
        for (int pos = tid; pos < 196; pos += 256) {
            float v = g_maskz[pos];
            omask[(size_t)p * 196 + pos] = v;
            g_masks[(size_t)p * 196 + pos] = v;
        }
        return;
    }
    roi_body(tid, g_props[p * 4], g_props[p * 4 + 1], g_props[p * 4 + 2], g_props[p * 4 + 3],
             bm1, wm2, bm2,
             g_flat + (size_t)p * 3136, omask + (size_t)p * 196,
             g_masks + (size_t)p * 196, smem_f);
}

// -------- SGEMM 64x64x8 tile, 128 threads, 8x4 micro: C = relu(A·B + bias) --------
__global__ void k_gemm64(const float* __restrict__ Ax, const float* __restrict__ Bx,
                         const float* __restrict__ bias, float* __restrict__ C,
                         int M, int N, int K) {
    __shared__ float As[8][72];
    __shared__ float Bs[8][64];
    int tid = threadIdx.x;
    int tx = tid & 15, ty = tid >> 4;
    int bm = blockIdx.y * 64, bn = blockIdx.x * 64;
    float acc[8][4];
#pragma unroll
    for (int i = 0; i < 8; i++)
#pragma unroll
        for (int j = 0; j < 4; j++) acc[i][j] = 0.f;

    int arow = tid >> 1, ac4 = (tid & 1) * 4;
    int bkr = tid >> 4, bc4 = (tid & 15) * 4;
    for (int k0 = 0; k0 < K; k0 += 8) {
        int row = bm + arow;
        float4 av = make_float4(0.f, 0.f, 0.f, 0.f);
        if (row < M) av = *(const float4*)&Ax[(size_t)row * K + k0 + ac4];
        As[ac4 + 0][arow] = av.x;
        As[ac4 + 1][arow] = av.y;
        As[ac4 + 2][arow] = av.z;
        As[ac4 + 3][arow] = av.w;
        float4 bv = *(const float4*)&Bx[(size_t)(k0 + bkr) * N + bn + bc4];
        *(float4*)&Bs[bkr][bc4] = bv;
        __syncthreads();
#pragma unroll
        for (int k = 0; k < 8; k++) {
            float4 a0 = *(const float4*)&As[k][ty * 8];
            float4 a1 = *(const float4*)&As[k][ty * 8 + 4];
            float4 b0 = *(const float4*)&Bs[k][tx * 4];
            float aval[8] = {a0.x, a0.y, a0.z, a0.w, a1.x, a1.y, a1.z, a1.w};
            float bval[4] = {b0.x, b0.y, b0.z, b0.w};
#pragma unroll
            for (int i2 = 0; i2 < 8; i2++)
#pragma unroll
                for (int j2 = 0; j2 < 4; j2++) acc[i2][j2] += aval[i2] * bval[j2];
        }
        __syncthreads();
    }
#pragma unroll
    for (int i2 = 0; i2 < 8; i2++) {
        int row = bm + ty * 8 + i2;
        if (row >= M) continue;
#pragma unroll
        for (int j2 = 0; j2 < 4; j2++) {
            int col = bn + tx * 4 + j2;
            C[(size_t)row * N + col] = fmaxf(acc[i2][j2] + bias[col], 0.f);
        }
    }
}

// -------- rcnn cls/box heads --------
__global__ void k_rheads(const float* __restrict__ wrc, const float* __restrict__ brc,
                         const float* __restrict__ wrb, const float* __restrict__ brb,
                         float* __restrict__ o_log, float* __restrict__ o_del) {
    int p = blockIdx.x;
    int w = threadIdx.x >> 5, lane = threadIdx.x & 31;
    const float* hp = g_h2 + (size_t)p * 512;
    float s = 0.f;
    if (w < 2) {
        for (int k = lane; k < 512; k += 32) s += hp[k] * wrc[k * 2 + w];
    } else {
        int j = w - 2;
        for (int k = lane; k < 512; k += 32) s += hp[k] * wrb[k * 4 + j];
    }
    for (int off = 16; off > 0; off >>= 1) s += __shfl_down_sync(0xffffffffu, s, off);
    if (lane == 0) {
        if (w < 2) {
            float v = s + brc[w];
            o_log[p * 2 + w] = v;
            g_rlogits[p * 2 + w] = v;
        } else {
            int j = w - 2;
            float v = s + brb[j];
            o_del[p * 4 + j] = v;
            g_rdeltas[p * 4 + j] = v;
        }
    }
}

// -------- decode stage 2 --------
__global__ void k_decode2(float* __restrict__ dets) {
    int p = blockIdx.x * blockDim.x + threadIdx.x;
    if (p >= NPROP) return;
    float l0 = g_rlogits[p * 2], l1 = g_rlogits[p * 2 + 1];
    float m = fmaxf(l0, l1);
    float e0 = expf(l0 - m), e1 = expf(l1 - m);
    float sc = e1 / (e0 + e1);
    g_dscores[p] = sc;
    float x1 = g_props[p * 4], y1 = g_props[p * 4 + 1];
    float x2 = g_props[p * 4 + 2], y2 = g_props[p * 4 + 3];
    float w = x2 - x1, h = y2 - y1;
    float cx = x1 + 0.5f * w, cy = y1 + 0.5f * h;
    float d0 = g_rdeltas[p * 4], d1 = g_rdeltas[p * 4 + 1];
    float d2 = g_rdeltas[p * 4 + 2], d3 = g_rdeltas[p * 4 + 3];
    float ncx = cx + d0 * w, ncy = cy + d1 * h;
    float nw = w * expf(d2), nh = h * expf(d3);
    dets[p * 4]     = fminf(fmaxf(ncx - 0.5f * nw, 0.f), 255.f);
    dets[p * 4 + 1] = fminf(fmaxf(ncy - 0.5f * nh, 0.f), 255.f);
    dets[p * 4 + 2] = fminf(fmaxf(ncx + 0.5f * nw, 0.f), 255.f);
    dets[p * 4 + 3] = fminf(fmaxf(ncy + 0.5f * nh, 0.f), 255.f);
    g_s2[p] = g_valid[p] ? sc : -1.0f;
}

// -------- final dets/scores/keep2 --------
__global__ void k_final2(float* __restrict__ o_fdets, float* __restrict__ o_fsc,
                         float* __restrict__ o_keep) {
    int r = blockIdx.x * blockDim.x + threadIdx.x;
    if (r >= NPROP) return;
    int o = g_order2[r];
    int k2 = g_keep2a[r] && g_valid[o];
    float kf = k2 ? 1.f : 0.f;
    float4 d = g_sb2[r];
    o_fdets[r * 4]     = k2 ? d.x : 0.f;
    o_fdets[r * 4 + 1] = k2 ? d.y : 0.f;
    o_fdets[r * 4 + 2] = k2 ? d.z : 0.f;
    o_fdets[r * 4 + 3] = k2 ? d.w : 0.f;
    o_fsc[r] = k2 ? g_dscores[o] : 0.f;
    if (o_keep) o_keep[r] = kf;
    g_keep2f[r] = kf;
}

// -------- final masks --------
__global__ void k_fmask(float* __restrict__ o) {
    int r = blockIdx.x, i = threadIdx.x;
    int oi = g_order2[r];
    float v = g_masks[(size_t)oi * 196 + i];
    float sgm = 1.f / (1.f + expf(-v));
    o[(size_t)r * 196 + i] = sgm * g_keep2f[r];
}

// ---------------- host ----------------
extern "C" void kernel_launch(void* const* d_in, const int* in_sizes, int n_in,
                              void* d_out, int out_size) {
    const float* x      = (const float*)d_in[0];
    const float* w_bb   = (const float*)d_in[1];
    const float* b_bb   = (const float*)d_in[2];
    const float* w_rpn  = (const float*)d_in[3];
    const float* b_rpn  = (const float*)d_in[4];
    const float* w_cls  = (const float*)d_in[5];
    const float* b_cls  = (const float*)d_in[6];
    const float* w_box  = (const float*)d_in[7];
    const float* b_box  = (const float*)d_in[8];
    const float* w_fc1  = (const float*)d_in[9];
    const float* b_fc1  = (const float*)d_in[10];
    const float* w_fc2  = (const float*)d_in[11];
    const float* b_fc2  = (const float*)d_in[12];
    const float* w_rcls = (const float*)d_in[13];
    const float* b_rcls = (const float*)d_in[14];
    const float* w_rbox = (const float*)d_in[15];
    const float* b_rbox = (const float*)d_in[16];
    const float* w_m1   = (const float*)d_in[17];
    const float* b_m1   = (const float*)d_in[18];
    const float* w_m2   = (const float*)d_in[19];
    const float* b_m2   = (const float*)d_in[20];
    float* out = (float*)d_out;

    const size_t O_RPNL = 0, O_RPND = 4608, O_PROP = 13824, O_ANCH = 21824;
    const size_t O_RLOG = 31040, O_RDEL = 35040, O_RMSK = 43040;
    const size_t O_FDET = 435040, O_FMSK = 443040, O_FSC = 835040, O_KEEP = 837040;

    float *p_scores, *p_s2, *p_flat, *p_h1, *p_h2, *p_dets;
    int *p_order, *p_order2, *p_keep1, *p_keep2a;
    unsigned long long *p_mask1, *p_mask2;
    cudaGetSymbolAddress((void**)&p_scores, g_scores);
    cudaGetSymbolAddress((void**)&p_order, g_order);
    cudaGetSymbolAddress((void**)&p_s2, g_s2);
    cudaGetSymbolAddress((void**)&p_order2, g_order2);
    cudaGetSymbolAddress((void**)&p_flat, g_flat);
    cudaGetSymbolAddress((void**)&p_h1, g_h1);
    cudaGetSymbolAddress((void**)&p_h2, g_h2);
    cudaGetSymbolAddress((void**)&p_dets, g_dets);
    cudaGetSymbolAddress((void**)&p_keep1, g_keep1);
    cudaGetSymbolAddress((void**)&p_keep2a, g_keep2a);
    cudaGetSymbolAddress((void**)&p_mask1, g_mask1);
    cudaGetSymbolAddress((void**)&p_mask2, g_mask2);

    cudaFuncSetAttribute(k_roi, cudaFuncAttributeMaxDynamicSharedMemorySize, SMEM_ROI_BYTES);
    cudaFuncSetAttribute(k_roizero, cudaFuncAttributeMaxDynamicSharedMemorySize, SMEM_ROI_BYTES);

    float4* p_sb1; float* p_sa1; float4* p_sb2; float* p_sa2;
    cudaGetSymbolAddress((void**)&p_sb1, g_sb1);
    cudaGetSymbolAddress((void**)&p_sa1, g_sa1);
    cudaGetSymbolAddress((void**)&p_sb2, g_sb2);
    cudaGetSymbolAddress((void**)&p_sa2, g_sa2);

    k_backbone<<<256, 256>>>(x, w_bb, b_bb);
    k_packwt<<<(9 * 64 * 64 + 255) / 256, 256>>>(w_m1);
    k_roizero<<<1, 256, SMEM_ROI_BYTES>>>(b_m1, w_m2, b_m2);
    k_rpnconv<<<256, 256>>>(w_rpn, b_rpn);
    k_heads1<<<18, 128>>>(w_cls, b_cls, w_box, b_box,
                          out + O_RPNL, out + O_RPND, out + O_ANCH);
    k_sort<4096><<<1, 1024>>>(p_scores, NANCH, p_order);
    k_gather1<<<(NANCH + 255) / 256, 256>>>();
    k_ioumask<NANCH, NW1><<<dim3(NW1, NW1), 64>>>(p_sb1, p_sa1, p_mask1, 0.5f);
    k_nmsreduce<NANCH, NW1><<<1, 32>>>(p_mask1, p_keep1);
    k_select1<<<1, 1024>>>(out + O_PROP);
    k_roi<<<NPROP, 256, SMEM_ROI_BYTES>>>(b_m1, w_m2, b_m2, out + O_RMSK);

    dim3 gfc(512 / 64, (NPROP + 63) / 64);
    k_gemm64<<<gfc, 128>>>(p_flat, w_fc1, b_fc1, p_h1, NPROP, 512, 3136);
    k_gemm64<<<gfc, 128>>>(p_h1, w_fc2, b_fc2, p_h2, NPROP, 512, 512);
    k_rheads<<<NPROP, 192>>>(w_rcls, b_rcls, w_rbox, b_rbox,
                             out + O_RLOG, out + O_RDEL);
    k_decode2<<<(NPROP + 255) / 256, 256>>>(p_dets);
    k_sort<2048><<<1, 1024>>>(p_s2, NPROP, p_order2);
    k_gather2<<<(NPROP + 255) / 256, 256>>>(p_dets);
    k_ioumask<NPROP, NW2><<<dim3(NW2, NW2), 64>>>(p_sb2, p_sa2, p_mask2, 0.3f);
    k_nmsreduce<NPROP, NW2><<<1, 32>>>(p_mask2, p_keep2a);
    float* o_keep = (out_size >= (int)(O_KEEP + NPROP)) ? (out + O_KEEP) : nullptr;
    k_final2<<<(NPROP + 255) / 256, 256>>>(out + O_FDET, out + O_FSC, o_keep);
    k_fmask<<<NPROP, 196>>>(out + O_FMSK);
}

// round 7
// speedup vs baseline: 2.9918x; 1.0644x over previous
#include <cuda_runtime.h>
#include <math.h>

#define NANCH 2304
#define NPROP 2000
#define NW1 36
#define NW2 32

// ---------------- scratch (device globals; no allocation) ----------------
__device__ float g_feat[64 * 256];
__device__ float g_featT[256 * 64];              // [y][x][c] for vectorized crop
__device__ float g_featP[64 * 18 * 18];          // halo-padded (borders stay 0)
__device__ float g_hrpn[64 * 256];
__device__ float g_scores[NANCH];
__device__ float g_boxes[NANCH * 4];
__device__ int   g_order[NANCH];
__device__ float g_props[NPROP * 4];
__device__ int   g_valid[NPROP];
__device__ float g_flat[NPROP * 3136];
__device__ float g_h1[NPROP * 512];
__device__ float g_h2[NPROP * 512];
__device__ float g_rlogits[NPROP * 2];
__device__ float g_rdeltas[NPROP * 4];
__device__ float g_dscores[NPROP];
__device__ float g_s2[NPROP];
__device__ int   g_order2[NPROP];
__device__ float g_masks[NPROP * 196];
__device__ float g_dets[NPROP * 4];
__device__ float g_wt[9 * 64 * 64];              // mask-conv weights [slab][ic][oc], tf32
__device__ float g_flatz[3136];                  // canonical zero-box ROI results
__device__ float g_maskz[196];
// NMS scratch
__device__ float4 g_sb1[NANCH];
__device__ float  g_sa1[NANCH];
__device__ unsigned long long g_mask1[(size_t)NANCH * NW1];
__device__ int    g_keep1[NANCH];
__device__ float4 g_sb2[NPROP];
__device__ float  g_sa2[NPROP];
__device__ unsigned long long g_mask2[(size_t)NPROP * NW2];
__device__ int    g_keep2a[NPROP];

__device__ __forceinline__ float to_tf32(float x) {
    unsigned u;
    asm("cvt.rna.tf32.f32 %0, %1;" : "=r"(u) : "f"(x));
    return __uint_as_float(u);
}
__device__ __forceinline__ void mma_tf32(float* c, const unsigned* a,
                                         unsigned b0, unsigned b1) {
    asm volatile(
        "mma.sync.aligned.m16n8k8.row.col.f32.tf32.tf32.f32 "
        "{%0,%1,%2,%3},{%4,%5,%6,%7},{%8,%9},{%0,%1,%2,%3};"
        : "+f"(c[0]), "+f"(c[1]), "+f"(c[2]), "+f"(c[3])
        : "r"(a[0]), "r"(a[1]), "r"(a[2]), "r"(a[3]), "r"(b0), "r"(b1));
}

// ---------------- backbone: conv 3->64, k16 s16 VALID, relu (split-K x4) ------
__global__ void k_backbone(const float* __restrict__ x, const float* __restrict__ w,
                           const float* __restrict__ b) {
    __shared__ float patch[768];
    __shared__ float part[256];
    int pos = blockIdx.x;
    int h = pos >> 4, wq = pos & 15;
    int tid = threadIdx.x;     // 256
    for (int k = tid; k < 768; k += 256) {
        int ic = k >> 8, r = k & 255, iy = r >> 4, ix = r & 15;
        patch[k] = x[ic * 65536 + (h * 16 + iy) * 256 + (wq * 16 + ix)];
    }
    __syncthreads();
    int oc = tid & 63, ch = tid >> 6;
    const float* wp = w + oc * 768 + ch * 192;
    const float* pp = patch + ch * 192;
    float a0 = 0.f, a1 = 0.f;
#pragma unroll 8
    for (int k = 0; k < 192; k += 2) { a0 += pp[k] * wp[k]; a1 += pp[k + 1] * wp[k + 1]; }
    part[tid] = a0 + a1;
    __syncthreads();
    if (tid < 64) {
        float s = b[tid] + part[tid] + part[tid + 64] + part[tid + 128] + part[tid + 192];
        float v = fmaxf(s, 0.f);
        g_feat[tid * 256 + pos] = v;
        g_featT[pos * 64 + tid] = v;
        g_featP[tid * 324 + (h + 1) * 18 + (wq + 1)] = v;
    }
}

// ---------------- rpn conv 3x3 SAME, relu (halo, unconditional, split-K x4) ----
__global__ void k_rpnconv(const float* __restrict__ w, const float* __restrict__ b) {
    __shared__ float part[256];
    int pos = blockIdx.x;
    int y = pos >> 4, xq = pos & 15;
    int tid = threadIdx.x;     // 256
    int oc = tid & 63, ch = tid >> 6;
    float acc0 = 0.f, acc1 = 0.f;
    for (int icl = 0; icl < 16; icl += 2) {
        int ic = ch * 16 + icl;
        const float* f0 = g_featP + ic * 324 + y * 18 + xq;
        const float* f1 = f0 + 324;
        const float* wb0 = w + oc * 576 + ic * 9;
        const float* wb1 = wb0 + 9;
#pragma unroll
        for (int ky = 0; ky < 3; ky++) {
#pragma unroll
            for (int kx = 0; kx < 3; kx++) {
                acc0 += f0[ky * 18 + kx] * wb0[ky * 3 + kx];
                acc1 += f1[ky * 18 + kx] * wb1[ky * 3 + kx];
            }
        }
    }
    part[tid] = acc0 + acc1;
    __syncthreads();
    if (tid < 64) {
        float s = b[tid] + part[tid] + part[tid + 64] + part[tid + 128] + part[tid + 192];
        g_hrpn[tid * 256 + pos] = fmaxf(s, 0.f);
    }
}

// -------- rpn heads (1x1), anchors, softmax score, decode, clip --------
__global__ void k_heads1(const float* __restrict__ wc, const float* __restrict__ bc,
                         const float* __restrict__ wb, const float* __restrict__ bb,
                         float* __restrict__ o_logits, float* __restrict__ o_deltas,
                         float* __restrict__ o_anch) {
    int i = blockIdx.x * blockDim.x + threadIdx.x;
    if (i >= NANCH) return;
    int cell = i / 9, a = i % 9;
    float l0 = bc[a * 2], l1 = bc[a * 2 + 1];
    float d0 = bb[a * 4], d1 = bb[a * 4 + 1], d2 = bb[a * 4 + 2], d3 = bb[a * 4 + 3];
    for (int ic = 0; ic < 64; ic++) {
        float f = g_hrpn[ic * 256 + cell];
        l0 += f * wc[(a * 2) * 64 + ic];
        l1 += f * wc[(a * 2 + 1) * 64 + ic];
        d0 += f * wb[(a * 4) * 64 + ic];
        d1 += f * wb[(a * 4 + 1) * 64 + ic];
        d2 += f * wb[(a * 4 + 2) * 64 + ic];
        d3 += f * wb[(a * 4 + 3) * 64 + ic];
    }
    o_logits[i * 2] = l0; o_logits[i * 2 + 1] = l1;
    o_deltas[i * 4] = d0; o_deltas[i * 4 + 1] = d1;
    o_deltas[i * 4 + 2] = d2; o_deltas[i * 4 + 3] = d3;
    float m = fmaxf(l0, l1);
    float e0 = expf(l0 - m), e1 = expf(l1 - m);
    g_scores[i] = e1 / (e0 + e1);

    const float S[3] = {32.f, 64.f, 128.f};
    const float R[3] = {0.5f, 1.f, 2.f};
    int h = cell >> 4, wq = cell & 15;
    float s = S[a / 3], r = R[a % 3];
    float ws = s * sqrtf(r), hs = s / sqrtf(r);
    float cx = (wq + 0.5f) * 16.f, cy = (h + 0.5f) * 16.f;
    float ax1 = cx - ws * 0.5f, ay1 = cy - hs * 0.5f;
    float ax2 = cx + ws * 0.5f, ay2 = cy + hs * 0.5f;
    o_anch[i * 4] = ax1; o_anch[i * 4 + 1] = ay1;
    o_anch[i * 4 + 2] = ax2; o_anch[i * 4 + 3] = ay2;

    float aw = ax2 - ax1, ah = ay2 - ay1;
    float acx = ax1 + 0.5f * aw, acy = ay1 + 0.5f * ah;
    float ncx = acx + d0 * aw, ncy = acy + d1 * ah;
    float nw = aw * expf(d2), nh = ah * expf(d3);
    g_boxes[i * 4]     = fminf(fmaxf(ncx - 0.5f * nw, 0.f), 255.f);
    g_boxes[i * 4 + 1] = fminf(fmaxf(ncy - 0.5f * nh, 0.f), 255.f);
    g_boxes[i * 4 + 2] = fminf(fmaxf(ncx + 0.5f * nw, 0.f), 255.f);
    g_boxes[i * 4 + 3] = fminf(fmaxf(ncy + 0.5f * nh, 0.f), 255.f);
}

// -------- pack mask-conv weights: [oc][ic][9] -> [slab][ic][oc], tf32-rounded ----
__global__ void k_packwt(const float* __restrict__ w) {
    int i = blockIdx.x * blockDim.x + threadIdx.x;
    if (i >= 9 * 64 * 64) return;
    int slab = i >> 12, r = i & 4095, ic = r >> 6, oc = r & 63;
    g_wt[i] = to_tf32(w[oc * 576 + ic * 9 + slab]);
}

// -------- single-block bitonic sort: desc value, stable idx; fused box gather ----
template <int SIZE>
__global__ void k_sort(const float* __restrict__ sc, int n, int* __restrict__ ord,
                       const float* __restrict__ boxes, float4* __restrict__ sb,
                       float* __restrict__ sa) {
    __shared__ unsigned long long k[SIZE];
    int tid = threadIdx.x;
    for (int i = tid; i < SIZE; i += 1024) {
        if (i < n) {
            unsigned u = __float_as_uint(sc[i]);
            unsigned o = (u & 0x80000000u) ? ~u : (u | 0x80000000u);
            k[i] = ((unsigned long long)(~o) << 32) | (unsigned)i;
        } else k[i] = 0xFFFFFFFFFFFFFFFFULL;
    }
    __syncthreads();
    for (int kk = 2; kk <= SIZE; kk <<= 1) {
        for (int j = kk >> 1; j > 0; j >>= 1) {
            for (int i = tid; i < SIZE; i += 1024) {
                int ixj = i ^ j;
                if (ixj > i) {
                    bool up = ((i & kk) == 0);
                    unsigned long long a = k[i], b = k[ixj];
                    if ((a > b) == up) { k[i] = b; k[ixj] = a; }
                }
            }
            __syncthreads();
        }
    }
    for (int i = tid; i < n; i += 1024) {
        int idx = (int)(k[i] & 0xFFFFFFFFu);
        ord[i] = idx;
        float4 b = *(const float4*)&boxes[idx * 4];
        sb[i] = b;
        sa[i] = fmaxf(b.z - b.x, 0.f) * fmaxf(b.w - b.y, 0.f);
    }
}

// -------- IoU bitmask matrix --------
template <int N, int NW>
__global__ void k_ioumask(const float4* __restrict__ sb, const float* __restrict__ sa,
                          unsigned long long* __restrict__ mask, float thr) {
    __shared__ float4 cbx[64];
    __shared__ float car[64];
    int rb = blockIdx.y, cb = blockIdx.x;
    int t = threadIdx.x;
    int j0 = cb * 64;
    if (j0 + t < N) { cbx[t] = sb[j0 + t]; car[t] = sa[j0 + t]; }
    __syncthreads();
    int i = rb * 64 + t;
    if (i >= N) return;
    float4 bi = sb[i];
    float ai = sa[i];
    unsigned long long m = 0;
    int jmax = min(64, N - j0);
    for (int jj = 0; jj < jmax; jj++) {
        int j = j0 + jj;
        if (j <= i) continue;
        float xx1 = fmaxf(bi.x, cbx[jj].x), yy1 = fmaxf(bi.y, cbx[jj].y);
        float xx2 = fminf(bi.z, cbx[jj].z), yy2 = fminf(bi.w, cbx[jj].w);
        float inter = fmaxf(xx2 - xx1, 0.f) * fmaxf(yy2 - yy1, 0.f);
        float iou = inter / (ai + car[jj] - inter + 1e-8f);
        if (iou > thr) m |= 1ULL << jj;
    }
    mask[(size_t)i * NW + cb] = m;
}

// -------- chunked exact greedy reduce over bitmasks; one warp --------
template <int N, int NW>
__global__ void k_nmsreduce(const unsigned long long* __restrict__ mask,
                            int* __restrict__ keep) {
    __shared__ unsigned long long s_blk[64];
    int lane = threadIdx.x;                      // 32
    unsigned long long remv0 = 0ULL, remv1 = 0ULL;
    const int NC = (N + 63) / 64;
    for (int cb = 0; cb < NC; cb++) {
        int j0 = cb * 64;
        int jmax = min(64, N - j0);
        for (int t = lane; t < jmax; t += 32)
            s_blk[t] = mask[(size_t)(j0 + t) * NW + cb];
        __syncwarp();
        int owner = cb & 31;
        unsigned long long r = __shfl_sync(0xffffffffu, (cb < 32) ? remv0 : remv1, owner);
        unsigned long long kept = 0ULL;
        if (lane == 0) {
#pragma unroll 4
            for (int jj = 0; jj < jmax; jj++) {
                if (!((r >> jj) & 1ULL)) {
                    kept |= 1ULL << jj;
                    r |= s_blk[jj];
                }
            }
        }
        kept = __shfl_sync(0xffffffffu, kept, 0);
        r = __shfl_sync(0xffffffffu, r, 0);
        if (lane == owner) { if (cb < 32) remv0 = r; else remv1 = r; }
        for (int t = lane; t < jmax; t += 32)
            keep[j0 + t] = (int)((kept >> t) & 1ULL);
        int w1 = lane, w2 = lane + 32;
        bool u1 = (w1 > cb) && (w1 < NW), u2 = (w2 > cb) && (w2 < NW);
        for (int jj = 0; jj < jmax; jj++) {
            if ((kept >> jj) & 1ULL) {
                const unsigned long long* row = mask + (size_t)(j0 + jj) * NW;
                if (u1) remv0 |= row[w1];
                if (u2) remv1 |= row[w2];
            }
        }
        __syncwarp();
    }
}

// -------- stable kept-first selection of NPROP proposals --------
__global__ void k_select1(float* __restrict__ o_props) {
    __shared__ int s_src[NPROP];
    int tid = threadIdx.x;
    if (tid < 32) {
        const int CH = NANCH / 32;
        int beg = tid * CH, end = beg + CH;
        int cnt = 0;
        for (int i = beg; i < end; i++) cnt += g_keep1[i];
        int xsc = cnt;
        for (int off = 1; off < 32; off <<= 1) {
            int v = __shfl_up_sync(0xffffffffu, xsc, off);
            if (tid >= off) xsc += v;
        }
        int excl = xsc - cnt;
        int total = __shfl_sync(0xffffffffu, xsc, 31);
        int kpos = excl;
        int npos = total + (beg - excl);
        for (int i = beg; i < end; i++) {
            int pos = g_keep1[i] ? kpos++ : npos++;
            if (pos < NPROP) s_src[pos] = i;
        }
    }
    __syncthreads();
    for (int p = tid; p < NPROP; p += 1024) {
        int i = s_src[p];
        int v = g_keep1[i];
        float4 bb = g_sb1[i];
        float px1 = v ? bb.x : 0.f, py1 = v ? bb.y : 0.f;
        float px2 = v ? bb.z : 0.f, py2 = v ? bb.w : 0.f;
        g_props[p * 4] = px1; g_props[p * 4 + 1] = py1;
        g_props[p * 4 + 2] = px2; g_props[p * 4 + 3] = py2;
        o_props[p * 4] = px1; o_props[p * 4 + 1] = py1;
        o_props[p * 4 + 2] = px2; o_props[p * 4 + 3] = py2;
        g_valid[p] = v;
    }
}

// ===================== ROI body: tf32 MMA implicit GEMM =====================
#define CROPH_F (16 * 16 * 68)
#define WSLAB_F (64 * 68)
#define SMEM_ROI_BYTES ((CROPH_F + WSLAB_F + 64 + 64 + 96) * 4)

__device__ __forceinline__ void roi_body(
    int tid, float bx1, float by1, float bx2, float by2,
    const float* __restrict__ bm1, const float* __restrict__ wm2,
    const float* __restrict__ bm2,
    float* __restrict__ flat_out, float* __restrict__ maskA, float* __restrict__ maskB,
    float* smem)
{
    float* s_crop = smem;                    // [yH][xH][68]
    float* s_w = s_crop + CROPH_F;           // [ic][68]
    float* s_w2 = s_w + WSLAB_F;
    float* s_b1 = s_w2 + 64;
    float* s_wy = s_b1 + 64;
    float* s_wx = s_wy + 14;
    int* s_y0 = (int*)(s_wx + 14);
    int* s_y1 = s_y0 + 14;
    int* s_x0 = s_y1 + 14;
    int* s_x1 = s_x0 + 14;

    int lane = tid & 31, wrp = tid >> 5;     // 8 warps

    if (tid < 28) {
        int t = tid % 14;
        float tt = (float)t / 13.0f;
        if (tid < 14) {
            float y1n = by1 / 255.0f, y2n = by2 / 255.0f;
            float fy = (y1n + (y2n - y1n) * tt) * 15.0f;
            float y0f = fminf(fmaxf(floorf(fy), 0.f), 15.f);
            int y0 = (int)y0f;
            s_y0[t] = y0; s_y1[t] = min(y0 + 1, 15); s_wy[t] = fy - y0f;
        } else {
            float x1n = bx1 / 255.0f, x2n = bx2 / 255.0f;
            float fx = (x1n + (x2n - x1n) * tt) * 15.0f;
            float x0f = fminf(fmaxf(floorf(fx), 0.f), 15.f);
            int x0 = (int)x0f;
            s_x0[t] = x0; s_x1[t] = min(x0 + 1, 15); s_wx[t] = fx - x0f;
        }
    }
    if (tid >= 32 && tid < 96) {
        int c = tid - 32;
        s_w2[c] = wm2[c];
        s_b1[c] = bm1[c];
    }
    for (int idx = tid; idx < CROPH_F / 4; idx += 256)
        ((float4*)s_crop)[idx] = make_float4(0.f, 0.f, 0.f, 0.f);
    __syncthreads();

    // bilinear crop (fp32), 4 channels per thread-iter via featT [y][x][c]
    const float4* ft4 = (const float4*)g_featT;
    for (int idx = tid; idx < 3136; idx += 256) {
        int pos = idx >> 4, c4 = idx & 15;
        int ty = pos / 14, tx = pos - ty * 14;
        int y0 = s_y0[ty], y1 = s_y1[ty], x0 = s_x0[tx], x1 = s_x1[tx];
        float wy = s_wy[ty], wx = s_wx[tx];
        float4 f00 = ft4[(y0 * 16 + x0) * 16 + c4];
        float4 f01 = ft4[(y0 * 16 + x1) * 16 + c4];
        float4 f10 = ft4[(y1 * 16 + x0) * 16 + c4];
        float4 f11 = ft4[(y1 * 16 + x1) * 16 + c4];
        float4 v;
        { float top = f00.x * (1.f - wx) + f01.x * wx;
          float bot = f10.x * (1.f - wx) + f11.x * wx;
          v.x = top * (1.f - wy) + bot * wy; }
        { float top = f00.y * (1.f - wx) + f01.y * wx;
          float bot = f10.y * (1.f - wx) + f11.y * wx;
          v.y = top * (1.f - wy) + bot * wy; }
        { float top = f00.z * (1.f - wx) + f01.z * wx;
          float bot = f10.z * (1.f - wx) + f11.z * wx;
          v.z = top * (1.f - wy) + bot * wy; }
        { float top = f00.w * (1.f - wx) + f01.w * wx;
          float bot = f10.w * (1.f - wx) + f11.w * wx;
          v.w = top * (1.f - wy) + bot * wy; }
        *(float4*)&s_crop[((ty + 1) * 16 + (tx + 1)) * 68 + c4 * 4] = v;
    }
    __syncthreads();

    // pool 2x2 -> flat [64*49]
    for (int idx = tid; idx < 784; idx += 256) {
        int pos = idx >> 4, c4 = idx & 15;
        int py = pos / 7, px = pos - py * 7;
        float4 a = *(const float4*)&s_crop[((2 * py + 1) * 16 + 2 * px + 1) * 68 + c4 * 4];
        float4 b = *(const float4*)&s_crop[((2 * py + 1) * 16 + 2 * px + 2) * 68 + c4 * 4];
        float4 c = *(const float4*)&s_crop[((2 * py + 2) * 16 + 2 * px + 1) * 68 + c4 * 4];
        float4 d = *(const float4*)&s_crop[((2 * py + 2) * 16 + 2 * px + 2) * 68 + c4 * 4];
        flat_out[(c4 * 4 + 0) * 49 + pos] = fmaxf(fmaxf(a.x, b.x), fmaxf(c.x, d.x));
        flat_out[(c4 * 4 + 1) * 49 + pos] = fmaxf(fmaxf(a.y, b.y), fmaxf(c.y, d.y));
        flat_out[(c4 * 4 + 2) * 49 + pos] = fmaxf(fmaxf(a.z, b.z), fmaxf(c.z, d.z));
        flat_out[(c4 * 4 + 3) * 49 + pos] = fmaxf(fmaxf(a.w, b.w), fmaxf(c.w, d.w));
    }
    __syncthreads();

    // round crop to tf32 in place (masks path only)
    for (int idx = tid; idx < CROPH_F / 4; idx += 256) {
        float4 v = ((float4*)s_crop)[idx];
        v.x = to_tf32(v.x); v.y = to_tf32(v.y); v.z = to_tf32(v.z); v.w = to_tf32(v.w);
        ((float4*)s_crop)[idx] = v;
    }

    int g = lane >> 2, q = lane & 3;
    int pb[2][2];
#pragma unroll
    for (int mt = 0; mt < 2; mt++)
#pragma unroll
        for (int hh = 0; hh < 2; hh++) {
            int p = wrp * 32 + mt * 16 + g + hh * 8;
            if (p < 196) {
                int y = p / 14, xx = p % 14;
                pb[mt][hh] = (y * 16 + xx) * 68;
            } else pb[mt][hh] = 0;
        }

    float c[2][8][4];
#pragma unroll
    for (int mt = 0; mt < 2; mt++)
#pragma unroll
        for (int nt = 0; nt < 8; nt++)
#pragma unroll
            for (int j = 0; j < 4; j++) c[mt][nt][j] = 0.f;

    for (int slab = 0; slab < 9; slab++) {
        __syncthreads();
        for (int f = tid; f < 4096; f += 256) {
            int ic = f >> 6, oc = f & 63;
            s_w[ic * 68 + oc] = g_wt[slab * 4096 + f];
        }
        __syncthreads();
        int ky = slab / 3, kx = slab % 3;
        int off = (ky * 16 + kx) * 68;
#pragma unroll 2
        for (int icT = 0; icT < 8; icT++) {
            int ab = off + icT * 8 + q;
            unsigned a[2][4];
#pragma unroll
            for (int mt = 0; mt < 2; mt++) {
                a[mt][0] = __float_as_uint(s_crop[pb[mt][0] + ab]);
                a[mt][1] = __float_as_uint(s_crop[pb[mt][1] + ab]);
                a[mt][2] = __float_as_uint(s_crop[pb[mt][0] + ab + 4]);
                a[mt][3] = __float_as_uint(s_crop[pb[mt][1] + ab + 4]);
            }
            int brow = (icT * 8 + q) * 68 + g;
#pragma unroll
            for (int nt = 0; nt < 8; nt++) {
                unsigned b0 = __float_as_uint(s_w[brow + nt * 8]);
                unsigned b1 = __float_as_uint(s_w[brow + nt * 8 + 4 * 68]);
                mma_tf32(c[0][nt], a[0], b0, b1);
                mma_tf32(c[1][nt], a[1], b0, b1);
            }
        }
    }

    float part[2][2] = {{0.f, 0.f}, {0.f, 0.f}};
#pragma unroll
    for (int nt = 0; nt < 8; nt++) {
        int col0 = nt * 8 + q * 2, col1 = col0 + 1;
        float bA = s_b1[col0], bB = s_b1[col1];
        float w20 = s_w2[col0], w21 = s_w2[col1];
#pragma unroll
        for (int mt = 0; mt < 2; mt++) {
            part[mt][0] += fmaxf(c[mt][nt][0] + bA, 0.f) * w20
                         + fmaxf(c[mt][nt][1] + bB, 0.f) * w21;
            part[mt][1] += fmaxf(c[mt][nt][2] + bA, 0.f) * w20
                         + fmaxf(c[mt][nt][3] + bB, 0.f) * w21;
        }
    }
    float b2 = bm2[0];
#pragma unroll
    for (int mt = 0; mt < 2; mt++)
#pragma unroll
        for (int hh = 0; hh < 2; hh++) {
            float v = part[mt][hh];
            v += __shfl_xor_sync(0xffffffffu, v, 1);
            v += __shfl_xor_sync(0xffffffffu, v, 2);
            int p = wrp * 32 + mt * 16 + g + hh * 8;
            if (q == 0 && p < 196) {
                float logit = b2 + v;
                maskA[p] = logit;
                maskB[p] = logit;
            }
        }
}

__global__ void __launch_bounds__(256, 2)
k_roizero(const float* __restrict__ bm1, const float* __restrict__ wm2,
          const float* __restrict__ bm2) {
    extern __shared__ float smem_f[];
    roi_body(threadIdx.x, 0.f, 0.f, 0.f, 0.f, bm1, wm2, bm2,
             g_flatz, g_maskz, g_maskz, smem_f);
}

__global__ void __launch_bounds__(256, 2)
k_roi(const float* __restrict__ bm1, const float* __restrict__ wm2,
      const float* __restrict__ bm2, float* __restrict__ omask) {
    extern __shared__ float smem_f[];
    int p = blockIdx.x, tid = threadIdx.x;
    if (!g_valid[p]) {
        float* fo = g_flat + (size_t)p * 3136;
        for (int idx = tid; idx < 784; idx += 256)
            ((float4*)fo)[idx] = ((const float4*)g_flatz)[idx];
        for (int pos = tid; pos < 196; pos += 256) {
            float v = g_maskz[pos];
            omask[(size_t)p * 196 + pos] = v;
            g_masks[(size_t)p * 196 + pos] = v;
        }
        return;
    }
    roi_body(tid, g_props[p * 4], g_props[p * 4 + 1], g_props[p * 4 + 2], g_props[p * 4 + 3],
             bm1, wm2, bm2,
             g_flat + (size_t)p * 3136, omask + (size_t)p * 196,
             g_masks + (size_t)p * 196, smem_f);
}

// -------- SGEMM 64x64x8, 128 thr, 8x4 micro, double-buffered: C=relu(A·B+bias) ----
__global__ void k_gemm64(const float* __restrict__ Ax, const float* __restrict__ Bx,
                         const float* __restrict__ bias, float* __restrict__ C,
                         int M, int N, int K) {
    __shared__ float As[2][8][72];
    __shared__ float Bs[2][8][64];
    int tid = threadIdx.x;              // 128
    int tx = tid & 15, ty = tid >> 4;   // ty 0..7
    int bm = blockIdx.y * 64, bn = blockIdx.x * 64;
    float acc[8][4];
#pragma unroll
    for (int i = 0; i < 8; i++)
#pragma unroll
        for (int j = 0; j < 4; j++) acc[i][j] = 0.f;

    int arow = tid >> 1, ac4 = (tid & 1) * 4;
    int bkr = tid >> 4, bc4 = (tid & 15) * 4;
    int row = bm + arow;
    const int nk = K / 8;

    float4 ra, rb;
    ra = make_float4(0.f, 0.f, 0.f, 0.f);
    if (row < M) ra = *(const float4*)&Ax[(size_t)row * K + ac4];
    rb = *(const float4*)&Bx[(size_t)bkr * N + bn + bc4];
    As[0][ac4 + 0][arow] = ra.x; As[0][ac4 + 1][arow] = ra.y;
    As[0][ac4 + 2][arow] = ra.z; As[0][ac4 + 3][arow] = ra.w;
    *(float4*)&Bs[0][bkr][bc4] = rb;
    __syncthreads();
    int cur = 0;
    for (int t = 1; t < nk; t++) {
        int k0 = t * 8;
        ra = make_float4(0.f, 0.f, 0.f, 0.f);
        if (row < M) ra = *(const float4*)&Ax[(size_t)row * K + k0 + ac4];
        rb = *(const float4*)&Bx[(size_t)(k0 + bkr) * N + bn + bc4];
#pragma unroll
        for (int k = 0; k < 8; k++) {
            float4 a0 = *(const float4*)&As[cur][k][ty * 8];
            float4 a1 = *(const float4*)&As[cur][k][ty * 8 + 4];
            float4 b0 = *(const float4*)&Bs[cur][k][tx * 4];
            float aval[8] = {a0.x, a0.y, a0.z, a0.w, a1.x, a1.y, a1.z, a1.w};
            float bval[4] = {b0.x, b0.y, b0.z, b0.w};
#pragma unroll
            for (int i2 = 0; i2 < 8; i2++)
#pragma unroll
                for (int j2 = 0; j2 < 4; j2++) acc[i2][j2] += aval[i2] * bval[j2];
        }
        int nxt = cur ^ 1;
        As[nxt][ac4 + 0][arow] = ra.x; As[nxt][ac4 + 1][arow] = ra.y;
        As[nxt][ac4 + 2][arow] = ra.z; As[nxt][ac4 + 3][arow] = ra.w;
        *(float4*)&Bs[nxt][bkr][bc4] = rb;
        __syncthreads();
        cur = nxt;
    }
#pragma unroll
    for (int k = 0; k < 8; k++) {
        float4 a0 = *(const float4*)&As[cur][k][ty * 8];
        float4 a1 = *(const float4*)&As[cur][k][ty * 8 + 4];
        float4 b0 = *(const float4*)&Bs[cur][k][tx * 4];
        float aval[8] = {a0.x, a0.y, a0.z, a0.w, a1.x, a1.y, a1.z, a1.w};
        float bval[4] = {b0.x, b0.y, b0.z, b0.w};
#pragma unroll
        for (int i2 = 0; i2 < 8; i2++)
#pragma unroll
            for (int j2 = 0; j2 < 4; j2++) acc[i2][j2] += aval[i2] * bval[j2];
    }
#pragma unroll
    for (int i2 = 0; i2 < 8; i2++) {
        int r2 = bm + ty * 8 + i2;
        if (r2 >= M) continue;
#pragma unroll
        for (int j2 = 0; j2 < 4; j2++) {
            int col = bn + tx * 4 + j2;
            C[(size_t)r2 * N + col] = fmaxf(acc[i2][j2] + bias[col], 0.f);
        }
    }
}

// -------- rcnn cls/box heads + fused stage-2 decode --------
__global__ void k_rheads(const float* __restrict__ wrc, const float* __restrict__ brc,
                         const float* __restrict__ wrb, const float* __restrict__ brb,
                         float* __restrict__ o_log, float* __restrict__ o_del,
                         float* __restrict__ dets) {
    __shared__ float s6[6];
    int p = blockIdx.x;
    int w = threadIdx.x >> 5, lane = threadIdx.x & 31;
    const float* hp = g_h2 + (size_t)p * 512;
    float s = 0.f;
    if (w < 2) {
        for (int k = lane; k < 512; k += 32) s += hp[k] * wrc[k * 2 + w];
    } else {
        int j = w - 2;
        for (int k = lane; k < 512; k += 32) s += hp[k] * wrb[k * 4 + j];
    }
    for (int off = 16; off > 0; off >>= 1) s += __shfl_down_sync(0xffffffffu, s, off);
    if (lane == 0) {
        if (w < 2) {
            float v = s + brc[w];
            o_log[p * 2 + w] = v;
            g_rlogits[p * 2 + w] = v;
            s6[w] = v;
        } else {
            int j = w - 2;
            float v = s + brb[j];
            o_del[p * 4 + j] = v;
            g_rdeltas[p * 4 + j] = v;
            s6[w] = v;
        }
    }
    __syncthreads();
    if (threadIdx.x == 0) {
        float l0 = s6[0], l1 = s6[1];
        float m = fmaxf(l0, l1);
        float e0 = expf(l0 - m), e1 = expf(l1 - m);
        float sc = e1 / (e0 + e1);
        g_dscores[p] = sc;
        float x1 = g_props[p * 4], y1 = g_props[p * 4 + 1];
        float x2 = g_props[p * 4 + 2], y2 = g_props[p * 4 + 3];
        float wd = x2 - x1, h = y2 - y1;
        float cx = x1 + 0.5f * wd, cy = y1 + 0.5f * h;
        float d0 = s6[2], d1 = s6[3], d2 = s6[4], d3 = s6[5];
        float ncx = cx + d0 * wd, ncy = cy + d1 * h;
        float nw = wd * expf(d2), nh = h * expf(d3);
        dets[p * 4]     = fminf(fmaxf(ncx - 0.5f * nw, 0.f), 255.f);
        dets[p * 4 + 1] = fminf(fmaxf(ncy - 0.5f * nh, 0.f), 255.f);
        dets[p * 4 + 2] = fminf(fmaxf(ncx + 0.5f * nw, 0.f), 255.f);
        dets[p * 4 + 3] = fminf(fmaxf(ncy + 0.5f * nh, 0.f), 255.f);
        g_s2[p] = g_valid[p] ? sc : -1.0f;
    }
}

// -------- final dets/scores/keep2 + masks (fused) --------
__global__ void k_final(float* __restrict__ o_fdets, float* __restrict__ o_fsc,
                        float* __restrict__ o_keep, float* __restrict__ o_fmsk) {
    __shared__ float s_kf;
    __shared__ int s_oi;
    int r = blockIdx.x, i = threadIdx.x;    // 196 threads
    if (i == 0) {
        int o = g_order2[r];
        int k2 = g_keep2a[r] && g_valid[o];
        float kf = k2 ? 1.f : 0.f;
        float4 d = g_sb2[r];
        o_fdets[r * 4]     = k2 ? d.x : 0.f;
        o_fdets[r * 4 + 1] = k2 ? d.y : 0.f;
        o_fdets[r * 4 + 2] = k2 ? d.z : 0.f;
        o_fdets[r * 4 + 3] = k2 ? d.w : 0.f;
        o_fsc[r] = k2 ? g_dscores[o] : 0.f;
        if (o_keep) o_keep[r] = kf;
        s_kf = kf;
        s_oi = o;
    }
    __syncthreads();
    float v = g_masks[(size_t)s_oi * 196 + i];
    float sgm = 1.f / (1.f + expf(-v));
    o_fmsk[(size_t)r * 196 + i] = sgm * s_kf;
}

// ---------------- host ----------------
extern "C" void kernel_launch(void* const* d_in, const int* in_sizes, int n_in,
                              void* d_out, int out_size) {
    const float* x      = (const float*)d_in[0];
    const float* w_bb   = (const float*)d_in[1];
    const float* b_bb   = (const float*)d_in[2];
    const float* w_rpn  = (const float*)d_in[3];
    const float* b_rpn  = (const float*)d_in[4];
    const float* w_cls  = (const float*)d_in[5];
    const float* b_cls  = (const float*)d_in[6];
    const float* w_box  = (const float*)d_in[7];
    const float* b_box  = (const float*)d_in[8];
    const float* w_fc1  = (const float*)d_in[9];
    const float* b_fc1  = (const float*)d_in[10];
    const float* w_fc2  = (const float*)d_in[11];
    const float* b_fc2  = (const float*)d_in[12];
    const float* w_rcls = (const float*)d_in[13];
    const float* b_rcls = (const float*)d_in[14];
    const float* w_rbox = (const float*)d_in[15];
    const float* b_rbox = (const float*)d_in[16];
    const float* w_m1   = (const float*)d_in[17];
    const float* b_m1   = (const float*)d_in[18];
    const float* w_m2   = (const float*)d_in[19];
    const float* b_m2   = (const float*)d_in[20];
    float* out = (float*)d_out;

    const size_t O_RPNL = 0, O_RPND = 4608, O_PROP = 13824, O_ANCH = 21824;
    const size_t O_RLOG = 31040, O_RDEL = 35040, O_RMSK = 43040;
    const size_t O_FDET = 435040, O_FMSK = 443040, O_FSC = 835040, O_KEEP = 837040;

    float *p_scores, *p_s2, *p_flat, *p_h1, *p_h2, *p_dets, *p_boxes;
    int *p_order, *p_order2, *p_keep1, *p_keep2a;
    unsigned long long *p_mask1, *p_mask2;
    cudaGetSymbolAddress((void**)&p_scores, g_scores);
    cudaGetSymbolAddress((void**)&p_order, g_order);
    cudaGetSymbolAddress((void**)&p_s2, g_s2);
    cudaGetSymbolAddress((void**)&p_order2, g_order2);
    cudaGetSymbolAddress((void**)&p_flat, g_flat);
    cudaGetSymbolAddress((void**)&p_h1, g_h1);
    cudaGetSymbolAddress((void**)&p_h2, g_h2);
    cudaGetSymbolAddress((void**)&p_dets, g_dets);
    cudaGetSymbolAddress((void**)&p_boxes, g_boxes);
    cudaGetSymbolAddress((void**)&p_keep1, g_keep1);
    cudaGetSymbolAddress((void**)&p_keep2a, g_keep2a);
    cudaGetSymbolAddress((void**)&p_mask1, g_mask1);
    cudaGetSymbolAddress((void**)&p_mask2, g_mask2);

    cudaFuncSetAttribute(k_roi, cudaFuncAttributeMaxDynamicSharedMemorySize, SMEM_ROI_BYTES);
    cudaFuncSetAttribute(k_roizero, cudaFuncAttributeMaxDynamicSharedMemorySize, SMEM_ROI_BYTES);

    float4* p_sb1; float* p_sa1; float4* p_sb2; float* p_sa2;
    cudaGetSymbolAddress((void**)&p_sb1, g_sb1);
    cudaGetSymbolAddress((void**)&p_sa1, g_sa1);
    cudaGetSymbolAddress((void**)&p_sb2, g_sb2);
    cudaGetSymbolAddress((void**)&p_sa2, g_sa2);

    k_backbone<<<256, 256>>>(x, w_bb, b_bb);
    k_packwt<<<(9 * 64 * 64 + 255) / 256, 256>>>(w_m1);
    k_roizero<<<1, 256, SMEM_ROI_BYTES>>>(b_m1, w_m2, b_m2);
    k_rpnconv<<<256, 256>>>(w_rpn, b_rpn);
    k_heads1<<<18, 128>>>(w_cls, b_cls, w_box, b_box,
                          out + O_RPNL, out + O_RPND, out + O_ANCH);
    k_sort<4096><<<1, 1024>>>(p_scores, NANCH, p_order, p_boxes, p_sb1, p_sa1);
    k_ioumask<NANCH, NW1><<<dim3(NW1, NW1), 64>>>(p_sb1, p_sa1, p_mask1, 0.5f);
    k_nmsreduce<NANCH, NW1><<<1, 32>>>(p_mask1, p_keep1);
    k_select1<<<1, 1024>>>(out + O_PROP);
    k_roi<<<NPROP, 256, SMEM_ROI_BYTES>>>(b_m1, w_m2, b_m2, out + O_RMSK);

    dim3 gfc(512 / 64, (NPROP + 63) / 64);
    k_gemm64<<<gfc, 128>>>(p_flat, w_fc1, b_fc1, p_h1, NPROP, 512, 3136);
    k_gemm64<<<gfc, 128>>>(p_h1, w_fc2, b_fc2, p_h2, NPROP, 512, 512);
    k_rheads<<<NPROP, 192>>>(w_rcls, b_rcls, w_rbox, b_rbox,
                             out + O_RLOG, out + O_RDEL, p_dets);
    k_sort<2048><<<1, 1024>>>(p_s2, NPROP, p_order2, p_dets, p_sb2, p_sa2);
    k_ioumask<NPROP, NW2><<<dim3(NW2, NW2), 64>>>(p_sb2, p_sa2, p_mask2, 0.3f);
    k_nmsreduce<NPROP, NW2><<<1, 32>>>(p_mask2, p_keep2a);
    float* o_keep = (out_size >= (int)(O_KEEP + NPROP)) ? (out + O_KEEP) : nullptr;
    k_final<<<NPROP, 196>>>(out + O_FDET, out + O_FSC, o_keep, out + O_FMSK);
}

// round 8
// speedup vs baseline: 3.1295x; 1.0460x over previous
#include <cuda_runtime.h>
#include <cuda_fp16.h>
#include <math.h>

#define NANCH 2304
#define NPROP 2000
#define NW1 36
#define NW2 32

// ---------------- scratch (device globals; no allocation) ----------------
__device__ float g_feat[64 * 256];
__device__ float g_featT[256 * 64];              // [y][x][c] for vectorized crop
__device__ float g_featP[64 * 18 * 18];          // halo-padded (borders stay 0)
__device__ float g_hrpn[64 * 256];
__device__ float g_scores[NANCH];
__device__ float g_boxes[NANCH * 4];
__device__ int   g_order[NANCH];
__device__ float g_props[NPROP * 4];
__device__ int   g_valid[NPROP];
__device__ float g_flat[NPROP * 3136];
__device__ float g_h1[NPROP * 512];
__device__ float g_h2[NPROP * 512];
__device__ float g_rlogits[NPROP * 2];
__device__ float g_rdeltas[NPROP * 4];
__device__ float g_dscores[NPROP];
__device__ float g_s2[NPROP];
__device__ int   g_order2[NPROP];
__device__ float g_masks[NPROP * 196];
__device__ float g_dets[NPROP * 4];
__device__ unsigned short g_wh[9 * 64 * 64];     // mask-conv weights [slab][oc][ic], fp16
__device__ float g_flatz[3136];                  // canonical zero-box ROI results
__device__ float g_maskz[196];
// NMS scratch
__device__ float4 g_sb1[NANCH];
__device__ float  g_sa1[NANCH];
__device__ unsigned long long g_mask1[(size_t)NANCH * NW1];
__device__ int    g_keep1[NANCH];
__device__ float4 g_sb2[NPROP];
__device__ float  g_sa2[NPROP];
__device__ unsigned long long g_mask2[(size_t)NPROP * NW2];
__device__ int    g_keep2a[NPROP];

__device__ __forceinline__ void mma_f16(float* c, const unsigned* a,
                                        unsigned b0, unsigned b1) {
    asm volatile(
        "mma.sync.aligned.m16n8k16.row.col.f32.f16.f16.f32 "
        "{%0,%1,%2,%3},{%4,%5,%6,%7},{%8,%9},{%0,%1,%2,%3};"
        : "+f"(c[0]), "+f"(c[1]), "+f"(c[2]), "+f"(c[3])
        : "r"(a[0]), "r"(a[1]), "r"(a[2]), "r"(a[3]), "r"(b0), "r"(b1));
}

// ---------------- backbone: conv 3->64, k16 s16 VALID, relu (split-K x4) ------
__global__ void k_backbone(const float* __restrict__ x, const float* __restrict__ w,
                           const float* __restrict__ b) {
    __shared__ float patch[768];
    __shared__ float part[256];
    int pos = blockIdx.x;
    int h = pos >> 4, wq = pos & 15;
    int tid = threadIdx.x;     // 256
    for (int k = tid; k < 768; k += 256) {
        int ic = k >> 8, r = k & 255, iy = r >> 4, ix = r & 15;
        patch[k] = x[ic * 65536 + (h * 16 + iy) * 256 + (wq * 16 + ix)];
    }
    __syncthreads();
    int oc = tid & 63, ch = tid >> 6;
    const float* wp = w + oc * 768 + ch * 192;
    const float* pp = patch + ch * 192;
    float a0 = 0.f, a1 = 0.f;
#pragma unroll 8
    for (int k = 0; k < 192; k += 2) { a0 += pp[k] * wp[k]; a1 += pp[k + 1] * wp[k + 1]; }
    part[tid] = a0 + a1;
    __syncthreads();
    if (tid < 64) {
        float s = b[tid] + part[tid] + part[tid + 64] + part[tid + 128] + part[tid + 192];
        float v = fmaxf(s, 0.f);
        g_feat[tid * 256 + pos] = v;
        g_featT[pos * 64 + tid] = v;
        g_featP[tid * 324 + (h + 1) * 18 + (wq + 1)] = v;
    }
}

// ---------------- rpn conv 3x3 SAME, relu (smem-staged features, split-K x4) ----
__global__ void k_rpnconv(const float* __restrict__ w, const float* __restrict__ b) {
    __shared__ float s_f[576];   // [ic][3][3] window for this position
    __shared__ float part[256];
    int pos = blockIdx.x;
    int y = pos >> 4, xq = pos & 15;
    int tid = threadIdx.x;     // 256
    for (int k = tid; k < 576; k += 256) {
        int ic = k / 9, r = k % 9, ky = r / 3, kx = r % 3;
        s_f[k] = g_featP[ic * 324 + (y + ky) * 18 + (xq + kx)];
    }
    __syncthreads();
    int oc = tid & 63, ch = tid >> 6;
    float acc0 = 0.f, acc1 = 0.f;
    for (int icl = 0; icl < 16; icl += 2) {
        int ic = ch * 16 + icl;
        const float* f0 = s_f + ic * 9;
        const float* wb0 = w + oc * 576 + ic * 9;
#pragma unroll
        for (int k = 0; k < 9; k++) {
            acc0 += f0[k] * wb0[k];
            acc1 += f0[9 + k] * wb0[9 + k];
        }
    }
    part[tid] = acc0 + acc1;
    __syncthreads();
    if (tid < 64) {
        float s = b[tid] + part[tid] + part[tid + 64] + part[tid + 128] + part[tid + 192];
        g_hrpn[tid * 256 + pos] = fmaxf(s, 0.f);
    }
}

// -------- rpn heads (1x1), anchors, softmax score, decode, clip --------
__global__ void k_heads1(const float* __restrict__ wc, const float* __restrict__ bc,
                         const float* __restrict__ wb, const float* __restrict__ bb,
                         float* __restrict__ o_logits, float* __restrict__ o_deltas,
                         float* __restrict__ o_anch) {
    int i = blockIdx.x * blockDim.x + threadIdx.x;
    if (i >= NANCH) return;
    int cell = i / 9, a = i % 9;
    float l0 = bc[a * 2], l1 = bc[a * 2 + 1];
    float d0 = bb[a * 4], d1 = bb[a * 4 + 1], d2 = bb[a * 4 + 2], d3 = bb[a * 4 + 3];
    for (int ic = 0; ic < 64; ic++) {
        float f = g_hrpn[ic * 256 + cell];
        l0 += f * wc[(a * 2) * 64 + ic];
        l1 += f * wc[(a * 2 + 1) * 64 + ic];
        d0 += f * wb[(a * 4) * 64 + ic];
        d1 += f * wb[(a * 4 + 1) * 64 + ic];
        d2 += f * wb[(a * 4 + 2) * 64 + ic];
        d3 += f * wb[(a * 4 + 3) * 64 + ic];
    }
    o_logits[i * 2] = l0; o_logits[i * 2 + 1] = l1;
    o_deltas[i * 4] = d0; o_deltas[i * 4 + 1] = d1;
    o_deltas[i * 4 + 2] = d2; o_deltas[i * 4 + 3] = d3;
    float m = fmaxf(l0, l1);
    float e0 = expf(l0 - m), e1 = expf(l1 - m);
    g_scores[i] = e1 / (e0 + e1);

    const float S[3] = {32.f, 64.f, 128.f};
    const float R[3] = {0.5f, 1.f, 2.f};
    int h = cell >> 4, wq = cell & 15;
    float s = S[a / 3], r = R[a % 3];
    float ws = s * sqrtf(r), hs = s / sqrtf(r);
    float cx = (wq + 0.5f) * 16.f, cy = (h + 0.5f) * 16.f;
    float ax1 = cx - ws * 0.5f, ay1 = cy - hs * 0.5f;
    float ax2 = cx + ws * 0.5f, ay2 = cy + hs * 0.5f;
    o_anch[i * 4] = ax1; o_anch[i * 4 + 1] = ay1;
    o_anch[i * 4 + 2] = ax2; o_anch[i * 4 + 3] = ay2;

    float aw = ax2 - ax1, ah = ay2 - ay1;
    float acx = ax1 + 0.5f * aw, acy = ay1 + 0.5f * ah;
    float ncx = acx + d0 * aw, ncy = acy + d1 * ah;
    float nw = aw * expf(d2), nh = ah * expf(d3);
    g_boxes[i * 4]     = fminf(fmaxf(ncx - 0.5f * nw, 0.f), 255.f);
    g_boxes[i * 4 + 1] = fminf(fmaxf(ncy - 0.5f * nh, 0.f), 255.f);
    g_boxes[i * 4 + 2] = fminf(fmaxf(ncx + 0.5f * nw, 0.f), 255.f);
    g_boxes[i * 4 + 3] = fminf(fmaxf(ncy + 0.5f * nh, 0.f), 255.f);
}

// -------- pack mask-conv weights: [oc][ic][9] -> [slab][oc][ic], fp16 ----
__global__ void k_packwh(const float* __restrict__ w) {
    int i = blockIdx.x * blockDim.x + threadIdx.x;
    if (i >= 9 * 64 * 64) return;
    int slab = i >> 12, r = i & 4095, oc = r >> 6, ic = r & 63;
    g_wh[i] = __half_as_ushort(__float2half_rn(w[oc * 576 + ic * 9 + slab]));
}

// -------- single-block bitonic sort: desc value, stable idx; fused box gather ----
template <int SIZE>
__global__ void k_sort(const float* __restrict__ sc, int n, int* __restrict__ ord,
                       const float* __restrict__ boxes, float4* __restrict__ sb,
                       float* __restrict__ sa) {
    __shared__ unsigned long long k[SIZE];
    int tid = threadIdx.x;
    for (int i = tid; i < SIZE; i += 1024) {
        if (i < n) {
            unsigned u = __float_as_uint(sc[i]);
            unsigned o = (u & 0x80000000u) ? ~u : (u | 0x80000000u);
            k[i] = ((unsigned long long)(~o) << 32) | (unsigned)i;
        } else k[i] = 0xFFFFFFFFFFFFFFFFULL;
    }
    __syncthreads();
    for (int kk = 2; kk <= SIZE; kk <<= 1) {
        for (int j = kk >> 1; j > 0; j >>= 1) {
            for (int i = tid; i < SIZE; i += 1024) {
                int ixj = i ^ j;
                if (ixj > i) {
                    bool up = ((i & kk) == 0);
                    unsigned long long a = k[i], b = k[ixj];
                    if ((a > b) == up) { k[i] = b; k[ixj] = a; }
                }
            }
            __syncthreads();
        }
    }
    for (int i = tid; i < n; i += 1024) {
        int idx = (int)(k[i] & 0xFFFFFFFFu);
        ord[i] = idx;
        float4 b = *(const float4*)&boxes[idx * 4];
        sb[i] = b;
        sa[i] = fmaxf(b.z - b.x, 0.f) * fmaxf(b.w - b.y, 0.f);
    }
}

// -------- IoU bitmask matrix --------
template <int N, int NW>
__global__ void k_ioumask(const float4* __restrict__ sb, const float* __restrict__ sa,
                          unsigned long long* __restrict__ mask, float thr) {
    __shared__ float4 cbx[64];
    __shared__ float car[64];
    int rb = blockIdx.y, cb = blockIdx.x;
    int t = threadIdx.x;
    int j0 = cb * 64;
    if (j0 + t < N) { cbx[t] = sb[j0 + t]; car[t] = sa[j0 + t]; }
    __syncthreads();
    int i = rb * 64 + t;
    if (i >= N) return;
    float4 bi = sb[i];
    float ai = sa[i];
    unsigned long long m = 0;
    int jmax = min(64, N - j0);
    for (int jj = 0; jj < jmax; jj++) {
        int j = j0 + jj;
        if (j <= i) continue;
        float xx1 = fmaxf(bi.x, cbx[jj].x), yy1 = fmaxf(bi.y, cbx[jj].y);
        float xx2 = fminf(bi.z, cbx[jj].z), yy2 = fminf(bi.w, cbx[jj].w);
        float inter = fmaxf(xx2 - xx1, 0.f) * fmaxf(yy2 - yy1, 0.f);
        float iou = inter / (ai + car[jj] - inter + 1e-8f);
        if (iou > thr) m |= 1ULL << jj;
    }
    mask[(size_t)i * NW + cb] = m;
}

// -------- chunked exact greedy reduce over bitmasks; one warp --------
template <int N, int NW>
__global__ void k_nmsreduce(const unsigned long long* __restrict__ mask,
                            int* __restrict__ keep) {
    __shared__ unsigned long long s_blk[64];
    int lane = threadIdx.x;                      // 32
    unsigned long long remv0 = 0ULL, remv1 = 0ULL;
    const int NC = (N + 63) / 64;
    for (int cb = 0; cb < NC; cb++) {
        int j0 = cb * 64;
        int jmax = min(64, N - j0);
        for (int t = lane; t < jmax; t += 32)
            s_blk[t] = mask[(size_t)(j0 + t) * NW + cb];
        __syncwarp();
        int owner = cb & 31;
        unsigned long long r = __shfl_sync(0xffffffffu, (cb < 32) ? remv0 : remv1, owner);
        unsigned long long kept = 0ULL;
        if (lane == 0) {
#pragma unroll 4
            for (int jj = 0; jj < jmax; jj++) {
                if (!((r >> jj) & 1ULL)) {
                    kept |= 1ULL << jj;
                    r |= s_blk[jj];
                }
            }
        }
        kept = __shfl_sync(0xffffffffu, kept, 0);
        r = __shfl_sync(0xffffffffu, r, 0);
        if (lane == owner) { if (cb < 32) remv0 = r; else remv1 = r; }
        for (int t = lane; t < jmax; t += 32)
            keep[j0 + t] = (int)((kept >> t) & 1ULL);
        int w1 = lane, w2 = lane + 32;
        bool u1 = (w1 > cb) && (w1 < NW), u2 = (w2 > cb) && (w2 < NW);
        for (int jj = 0; jj < jmax; jj++) {
            if ((kept >> jj) & 1ULL) {
                const unsigned long long* row = mask + (size_t)(j0 + jj) * NW;
                if (u1) remv0 |= row[w1];
                if (u2) remv1 |= row[w2];
            }
        }
        __syncwarp();
    }
}

// -------- stable kept-first selection of NPROP proposals --------
__global__ void k_select1(float* __restrict__ o_props) {
    __shared__ int s_src[NPROP];
    int tid = threadIdx.x;
    if (tid < 32) {
        const int CH = NANCH / 32;
        int beg = tid * CH, end = beg + CH;
        int cnt = 0;
        for (int i = beg; i < end; i++) cnt += g_keep1[i];
        int xsc = cnt;
        for (int off = 1; off < 32; off <<= 1) {
            int v = __shfl_up_sync(0xffffffffu, xsc, off);
            if (tid >= off) xsc += v;
        }
        int excl = xsc - cnt;
        int total = __shfl_sync(0xffffffffu, xsc, 31);
        int kpos = excl;
        int npos = total + (beg - excl);
        for (int i = beg; i < end; i++) {
            int pos = g_keep1[i] ? kpos++ : npos++;
            if (pos < NPROP) s_src[pos] = i;
        }
    }
    __syncthreads();
    for (int p = tid; p < NPROP; p += 1024) {
        int i = s_src[p];
        int v = g_keep1[i];
        float4 bb = g_sb1[i];
        float px1 = v ? bb.x : 0.f, py1 = v ? bb.y : 0.f;
        float px2 = v ? bb.z : 0.f, py2 = v ? bb.w : 0.f;
        g_props[p * 4] = px1; g_props[p * 4 + 1] = py1;
        g_props[p * 4 + 2] = px2; g_props[p * 4 + 3] = py2;
        o_props[p * 4] = px1; o_props[p * 4 + 1] = py1;
        o_props[p * 4 + 2] = px2; o_props[p * 4 + 3] = py2;
        g_valid[p] = v;
    }
}

// ===================== ROI body: fp16 MMA implicit GEMM =====================
// smem: half crop [16][16][72] | half wslab [64][72] | fp32 w2/b1/grid
#define CROPH_H (16 * 16 * 72)        // halves
#define WSLAB_H (64 * 72)             // halves
#define SMEM_ROI_BYTES (CROPH_H * 2 + WSLAB_H * 2 + (64 + 64 + 28) * 4 + 56 * 4 + 16)

__device__ __forceinline__ void roi_body(
    int tid, float bx1, float by1, float bx2, float by2,
    const float* __restrict__ bm1, const float* __restrict__ wm2,
    const float* __restrict__ bm2,
    float* __restrict__ flat_out, float* __restrict__ maskA, float* __restrict__ maskB,
    __half* smem)
{
    __half* s_ch = smem;                       // [yH][xH][72] halves
    __half* s_wh = smem + CROPH_H;             // [oc][72] halves per slab
    float* s_w2 = (float*)(smem + CROPH_H + WSLAB_H);
    float* s_b1 = s_w2 + 64;
    float* s_wy = s_b1 + 64;
    float* s_wx = s_wy + 14;
    int* s_y0 = (int*)(s_wx + 14);
    int* s_y1 = s_y0 + 14;
    int* s_x0 = s_y1 + 14;
    int* s_x1 = s_x0 + 14;

    int lane = tid & 31, wrp = tid >> 5;     // 8 warps

    if (tid < 28) {
        int t = tid % 14;
        float tt = (float)t / 13.0f;
        if (tid < 14) {
            float y1n = by1 / 255.0f, y2n = by2 / 255.0f;
            float fy = (y1n + (y2n - y1n) * tt) * 15.0f;
            float y0f = fminf(fmaxf(floorf(fy), 0.f), 15.f);
            int y0 = (int)y0f;
            s_y0[t] = y0; s_y1[t] = min(y0 + 1, 15); s_wy[t] = fy - y0f;
        } else {
            float x1n = bx1 / 255.0f, x2n = bx2 / 255.0f;
            float fx = (x1n + (x2n - x1n) * tt) * 15.0f;
            float x0f = fminf(fmaxf(floorf(fx), 0.f), 15.f);
            int x0 = (int)x0f;
            s_x0[t] = x0; s_x1[t] = min(x0 + 1, 15); s_wx[t] = fx - x0f;
        }
    }
    if (tid >= 32 && tid < 96) {
        int c = tid - 32;
        s_w2[c] = wm2[c];
        s_b1[c] = bm1[c];
    }
    // zero half crop (borders + ic pad)
    for (int idx = tid; idx < CROPH_H / 2; idx += 256)
        ((unsigned*)s_ch)[idx] = 0u;
    __syncthreads();

    // fused bilinear crop (fp32) + 2x2 maxpool + fp16 store
    const float4* ft4 = (const float4*)g_featT;
    for (int task = tid; task < 784; task += 256) {
        int cell = task >> 4, c4 = task & 15;
        int py = cell / 7, px = cell - py * 7;
        float4 v[2][2];
#pragma unroll
        for (int dy = 0; dy < 2; dy++)
#pragma unroll
            for (int dx = 0; dx < 2; dx++) {
                int ty = 2 * py + dy, tx = 2 * px + dx;
                int y0 = s_y0[ty], y1 = s_y1[ty], x0 = s_x0[tx], x1 = s_x1[tx];
                float wy = s_wy[ty], wx = s_wx[tx];
                float4 f00 = ft4[(y0 * 16 + x0) * 16 + c4];
                float4 f01 = ft4[(y0 * 16 + x1) * 16 + c4];
                float4 f10 = ft4[(y1 * 16 + x0) * 16 + c4];
                float4 f11 = ft4[(y1 * 16 + x1) * 16 + c4];
                float4 r;
                { float top = f00.x * (1.f - wx) + f01.x * wx;
                  float bot = f10.x * (1.f - wx) + f11.x * wx;
                  r.x = top * (1.f - wy) + bot * wy; }
                { float top = f00.y * (1.f - wx) + f01.y * wx;
                  float bot = f10.y * (1.f - wx) + f11.y * wx;
                  r.y = top * (1.f - wy) + bot * wy; }
                { float top = f00.z * (1.f - wx) + f01.z * wx;
                  float bot = f10.z * (1.f - wx) + f11.z * wx;
                  r.z = top * (1.f - wy) + bot * wy; }
                { float top = f00.w * (1.f - wx) + f01.w * wx;
                  float bot = f10.w * (1.f - wx) + f11.w * wx;
                  r.w = top * (1.f - wy) + bot * wy; }
                v[dy][dx] = r;
                __half2* dst = (__half2*)&s_ch[((ty + 1) * 16 + (tx + 1)) * 72 + c4 * 4];
                dst[0] = __floats2half2_rn(r.x, r.y);
                dst[1] = __floats2half2_rn(r.z, r.w);
            }
        // pool (exact fp32)
        flat_out[(c4 * 4 + 0) * 49 + cell] =
            fmaxf(fmaxf(v[0][0].x, v[0][1].x), fmaxf(v[1][0].x, v[1][1].x));
        flat_out[(c4 * 4 + 1) * 49 + cell] =
            fmaxf(fmaxf(v[0][0].y, v[0][1].y), fmaxf(v[1][0].y, v[1][1].y));
        flat_out[(c4 * 4 + 2) * 49 + cell] =
            fmaxf(fmaxf(v[0][0].z, v[0][1].z), fmaxf(v[1][0].z, v[1][1].z));
        flat_out[(c4 * 4 + 3) * 49 + cell] =
            fmaxf(fmaxf(v[0][0].w, v[0][1].w), fmaxf(v[1][0].w, v[1][1].w));
    }

    // per-thread A-row bases (half units)
    int g = lane >> 2, q = lane & 3;
    int pb[2][2];
#pragma unroll
    for (int mt = 0; mt < 2; mt++)
#pragma unroll
        for (int hh = 0; hh < 2; hh++) {
            int p = wrp * 32 + mt * 16 + g + hh * 8;
            if (p < 196) {
                int y = p / 14, xx = p % 14;
                pb[mt][hh] = (y * 16 + xx) * 72;
            } else pb[mt][hh] = 0;
        }

    float c[2][8][4];
#pragma unroll
    for (int mt = 0; mt < 2; mt++)
#pragma unroll
        for (int nt = 0; nt < 8; nt++)
#pragma unroll
            for (int j = 0; j < 4; j++) c[mt][nt][j] = 0.f;

    const unsigned* gwu = (const unsigned*)g_wh;
    for (int slab = 0; slab < 9; slab++) {
        __syncthreads();
        // stage weights [oc][72] halves (pad ic 64..71 zero)
        for (int f = tid; f < 2304; f += 256) {      // uints
            int oc = f / 36, icu = f - oc * 36;
            ((unsigned*)s_wh)[oc * 36 + icu] =
                (icu < 32) ? gwu[slab * 2048 + oc * 32 + icu] : 0u;
        }
        __syncthreads();
        int ky = slab / 3, kx = slab % 3;
        int off = (ky * 16 + kx) * 72;
#pragma unroll
        for (int kT = 0; kT < 4; kT++) {
            int ab = off + kT * 16 + 2 * q;
            unsigned a[2][4];
#pragma unroll
            for (int mt = 0; mt < 2; mt++) {
                a[mt][0] = *(const unsigned*)&s_ch[pb[mt][0] + ab];
                a[mt][1] = *(const unsigned*)&s_ch[pb[mt][1] + ab];
                a[mt][2] = *(const unsigned*)&s_ch[pb[mt][0] + ab + 8];
                a[mt][3] = *(const unsigned*)&s_ch[pb[mt][1] + ab + 8];
            }
            int bbase = kT * 16 + 2 * q;
#pragma unroll
            for (int nt = 0; nt < 8; nt++) {
                int oc = nt * 8 + g;
                unsigned b0 = *(const unsigned*)&s_wh[oc * 72 + bbase];
                unsigned b1 = *(const unsigned*)&s_wh[oc * 72 + bbase + 8];
                mma_f16(c[0][nt], a[0], b0, b1);
                mma_f16(c[1][nt], a[1], b0, b1);
            }
        }
    }

    // bias + relu + 1x1 conv in registers; reduce across 4-lane row group
    float part[2][2] = {{0.f, 0.f}, {0.f, 0.f}};
#pragma unroll
    for (int nt = 0; nt < 8; nt++) {
        int col0 = nt * 8 + q * 2, col1 = col0 + 1;
        float bA = s_b1[col0], bB = s_b1[col1];
        float w20 = s_w2[col0], w21 = s_w2[col1];
#pragma unroll
        for (int mt = 0; mt < 2; mt++) {
            part[mt][0] += fmaxf(c[mt][nt][0] + bA, 0.f) * w20
                         + fmaxf(c[mt][nt][1] + bB, 0.f) * w21;
            part[mt][1] += fmaxf(c[mt][nt][2] + bA, 0.f) * w20
                         + fmaxf(c[mt][nt][3] + bB, 0.f) * w21;
        }
    }
    float b2 = bm2[0];
#pragma unroll
    for (int mt = 0; mt < 2; mt++)
#pragma unroll
        for (int hh = 0; hh < 2; hh++) {
            float v = part[mt][hh];
            v += __shfl_xor_sync(0xffffffffu, v, 1);
            v += __shfl_xor_sync(0xffffffffu, v, 2);
            int p = wrp * 32 + mt * 16 + g + hh * 8;
            if (q == 0 && p < 196) {
                float logit = b2 + v;
                maskA[p] = logit;
                maskB[p] = logit;
            }
        }
}

__global__ void __launch_bounds__(256, 2)
k_roizero(const float* __restrict__ bm1, const float* __restrict__ wm2,
          const float* __restrict__ bm2) {
    extern __shared__ __half smem_h[];
    roi_body(threadIdx.x, 0.f, 0.f, 0.f, 0.f, bm1, wm2, bm2,
             g_flatz, g_maskz, g_maskz, smem_h);
}

__global__ void __launch_bounds__(256, 2)
k_roi(const float* __restrict__ bm1, const float* __restrict__ wm2,
      const float* __restrict__ bm2, float* __restrict__ omask) {
    extern __shared__ __half smem_h[];
    int p = blockIdx.x, tid = threadIdx.x;
    if (!g_valid[p]) {
        float* fo = g_flat + (size_t)p * 3136;
        for (int idx = tid; idx < 784; idx += 256)
            ((float4*)fo)[idx] = ((const float4*)g_flatz)[idx];
        for (int pos = tid; pos < 196; pos += 256) {
            float v = g_maskz[pos];
            omask[(size_t)p * 196 + pos] = v;
            g_masks[(size_t)p * 196 + pos] = v;
        }
        return;
    }
    roi_body(tid, g_props[p * 4], g_props[p * 4 + 1], g_props[p * 4 + 2], g_props[p * 4 + 3],
             bm1, wm2, bm2,
             g_flat + (size_t)p * 3136, omask + (size_t)p * 196,
             g_masks + (size_t)p * 196, smem_h);
}

// -------- SGEMM 64x64x8, 128 thr, 8x4 micro, double-buffered: C=relu(A·B+bias) ----
__global__ void k_gemm64(const float* __restrict__ Ax, const float* __restrict__ Bx,
                         const float* __restrict__ bias, float* __restrict__ C,
                         int M, int N, int K) {
    __shared__ float As[2][8][72];
    __shared__ float Bs[2][8][64];
    int tid = threadIdx.x;              // 128
    int tx = tid & 15, ty = tid >> 4;   // ty 0..7
    int bm = blockIdx.y * 64, bn = blockIdx.x * 64;
    float acc[8][4];
#pragma unroll
    for (int i = 0; i < 8; i++)
#pragma unroll
        for (int j = 0; j < 4; j++) acc[i][j] = 0.f;

    int arow = tid >> 1, ac4 = (tid & 1) * 4;
    int bkr = tid >> 4, bc4 = (tid & 15) * 4;
    int row = bm + arow;
    const int nk = K / 8;

    float4 ra, rb;
    ra = make_float4(0.f, 0.f, 0.f, 0.f);
    if (row < M) ra = *(const float4*)&Ax[(size_t)row * K + ac4];
    rb = *(const float4*)&Bx[(size_t)bkr * N + bn + bc4];
    As[0][ac4 + 0][arow] = ra.x; As[0][ac4 + 1][arow] = ra.y;
    As[0][ac4 + 2][arow] = ra.z; As[0][ac4 + 3][arow] = ra.w;
    *(float4*)&Bs[0][bkr][bc4] = rb;
    __syncthreads();
    int cur = 0;
    for (int t = 1; t < nk; t++) {
        int k0 = t * 8;
        ra = make_float4(0.f, 0.f, 0.f, 0.f);
        if (row < M) ra = *(const float4*)&Ax[(size_t)row * K + k0 + ac4];
        rb = *(const float4*)&Bx[(size_t)(k0 + bkr) * N + bn + bc4];
#pragma unroll
        for (int k = 0; k < 8; k++) {
            float4 a0 = *(const float4*)&As[cur][k][ty * 8];
            float4 a1 = *(const float4*)&As[cur][k][ty * 8 + 4];
            float4 b0 = *(const float4*)&Bs[cur][k][tx * 4];
            float aval[8] = {a0.x, a0.y, a0.z, a0.w, a1.x, a1.y, a1.z, a1.w};
            float bval[4] = {b0.x, b0.y, b0.z, b0.w};
#pragma unroll
            for (int i2 = 0; i2 < 8; i2++)
#pragma unroll
                for (int j2 = 0; j2 < 4; j2++) acc[i2][j2] += aval[i2] * bval[j2];
        }
        int nxt = cur ^ 1;
        As[nxt][ac4 + 0][arow] = ra.x; As[nxt][ac4 + 1][arow] = ra.y;
        As[nxt][ac4 + 2][arow] = ra.z; As[nxt][ac4 + 3][arow] = ra.w;
        *(float4*)&Bs[nxt][bkr][bc4] = rb;
        __syncthreads();
        cur = nxt;
    }
#pragma unroll
    for (int k = 0; k < 8; k++) {
        float4 a0 = *(const float4*)&As[cur][k][ty * 8];
        float4 a1 = *(const float4*)&As[cur][k][ty * 8 + 4];
        float4 b0 = *(const float4*)&Bs[cur][k][tx * 4];
        float aval[8] = {a0.x, a0.y, a0.z, a0.w, a1.x, a1.y, a1.z, a1.w};
        float bval[4] = {b0.x, b0.y, b0.z, b0.w};
#pragma unroll
        for (int i2 = 0; i2 < 8; i2++)
#pragma unroll
            for (int j2 = 0; j2 < 4; j2++) acc[i2][j2] += aval[i2] * bval[j2];
    }
#pragma unroll
    for (int i2 = 0; i2 < 8; i2++) {
        int r2 = bm + ty * 8 + i2;
        if (r2 >= M) continue;
#pragma unroll
        for (int j2 = 0; j2 < 4; j2++) {
            int col = bn + tx * 4 + j2;
            C[(size_t)r2 * N + col] = fmaxf(acc[i2][j2] + bias[col], 0.f);
        }
    }
}

// -------- rcnn cls/box heads + fused stage-2 decode --------
__global__ void k_rheads(const float* __restrict__ wrc, const float* __restrict__ brc,
                         const float* __restrict__ wrb, const float* __restrict__ brb,
                         float* __restrict__ o_log, float* __restrict__ o_del,
                         float* __restrict__ dets) {
    __shared__ float s6[6];
    int p = blockIdx.x;
    int w = threadIdx.x >> 5, lane = threadIdx.x & 31;
    const float* hp = g_h2 + (size_t)p * 512;
    float s = 0.f;
    if (w < 2) {
        for (int k = lane; k < 512; k += 32) s += hp[k] * wrc[k * 2 + w];
    } else {
        int j = w - 2;
        for (int k = lane; k < 512; k += 32) s += hp[k] * wrb[k * 4 + j];
    }
    for (int off = 16; off > 0; off >>= 1) s += __shfl_down_sync(0xffffffffu, s, off);
    if (lane == 0) {
        if (w < 2) {
            float v = s + brc[w];
            o_log[p * 2 + w] = v;
            g_rlogits[p * 2 + w] = v;
            s6[w] = v;
        } else {
            int j = w - 2;
            float v = s + brb[j];
            o_del[p * 4 + j] = v;
            g_rdeltas[p * 4 + j] = v;
            s6[w] = v;
        }
    }
    __syncthreads();
    if (threadIdx.x == 0) {
        float l0 = s6[0], l1 = s6[1];
        float m = fmaxf(l0, l1);
        float e0 = expf(l0 - m), e1 = expf(l1 - m);
        float sc = e1 / (e0 + e1);
        g_dscores[p] = sc;
        float x1 = g_props[p * 4], y1 = g_props[p * 4 + 1];
        float x2 = g_props[p * 4 + 2], y2 = g_props[p * 4 + 3];
        float wd = x2 - x1, h = y2 - y1;
        float cx = x1 + 0.5f * wd, cy = y1 + 0.5f * h;
        float d0 = s6[2], d1 = s6[3], d2 = s6[4], d3 = s6[5];
        float ncx = cx + d0 * wd, ncy = cy + d1 * h;
        float nw = wd * expf(d2), nh = h * expf(d3);
        dets[p * 4]     = fminf(fmaxf(ncx - 0.5f * nw, 0.f), 255.f);
        dets[p * 4 + 1] = fminf(fmaxf(ncy - 0.5f * nh, 0.f), 255.f);
        dets[p * 4 + 2] = fminf(fmaxf(ncx + 0.5f * nw, 0.f), 255.f);
        dets[p * 4 + 3] = fminf(fmaxf(ncy + 0.5f * nh, 0.f), 255.f);
        g_s2[p] = g_valid[p] ? sc : -1.0f;
    }
}

// -------- final dets/scores/keep2 + masks (fused) --------
__global__ void k_final(float* __restrict__ o_fdets, float* __restrict__ o_fsc,
                        float* __restrict__ o_keep, float* __restrict__ o_fmsk) {
    __shared__ float s_kf;
    __shared__ int s_oi;
    int r = blockIdx.x, i = threadIdx.x;    // 196 threads
    if (i == 0) {
        int o = g_order2[r];
        int k2 = g_keep2a[r] && g_valid[o];
        float kf = k2 ? 1.f : 0.f;
        float4 d = g_sb2[r];
        o_fdets[r * 4]     = k2 ? d.x : 0.f;
        o_fdets[r * 4 + 1] = k2 ? d.y : 0.f;
        o_fdets[r * 4 + 2] = k2 ? d.z : 0.f;
        o_fdets[r * 4 + 3] = k2 ? d.w : 0.f;
        o_fsc[r] = k2 ? g_dscores[o] : 0.f;
        if (o_keep) o_keep[r] = kf;
        s_kf = kf;
        s_oi = o;
    }
    __syncthreads();
    float v = g_masks[(size_t)s_oi * 196 + i];
    float sgm = 1.f / (1.f + expf(-v));
    o_fmsk[(size_t)r * 196 + i] = sgm * s_kf;
}

// ---------------- host ----------------
extern "C" void kernel_launch(void* const* d_in, const int* in_sizes, int n_in,
                              void* d_out, int out_size) {
    const float* x      = (const float*)d_in[0];
    const float* w_bb   = (const float*)d_in[1];
    const float* b_bb   = (const float*)d_in[2];
    const float* w_rpn  = (const float*)d_in[3];
    const float* b_rpn  = (const float*)d_in[4];
    const float* w_cls  = (const float*)d_in[5];
    const float* b_cls  = (const float*)d_in[6];
    const float* w_box  = (const float*)d_in[7];
    const float* b_box  = (const float*)d_in[8];
    const float* w_fc1  = (const float*)d_in[9];
    const float* b_fc1  = (const float*)d_in[10];
    const float* w_fc2  = (const float*)d_in[11];
    const float* b_fc2  = (const float*)d_in[12];
    const float* w_rcls = (const float*)d_in[13];
    const float* b_rcls = (const float*)d_in[14];
    const float* w_rbox = (const float*)d_in[15];
    const float* b_rbox = (const float*)d_in[16];
    const float* w_m1   = (const float*)d_in[17];
    const float* b_m1   = (const float*)d_in[18];
    const float* w_m2   = (const float*)d_in[19];
    const float* b_m2   = (const float*)d_in[20];
    float* out = (float*)d_out;

    const size_t O_RPNL = 0, O_RPND = 4608, O_PROP = 13824, O_ANCH = 21824;
    const size_t O_RLOG = 31040, O_RDEL = 35040, O_RMSK = 43040;
    const size_t O_FDET = 435040, O_FMSK = 443040, O_FSC = 835040, O_KEEP = 837040;

    float *p_scores, *p_s2, *p_flat, *p_h1, *p_h2, *p_dets, *p_boxes;
    int *p_order, *p_order2, *p_keep1, *p_keep2a;
    unsigned long long *p_mask1, *p_mask2;
    cudaGetSymbolAddress((void**)&p_scores, g_scores);
    cudaGetSymbolAddress((void**)&p_order, g_order);
    cudaGetSymbolAddress((void**)&p_s2, g_s2);
    cudaGetSymbolAddress((void**)&p_order2, g_order2);
    cudaGetSymbolAddress((void**)&p_flat, g_flat);
    cudaGetSymbolAddress((void**)&p_h1, g_h1);
    cudaGetSymbolAddress((void**)&p_h2, g_h2);
    cudaGetSymbolAddress((void**)&p_dets, g_dets);
    cudaGetSymbolAddress((void**)&p_boxes, g_boxes);
    cudaGetSymbolAddress((void**)&p_keep1, g_keep1);
    cudaGetSymbolAddress((void**)&p_keep2a, g_keep2a);
    cudaGetSymbolAddress((void**)&p_mask1, g_mask1);
    cudaGetSymbolAddress((void**)&p_mask2, g_mask2);

    cudaFuncSetAttribute(k_roi, cudaFuncAttributeMaxDynamicSharedMemorySize, SMEM_ROI_BYTES);
    cudaFuncSetAttribute(k_roizero, cudaFuncAttributeMaxDynamicSharedMemorySize, SMEM_ROI_BYTES);

    float4* p_sb1; float* p_sa1; float4* p_sb2; float* p_sa2;
    cudaGetSymbolAddress((void**)&p_sb1, g_sb1);
    cudaGetSymbolAddress((void**)&p_sa1, g_sa1);
    cudaGetSymbolAddress((void**)&p_sb2, g_sb2);
    cudaGetSymbolAddress((void**)&p_sa2, g_sa2);

    k_backbone<<<256, 256>>>(x, w_bb, b_bb);
    k_packwh<<<(9 * 64 * 64 + 255) / 256, 256>>>(w_m1);
    k_roizero<<<1, 256, SMEM_ROI_BYTES>>>(b_m1, w_m2, b_m2);
    k_rpnconv<<<256, 256>>>(w_rpn, b_rpn);
    k_heads1<<<18, 128>>>(w_cls, b_cls, w_box, b_box,
                          out + O_RPNL, out + O_RPND, out + O_ANCH);
    k_sort<4096><<<1, 1024>>>(p_scores, NANCH, p_order, p_boxes, p_sb1, p_sa1);
    k_ioumask<NANCH, NW1><<<dim3(NW1, NW1), 64>>>(p_sb1, p_sa1, p_mask1, 0.5f);
    k_nmsreduce<NANCH, NW1><<<1, 32>>>(p_mask1, p_keep1);
    k_select1<<<1, 1024>>>(out + O_PROP);
    k_roi<<<NPROP, 256, SMEM_ROI_BYTES>>>(b_m1, w_m2, b_m2, out + O_RMSK);

    dim3 gfc(512 / 64, (NPROP + 63) / 64);
    k_gemm64<<<gfc, 128>>>(p_flat, w_fc1, b_fc1, p_h1, NPROP, 512, 3136);
    k_gemm64<<<gfc, 128>>>(p_h1, w_fc2, b_fc2, p_h2, NPROP, 512, 512);
    k_rheads<<<NPROP, 192>>>(w_rcls, b_rcls, w_rbox, b_rbox,
                             out + O_RLOG, out + O_RDEL, p_dets);
    k_sort<2048><<<1, 1024>>>(p_s2, NPROP, p_order2, p_dets, p_sb2, p_sa2);
    k_ioumask<NPROP, NW2><<<dim3(NW2, NW2), 64>>>(p_sb2, p_sa2, p_mask2, 0.3f);
    k_nmsreduce<NPROP, NW2><<<1, 32>>>(p_mask2, p_keep2a);
    float* o_keep = (out_size >= (int)(O_KEEP + NPROP)) ? (out + O_KEEP) : nullptr;
    k_final<<<NPROP, 196>>>(out + O_FDET, out + O_FSC, o_keep, out + O_FMSK);
}

// round 10
// speedup vs baseline: 3.2653x; 1.0434x over previous
#include <cuda_runtime.h>
#include <cuda_fp16.h>
#include <math.h>

#define NANCH 2304
#define NPROP 2000
#define NW1 36
#define NW2 32

// ---------------- scratch (device globals; no allocation) ----------------
__device__ float g_feat[64 * 256];
__device__ float g_featT[256 * 64];
__device__ float g_featP[64 * 18 * 18];
__device__ float g_hrpn[64 * 256];
__device__ float g_scores[NANCH];
__device__ float g_boxes[NANCH * 4];
__device__ int   g_order[NANCH];
__device__ float g_props[NPROP * 4];
__device__ int   g_valid[NPROP];
__device__ float g_flat[NPROP * 3136];
__device__ float g_h1[NPROP * 512];
__device__ float g_h2[NPROP * 512];
__device__ float g_rlogits[NPROP * 2];
__device__ float g_rdeltas[NPROP * 4];
__device__ float g_dscores[NPROP];
__device__ float g_s2[NPROP];
__device__ int   g_order2[NPROP];
__device__ float g_masks[NPROP * 196];
__device__ float g_dets[NPROP * 4];
__device__ unsigned short g_wh[9 * 64 * 64];     // mask-conv weights fp16 [slab][oc][ic]
__device__ float g_wpack[64 * 64 * 12];          // rpn-conv weights float4-aligned
__device__ float g_flatz[3136];
__device__ float g_maskz[196];
// split-fp16 FC weights, transposed [N][K]
__device__ __half g_bh1[512 * 3136];
__device__ __half g_bl1[512 * 3136];
__device__ __half g_bh2[512 * 512];
__device__ __half g_bl2[512 * 512];
// NMS scratch
__device__ float4 g_sb1[NANCH];
__device__ float  g_sa1[NANCH];
__device__ unsigned long long g_mask1[(size_t)NANCH * NW1];
__device__ int    g_keep1[NANCH];
__device__ float4 g_sb2[NPROP];
__device__ float  g_sa2[NPROP];
__device__ unsigned long long g_mask2[(size_t)NPROP * NW2];
__device__ int    g_keep2a[NPROP];

__device__ __forceinline__ void mma_f16(float* c, const unsigned* a,
                                        unsigned b0, unsigned b1) {
    asm volatile(
        "mma.sync.aligned.m16n8k16.row.col.f32.f16.f16.f32 "
        "{%0,%1,%2,%3},{%4,%5,%6,%7},{%8,%9},{%0,%1,%2,%3};"
        : "+f"(c[0]), "+f"(c[1]), "+f"(c[2]), "+f"(c[3])
        : "r"(a[0]), "r"(a[1]), "r"(a[2]), "r"(a[3]), "r"(b0), "r"(b1));
}

// ---------------- backbone ----------------
__global__ void k_backbone(const float* __restrict__ x, const float* __restrict__ w,
                           const float* __restrict__ b) {
    __shared__ float patch[768];
    __shared__ float part[256];
    int pos = blockIdx.x;
    int h = pos >> 4, wq = pos & 15;
    int tid = threadIdx.x;
    for (int k = tid; k < 768; k += 256) {
        int ic = k >> 8, r = k & 255, iy = r >> 4, ix = r & 15;
        patch[k] = x[ic * 65536 + (h * 16 + iy) * 256 + (wq * 16 + ix)];
    }
    __syncthreads();
    int oc = tid & 63, ch = tid >> 6;
    const float* wp = w + oc * 768 + ch * 192;
    const float* pp = patch + ch * 192;
    float a0 = 0.f, a1 = 0.f;
#pragma unroll 8
    for (int k = 0; k < 192; k += 2) { a0 += pp[k] * wp[k]; a1 += pp[k + 1] * wp[k + 1]; }
    part[tid] = a0 + a1;
    __syncthreads();
    if (tid < 64) {
        float s = b[tid] + part[tid] + part[tid + 64] + part[tid + 128] + part[tid + 192];
        float v = fmaxf(s, 0.f);
        g_feat[tid * 256 + pos] = v;
        g_featT[pos * 64 + tid] = v;
        g_featP[tid * 324 + (h + 1) * 18 + (wq + 1)] = v;
    }
}

// -------- pack rpn weights [oc][ic][9] -> [oc][ic][12] (float4-aligned) ----
__global__ void k_packw(const float* __restrict__ w) {
    int i = blockIdx.x * blockDim.x + threadIdx.x;
    if (i >= 64 * 64 * 12) return;
    int pair = i / 12, q = i % 12;
    g_wpack[i] = (q < 9) ? w[pair * 9 + q] : 0.f;
}

// ---------------- rpn conv 3x3 SAME, relu (packed float4 weights) ----------------
__global__ void k_rpnconv(const float* __restrict__ b) {
    __shared__ float s_f[576];
    __shared__ float part[256];
    int pos = blockIdx.x;
    int y = pos >> 4, xq = pos & 15;
    int tid = threadIdx.x;
    for (int k = tid; k < 576; k += 256) {
        int ic = k / 9, r = k % 9, ky = r / 3, kx = r % 3;
        s_f[k] = g_featP[ic * 324 + (y + ky) * 18 + (xq + kx)];
    }
    __syncthreads();
    int oc = tid & 63, ch = tid >> 6;
    const float4* wp4 = (const float4*)g_wpack;
    float acc0 = 0.f, acc1 = 0.f;
    for (int icl = 0; icl < 16; icl += 2) {
        int ic = ch * 16 + icl;
        float4 A0 = wp4[(oc * 64 + ic) * 3], A1 = wp4[(oc * 64 + ic) * 3 + 1],
               A2 = wp4[(oc * 64 + ic) * 3 + 2];
        float4 B0 = wp4[(oc * 64 + ic + 1) * 3], B1 = wp4[(oc * 64 + ic + 1) * 3 + 1],
               B2 = wp4[(oc * 64 + ic + 1) * 3 + 2];
        float wAr[9] = {A0.x, A0.y, A0.z, A0.w, A1.x, A1.y, A1.z, A1.w, A2.x};
        float wBr[9] = {B0.x, B0.y, B0.z, B0.w, B1.x, B1.y, B1.z, B1.w, B2.x};
        const float* f0 = s_f + ic * 9;
#pragma unroll
        for (int k = 0; k < 9; k++) {
            acc0 += f0[k] * wAr[k];
            acc1 += f0[9 + k] * wBr[k];
        }
    }
    part[tid] = acc0 + acc1;
    __syncthreads();
    if (tid < 64) {
        float s = b[tid] + part[tid] + part[tid + 64] + part[tid + 128] + part[tid + 192];
        g_hrpn[tid * 256 + pos] = fmaxf(s, 0.f);
    }
}

// -------- rpn heads (1x1), anchors, softmax score, decode, clip --------
__global__ void k_heads1(const float* __restrict__ wc, const float* __restrict__ bc,
                         const float* __restrict__ wb, const float* __restrict__ bb,
                         float* __restrict__ o_logits, float* __restrict__ o_deltas,
                         float* __restrict__ o_anch) {
    int i = blockIdx.x * blockDim.x + threadIdx.x;
    if (i >= NANCH) return;
    int cell = i / 9, a = i % 9;
    float l0 = bc[a * 2], l1 = bc[a * 2 + 1];
    float d0 = bb[a * 4], d1 = bb[a * 4 + 1], d2 = bb[a * 4 + 2], d3 = bb[a * 4 + 3];
    for (int ic = 0; ic < 64; ic++) {
        float f = g_hrpn[ic * 256 + cell];
        l0 += f * wc[(a * 2) * 64 + ic];
        l1 += f * wc[(a * 2 + 1) * 64 + ic];
        d0 += f * wb[(a * 4) * 64 + ic];
        d1 += f * wb[(a * 4 + 1) * 64 + ic];
        d2 += f * wb[(a * 4 + 2) * 64 + ic];
        d3 += f * wb[(a * 4 + 3) * 64 + ic];
    }
    o_logits[i * 2] = l0; o_logits[i * 2 + 1] = l1;
    o_deltas[i * 4] = d0; o_deltas[i * 4 + 1] = d1;
    o_deltas[i * 4 + 2] = d2; o_deltas[i * 4 + 3] = d3;
    float m = fmaxf(l0, l1);
    float e0 = expf(l0 - m), e1 = expf(l1 - m);
    g_scores[i] = e1 / (e0 + e1);

    const float S[3] = {32.f, 64.f, 128.f};
    const float R[3] = {0.5f, 1.f, 2.f};
    int h = cell >> 4, wq = cell & 15;
    float s = S[a / 3], r = R[a % 3];
    float ws = s * sqrtf(r), hs = s / sqrtf(r);
    float cx = (wq + 0.5f) * 16.f, cy = (h + 0.5f) * 16.f;
    float ax1 = cx - ws * 0.5f, ay1 = cy - hs * 0.5f;
    float ax2 = cx + ws * 0.5f, ay2 = cy + hs * 0.5f;
    o_anch[i * 4] = ax1; o_anch[i * 4 + 1] = ay1;
    o_anch[i * 4 + 2] = ax2; o_anch[i * 4 + 3] = ay2;

    float aw = ax2 - ax1, ah = ay2 - ay1;
    float acx = ax1 + 0.5f * aw, acy = ay1 + 0.5f * ah;
    float ncx = acx + d0 * aw, ncy = acy + d1 * ah;
    float nw = aw * expf(d2), nh = ah * expf(d3);
    g_boxes[i * 4]     = fminf(fmaxf(ncx - 0.5f * nw, 0.f), 255.f);
    g_boxes[i * 4 + 1] = fminf(fmaxf(ncy - 0.5f * nh, 0.f), 255.f);
    g_boxes[i * 4 + 2] = fminf(fmaxf(ncx + 0.5f * nw, 0.f), 255.f);
    g_boxes[i * 4 + 3] = fminf(fmaxf(ncy + 0.5f * nh, 0.f), 255.f);
}

// -------- pack mask-conv weights fp16 [slab][oc][ic] ----
__global__ void k_packwh(const float* __restrict__ w) {
    int i = blockIdx.x * blockDim.x + threadIdx.x;
    if (i >= 9 * 64 * 64) return;
    int slab = i >> 12, r = i & 4095, oc = r >> 6, ic = r & 63;
    g_wh[i] = __half_as_ushort(__float2half_rn(w[oc * 576 + ic * 9 + slab]));
}

// -------- pack FC weights: w[K][N] -> Bh/Bl [N][K] split-fp16 ----
__global__ void k_packB(const float* __restrict__ w, __half* __restrict__ Bh,
                        __half* __restrict__ Bl, int K, int N) {
    int i = blockIdx.x * blockDim.x + threadIdx.x;
    if (i >= K * N) return;
    int k = i / N, n = i - k * N;
    float x = w[i];
    __half h = __float2half_rn(x);
    __half l = __float2half_rn(x - __half2float(h));
    Bh[(size_t)n * K + k] = h;
    Bl[(size_t)n * K + k] = l;
}

// -------- single-block bitonic sort + fused box gather --------
template <int SIZE>
__global__ void k_sort(const float* __restrict__ sc, int n, int* __restrict__ ord,
                       const float* __restrict__ boxes, float4* __restrict__ sb,
                       float* __restrict__ sa) {
    __shared__ unsigned long long k[SIZE];
    int tid = threadIdx.x;
    for (int i = tid; i < SIZE; i += 1024) {
        if (i < n) {
            unsigned u = __float_as_uint(sc[i]);
            unsigned o = (u & 0x80000000u) ? ~u : (u | 0x80000000u);
            k[i] = ((unsigned long long)(~o) << 32) | (unsigned)i;
        } else k[i] = 0xFFFFFFFFFFFFFFFFULL;
    }
    __syncthreads();
    for (int kk = 2; kk <= SIZE; kk <<= 1) {
        for (int j = kk >> 1; j > 0; j >>= 1) {
            for (int i = tid; i < SIZE; i += 1024) {
                int ixj = i ^ j;
                if (ixj > i) {
                    bool up = ((i & kk) == 0);
                    unsigned long long a = k[i], b = k[ixj];
                    if ((a > b) == up) { k[i] = b; k[ixj] = a; }
                }
            }
            __syncthreads();
        }
    }
    for (int i = tid; i < n; i += 1024) {
        int idx = (int)(k[i] & 0xFFFFFFFFu);
        ord[i] = idx;
        float4 b = *(const float4*)&boxes[idx * 4];
        sb[i] = b;
        sa[i] = fmaxf(b.z - b.x, 0.f) * fmaxf(b.w - b.y, 0.f);
    }
}

// -------- IoU bitmask matrix --------
template <int N, int NW>
__global__ void k_ioumask(const float4* __restrict__ sb, const float* __restrict__ sa,
                          unsigned long long* __restrict__ mask, float thr) {
    __shared__ float4 cbx[64];
    __shared__ float car[64];
    int rb = blockIdx.y, cb = blockIdx.x;
    int t = threadIdx.x;
    int j0 = cb * 64;
    if (j0 + t < N) { cbx[t] = sb[j0 + t]; car[t] = sa[j0 + t]; }
    __syncthreads();
    int i = rb * 64 + t;
    if (i >= N) return;
    float4 bi = sb[i];
    float ai = sa[i];
    unsigned long long m = 0;
    int jmax = min(64, N - j0);
    for (int jj = 0; jj < jmax; jj++) {
        int j = j0 + jj;
        if (j <= i) continue;
        float xx1 = fmaxf(bi.x, cbx[jj].x), yy1 = fmaxf(bi.y, cbx[jj].y);
        float xx2 = fminf(bi.z, cbx[jj].z), yy2 = fminf(bi.w, cbx[jj].w);
        float inter = fmaxf(xx2 - xx1, 0.f) * fmaxf(yy2 - yy1, 0.f);
        float iou = inter / (ai + car[jj] - inter + 1e-8f);
        if (iou > thr) m |= 1ULL << jj;
    }
    mask[(size_t)i * NW + cb] = m;
}

// -------- chunked exact greedy reduce --------
template <int N, int NW>
__global__ void k_nmsreduce(const unsigned long long* __restrict__ mask,
                            int* __restrict__ keep) {
    __shared__ unsigned long long s_blk[64];
    int lane = threadIdx.x;
    unsigned long long remv0 = 0ULL, remv1 = 0ULL;
    const int NC = (N + 63) / 64;
    for (int cb = 0; cb < NC; cb++) {
        int j0 = cb * 64;
        int jmax = min(64, N - j0);
        for (int t = lane; t < jmax; t += 32)
            s_blk[t] = mask[(size_t)(j0 + t) * NW + cb];
        __syncwarp();
        int owner = cb & 31;
        unsigned long long r = __shfl_sync(0xffffffffu, (cb < 32) ? remv0 : remv1, owner);
        unsigned long long kept = 0ULL;
        if (lane == 0) {
#pragma unroll 4
            for (int jj = 0; jj < jmax; jj++) {
                if (!((r >> jj) & 1ULL)) {
                    kept |= 1ULL << jj;
                    r |= s_blk[jj];
                }
            }
        }
        kept = __shfl_sync(0xffffffffu, kept, 0);
        r = __shfl_sync(0xffffffffu, r, 0);
        if (lane == owner) { if (cb < 32) remv0 = r; else remv1 = r; }
        for (int t = lane; t < jmax; t += 32)
            keep[j0 + t] = (int)((kept >> t) & 1ULL);
        int w1 = lane, w2 = lane + 32;
        bool u1 = (w1 > cb) && (w1 < NW), u2 = (w2 > cb) && (w2 < NW);
        for (int jj = 0; jj < jmax; jj++) {
            if ((kept >> jj) & 1ULL) {
                const unsigned long long* row = mask + (size_t)(j0 + jj) * NW;
                if (u1) remv0 |= row[w1];
                if (u2) remv1 |= row[w2];
            }
        }
        __syncwarp();
    }
}

// -------- stable kept-first selection --------
__global__ void k_select1(float* __restrict__ o_props) {
    __shared__ int s_src[NPROP];
    int tid = threadIdx.x;
    if (tid < 32) {
        const int CH = NANCH / 32;
        int beg = tid * CH, end = beg + CH;
        int cnt = 0;
        for (int i = beg; i < end; i++) cnt += g_keep1[i];
        int xsc = cnt;
        for (int off = 1; off < 32; off <<= 1) {
            int v = __shfl_up_sync(0xffffffffu, xsc, off);
            if (tid >= off) xsc += v;
        }
        int excl = xsc - cnt;
        int total = __shfl_sync(0xffffffffu, xsc, 31);
        int kpos = excl;
        int npos = total + (beg - excl);
        for (int i = beg; i < end; i++) {
            int pos = g_keep1[i] ? kpos++ : npos++;
            if (pos < NPROP) s_src[pos] = i;
        }
    }
    __syncthreads();
    for (int p = tid; p < NPROP; p += 1024) {
        int i = s_src[p];
        int v = g_keep1[i];
        float4 bb = g_sb1[i];
        float px1 = v ? bb.x : 0.f, py1 = v ? bb.y : 0.f;
        float px2 = v ? bb.z : 0.f, py2 = v ? bb.w : 0.f;
        g_props[p * 4] = px1; g_props[p * 4 + 1] = py1;
        g_props[p * 4 + 2] = px2; g_props[p * 4 + 3] = py2;
        o_props[p * 4] = px1; o_props[p * 4 + 1] = py1;
        o_props[p * 4 + 2] = px2; o_props[p * 4 + 3] = py2;
        g_valid[p] = v;
    }
}

// ===================== ROI body: fp16 MMA implicit GEMM =====================
#define CROPH_H (16 * 16 * 72)
#define WSLAB_H (64 * 72)
#define SMEM_ROI_BYTES (CROPH_H * 2 + WSLAB_H * 2 + (64 + 64 + 28) * 4 + 56 * 4 + 16)

__device__ __forceinline__ void roi_body(
    int tid, float bx1, float by1, float bx2, float by2,
    const float* __restrict__ bm1, const float* __restrict__ wm2,
    const float* __restrict__ bm2,
    float* __restrict__ flat_out, float* __restrict__ maskA, float* __restrict__ maskB,
    __half* smem)
{
    __half* s_ch = smem;
    __half* s_wh = smem + CROPH_H;
    float* s_w2 = (float*)(smem + CROPH_H + WSLAB_H);
    float* s_b1 = s_w2 + 64;
    float* s_wy = s_b1 + 64;
    float* s_wx = s_wy + 14;
    int* s_y0 = (int*)(s_wx + 14);
    int* s_y1 = s_y0 + 14;
    int* s_x0 = s_y1 + 14;
    int* s_x1 = s_x0 + 14;

    int lane = tid & 31, wrp = tid >> 5;

    if (tid < 28) {
        int t = tid % 14;
        float tt = (float)t / 13.0f;
        if (tid < 14) {
            float y1n = by1 / 255.0f, y2n = by2 / 255.0f;
            float fy = (y1n + (y2n - y1n) * tt) * 15.0f;
            float y0f = fminf(fmaxf(floorf(fy), 0.f), 15.f);
            int y0 = (int)y0f;
            s_y0[t] = y0; s_y1[t] = min(y0 + 1, 15); s_wy[t] = fy - y0f;
        } else {
            float x1n = bx1 / 255.0f, x2n = bx2 / 255.0f;
            float fx = (x1n + (x2n - x1n) * tt) * 15.0f;
            float x0f = fminf(fmaxf(floorf(fx), 0.f), 15.f);
            int x0 = (int)x0f;
            s_x0[t] = x0; s_x1[t] = min(x0 + 1, 15); s_wx[t] = fx - x0f;
        }
    }
    if (tid >= 32 && tid < 96) {
        int c = tid - 32;
        s_w2[c] = wm2[c];
        s_b1[c] = bm1[c];
    }
    for (int idx = tid; idx < CROPH_H / 2; idx += 256)
        ((unsigned*)s_ch)[idx] = 0u;
    __syncthreads();

    const float4* ft4 = (const float4*)g_featT;
    for (int task = tid; task < 784; task += 256) {
        int cell = task >> 4, c4 = task & 15;
        int py = cell / 7, px = cell - py * 7;
        float4 v[2][2];
#pragma unroll
        for (int dy = 0; dy < 2; dy++)
#pragma unroll
            for (int dx = 0; dx < 2; dx++) {
                int ty = 2 * py + dy, tx = 2 * px + dx;
                int y0 = s_y0[ty], y1 = s_y1[ty], x0 = s_x0[tx], x1 = s_x1[tx];
                float wy = s_wy[ty], wx = s_wx[tx];
                float4 f00 = ft4[(y0 * 16 + x0) * 16 + c4];
                float4 f01 = ft4[(y0 * 16 + x1) * 16 + c4];
                float4 f10 = ft4[(y1 * 16 + x0) * 16 + c4];
                float4 f11 = ft4[(y1 * 16 + x1) * 16 + c4];
                float4 r;
                { float top = f00.x * (1.f - wx) + f01.x * wx;
                  float bot = f10.x * (1.f - wx) + f11.x * wx;
                  r.x = top * (1.f - wy) + bot * wy; }
                { float top = f00.y * (1.f - wx) + f01.y * wx;
                  float bot = f10.y * (1.f - wx) + f11.y * wx;
                  r.y = top * (1.f - wy) + bot * wy; }
                { float top = f00.z * (1.f - wx) + f01.z * wx;
                  float bot = f10.z * (1.f - wx) + f11.z * wx;
                  r.z = top * (1.f - wy) + bot * wy; }
                { float top = f00.w * (1.f - wx) + f01.w * wx;
                  float bot = f10.w * (1.f - wx) + f11.w * wx;
                  r.w = top * (1.f - wy) + bot * wy; }
                v[dy][dx] = r;
                __half2* dst = (__half2*)&s_ch[((ty + 1) * 16 + (tx + 1)) * 72 + c4 * 4];
                dst[0] = __floats2half2_rn(r.x, r.y);
                dst[1] = __floats2half2_rn(r.z, r.w);
            }
        flat_out[(c4 * 4 + 0) * 49 + cell] =
            fmaxf(fmaxf(v[0][0].x, v[0][1].x), fmaxf(v[1][0].x, v[1][1].x));
        flat_out[(c4 * 4 + 1) * 49 + cell] =
            fmaxf(fmaxf(v[0][0].y, v[0][1].y), fmaxf(v[1][0].y, v[1][1].y));
        flat_out[(c4 * 4 + 2) * 49 + cell] =
            fmaxf(fmaxf(v[0][0].z, v[0][1].z), fmaxf(v[1][0].z, v[1][1].z));
        flat_out[(c4 * 4 + 3) * 49 + cell] =
            fmaxf(fmaxf(v[0][0].w, v[0][1].w), fmaxf(v[1][0].w, v[1][1].w));
    }

    int g = lane >> 2, q = lane & 3;
    int pb[2][2];
#pragma unroll
    for (int mt = 0; mt < 2; mt++)
#pragma unroll
        for (int hh = 0; hh < 2; hh++) {
            int p = wrp * 32 + mt * 16 + g + hh * 8;
            if (p < 196) {
                int y = p / 14, xx = p % 14;
                pb[mt][hh] = (y * 16 + xx) * 72;
            } else pb[mt][hh] = 0;
        }

    float c[2][8][4];
#pragma unroll
    for (int mt = 0; mt < 2; mt++)
#pragma unroll
        for (int nt = 0; nt < 8; nt++)
#pragma unroll
            for (int j = 0; j < 4; j++) c[mt][nt][j] = 0.f;

    const unsigned* gwu = (const unsigned*)g_wh;
    for (int slab = 0; slab < 9; slab++) {
        __syncthreads();
        for (int f = tid; f < 2304; f += 256) {
            int oc = f / 36, icu = f - oc * 36;
            ((unsigned*)s_wh)[oc * 36 + icu] =
                (icu < 32) ? gwu[slab * 2048 + oc * 32 + icu] : 0u;
        }
        __syncthreads();
        int ky = slab / 3, kx = slab % 3;
        int off = (ky * 16 + kx) * 72;
#pragma unroll
        for (int kT = 0; kT < 4; kT++) {
            int ab = off + kT * 16 + 2 * q;
            unsigned a[2][4];
#pragma unroll
            for (int mt = 0; mt < 2; mt++) {
                a[mt][0] = *(const unsigned*)&s_ch[pb[mt][0] + ab];
                a[mt][1] = *(const unsigned*)&s_ch[pb[mt][1] + ab];
                a[mt][2] = *(const unsigned*)&s_ch[pb[mt][0] + ab + 8];
                a[mt][3] = *(const unsigned*)&s_ch[pb[mt][1] + ab + 8];
            }
            int bbase = kT * 16 + 2 * q;
#pragma unroll
            for (int nt = 0; nt < 8; nt++) {
                int oc = nt * 8 + g;
                unsigned b0 = *(const unsigned*)&s_wh[oc * 72 + bbase];
                unsigned b1 = *(const unsigned*)&s_wh[oc * 72 + bbase + 8];
                mma_f16(c[0][nt], a[0], b0, b1);
                mma_f16(c[1][nt], a[1], b0, b1);
            }
        }
    }

    float part[2][2] = {{0.f, 0.f}, {0.f, 0.f}};
#pragma unroll
    for (int nt = 0; nt < 8; nt++) {
        int col0 = nt * 8 + q * 2, col1 = col0 + 1;
        float bA = s_b1[col0], bB = s_b1[col1];
        float w20 = s_w2[col0], w21 = s_w2[col1];
#pragma unroll
        for (int mt = 0; mt < 2; mt++) {
            part[mt][0] += fmaxf(c[mt][nt][0] + bA, 0.f) * w20
                         + fmaxf(c[mt][nt][1] + bB, 0.f) * w21;
            part[mt][1] += fmaxf(c[mt][nt][2] + bA, 0.f) * w20
                         + fmaxf(c[mt][nt][3] + bB, 0.f) * w21;
        }
    }
    float b2 = bm2[0];
#pragma unroll
    for (int mt = 0; mt < 2; mt++)
#pragma unroll
        for (int hh = 0; hh < 2; hh++) {
            float v = part[mt][hh];
            v += __shfl_xor_sync(0xffffffffu, v, 1);
            v += __shfl_xor_sync(0xffffffffu, v, 2);
            int p = wrp * 32 + mt * 16 + g + hh * 8;
            if (q == 0 && p < 196) {
                float logit = b2 + v;
                maskA[p] = logit;
                maskB[p] = logit;
            }
        }
}

__global__ void __launch_bounds__(256, 2)
k_roizero(const float* __restrict__ bm1, const float* __restrict__ wm2,
          const float* __restrict__ bm2) {
    extern __shared__ __half smem_h[];
    roi_body(threadIdx.x, 0.f, 0.f, 0.f, 0.f, bm1, wm2, bm2,
             g_flatz, g_maskz, g_maskz, smem_h);
}

__global__ void __launch_bounds__(256, 2)
k_roi(const float* __restrict__ bm1, const float* __restrict__ wm2,
      const float* __restrict__ bm2, float* __restrict__ omask) {
    extern __shared__ __half smem_h[];
    int p = blockIdx.x, tid = threadIdx.x;
    if (!g_valid[p]) {
        float* fo = g_flat + (size_t)p * 3136;
        for (int idx = tid; idx < 784; idx += 256)
            ((float4*)fo)[idx] = ((const float4*)g_flatz)[idx];
        for (int pos = tid; pos < 196; pos += 256) {
            float v = g_maskz[pos];
            omask[(size_t)p * 196 + pos] = v;
            g_masks[(size_t)p * 196 + pos] = v;
        }
        return;
    }
    roi_body(tid, g_props[p * 4], g_props[p * 4 + 1], g_props[p * 4 + 2], g_props[p * 4 + 3],
             bm1, wm2, bm2,
             g_flat + (size_t)p * 3136, omask + (size_t)p * 196,
             g_masks + (size_t)p * 196, smem_h);
}

// ===== split-fp16 GEMM: C = relu(A·B + bias), A fp32 [M,K], B split [N][K] =====
// 256 thr = 8 warps, tile 64x64, k-chunk 32; warp = (m16, n32)
// rows padded to 40 halves (80 B) so 16-byte vector accesses stay aligned
__global__ void __launch_bounds__(256, 2)
k_gemmh(const float* __restrict__ A, const __half* __restrict__ Bh,
        const __half* __restrict__ Bl, const float* __restrict__ bias,
        float* __restrict__ C, int M, int N, int K) {
    __shared__ __half sAh[64][40], sAl[64][40], sBh[64][40], sBl[64][40];
    int tid = threadIdx.x;
    int lane = tid & 31, wrp = tid >> 5;
    int wm = wrp >> 1, wn = wrp & 1;
    int g = lane >> 2, q = lane & 3;
    int bm = blockIdx.y * 64, bn = blockIdx.x * 64;

    float acc[4][4];
#pragma unroll
    for (int nt = 0; nt < 4; nt++)
#pragma unroll
        for (int j = 0; j < 4; j++) acc[nt][j] = 0.f;

    int lr = tid >> 2, lc = (tid & 3) * 8;   // row 0..63, k-offset 0/8/16/24
    int arow = bm + lr;
    bool aok = arow < M;
    const __half* bhrow = Bh + (size_t)(bn + lr) * K;
    const __half* blrow = Bl + (size_t)(bn + lr) * K;

    for (int k0 = 0; k0 < K; k0 += 32) {
        __syncthreads();
        {
            float4 v0 = make_float4(0.f, 0.f, 0.f, 0.f), v1 = v0;
            if (aok) {
                v0 = *(const float4*)&A[(size_t)arow * K + k0 + lc];
                v1 = *(const float4*)&A[(size_t)arow * K + k0 + lc + 4];
            }
            float vf[8] = {v0.x, v0.y, v0.z, v0.w, v1.x, v1.y, v1.z, v1.w};
#pragma unroll
            for (int j = 0; j < 8; j++) {
                __half h = __float2half_rn(vf[j]);
                sAh[lr][lc + j] = h;
                sAl[lr][lc + j] = __float2half_rn(vf[j] - __half2float(h));
            }
        }
        *(uint4*)&sBh[lr][lc] = *(const uint4*)&bhrow[k0 + lc];
        *(uint4*)&sBl[lr][lc] = *(const uint4*)&blrow[k0 + lc];
        __syncthreads();

#pragma unroll
        for (int kT = 0; kT < 2; kT++) {
            int kb = kT * 16 + 2 * q;
            int m0 = wm * 16 + g;
            unsigned ah[4], al[4];
            ah[0] = *(const unsigned*)&sAh[m0][kb];
            ah[1] = *(const unsigned*)&sAh[m0 + 8][kb];
            ah[2] = *(const unsigned*)&sAh[m0][kb + 8];
            ah[3] = *(const unsigned*)&sAh[m0 + 8][kb + 8];
            al[0] = *(const unsigned*)&sAl[m0][kb];
            al[1] = *(const unsigned*)&sAl[m0 + 8][kb];
            al[2] = *(const unsigned*)&sAl[m0][kb + 8];
            al[3] = *(const unsigned*)&sAl[m0 + 8][kb + 8];
#pragma unroll
            for (int nt = 0; nt < 4; nt++) {
                int n = wn * 32 + nt * 8 + g;
                unsigned bh0 = *(const unsigned*)&sBh[n][kb];
                unsigned bh1 = *(const unsigned*)&sBh[n][kb + 8];
                unsigned bl0 = *(const unsigned*)&sBl[n][kb];
                unsigned bl1 = *(const unsigned*)&sBl[n][kb + 8];
                mma_f16(acc[nt], ah, bh0, bh1);
                mma_f16(acc[nt], ah, bl0, bl1);
                mma_f16(acc[nt], al, bh0, bh1);
            }
        }
    }
#pragma unroll
    for (int nt = 0; nt < 4; nt++) {
        int col0 = bn + wn * 32 + nt * 8 + 2 * q;
        float b0 = bias[col0], b1 = bias[col0 + 1];
        int r0 = bm + wm * 16 + g, r1 = r0 + 8;
        if (r0 < M) {
            C[(size_t)r0 * N + col0]     = fmaxf(acc[nt][0] + b0, 0.f);
            C[(size_t)r0 * N + col0 + 1] = fmaxf(acc[nt][1] + b1, 0.f);
        }
        if (r1 < M) {
            C[(size_t)r1 * N + col0]     = fmaxf(acc[nt][2] + b0, 0.f);
            C[(size_t)r1 * N + col0 + 1] = fmaxf(acc[nt][3] + b1, 0.f);
        }
    }
}

// -------- rcnn cls/box heads + fused stage-2 decode --------
__global__ void k_rheads(const float* __restrict__ wrc, const float* __restrict__ brc,
                         const float* __restrict__ wrb, const float* __restrict__ brb,
                         float* __restrict__ o_log, float* __restrict__ o_del,
                         float* __restrict__ dets) {
    __shared__ float s6[6];
    int p = blockIdx.x;
    int w = threadIdx.x >> 5, lane = threadIdx.x & 31;
    const float* hp = g_h2 + (size_t)p * 512;
    float s = 0.f;
    if (w < 2) {
        for (int k = lane; k < 512; k += 32) s += hp[k] * wrc[k * 2 + w];
    } else {
        int j = w - 2;
        for (int k = lane; k < 512; k += 32) s += hp[k] * wrb[k * 4 + j];
    }
    for (int off = 16; off > 0; off >>= 1) s += __shfl_down_sync(0xffffffffu, s, off);
    if (lane == 0) {
        if (w < 2) {
            float v = s + brc[w];
            o_log[p * 2 + w] = v;
            g_rlogits[p * 2 + w] = v;
            s6[w] = v;
        } else {
            int j = w - 2;
            float v = s + brb[j];
            o_del[p * 4 + j] = v;
            g_rdeltas[p * 4 + j] = v;
            s6[w] = v;
        }
    }
    __syncthreads();
    if (threadIdx.x == 0) {
        float l0 = s6[0], l1 = s6[1];
        float m = fmaxf(l0, l1);
        float e0 = expf(l0 - m), e1 = expf(l1 - m);
        float sc = e1 / (e0 + e1);
        g_dscores[p] = sc;
        float x1 = g_props[p * 4], y1 = g_props[p * 4 + 1];
        float x2 = g_props[p * 4 + 2], y2 = g_props[p * 4 + 3];
        float wd = x2 - x1, h = y2 - y1;
        float cx = x1 + 0.5f * wd, cy = y1 + 0.5f * h;
        float d0 = s6[2], d1 = s6[3], d2 = s6[4], d3 = s6[5];
        float ncx = cx + d0 * wd, ncy = cy + d1 * h;
        float nw = wd * expf(d2), nh = h * expf(d3);
        dets[p * 4]     = fminf(fmaxf(ncx - 0.5f * nw, 0.f), 255.f);
        dets[p * 4 + 1] = fminf(fmaxf(ncy - 0.5f * nh, 0.f), 255.f);
        dets[p * 4 + 2] = fminf(fmaxf(ncx + 0.5f * nw, 0.f), 255.f);
        dets[p * 4 + 3] = fminf(fmaxf(ncy + 0.5f * nh, 0.f), 255.f);
        g_s2[p] = g_valid[p] ? sc : -1.0f;
    }
}

// -------- final dets/scores/keep2 + masks (fused) --------
__global__ void k_final(float* __restrict__ o_fdets, float* __restrict__ o_fsc,
                        float* __restrict__ o_keep, float* __restrict__ o_fmsk) {
    __shared__ float s_kf;
    __shared__ int s_oi;
    int r = blockIdx.x, i = threadIdx.x;
    if (i == 0) {
        int o = g_order2[r];
        int k2 = g_keep2a[r] && g_valid[o];
        float kf = k2 ? 1.f : 0.f;
        float4 d = g_sb2[r];
        o_fdets[r * 4]     = k2 ? d.x : 0.f;
        o_fdets[r * 4 + 1] = k2 ? d.y : 0.f;
        o_fdets[r * 4 + 2] = k2 ? d.z : 0.f;
        o_fdets[r * 4 + 3] = k2 ? d.w : 0.f;
        o_fsc[r] = k2 ? g_dscores[o] : 0.f;
        if (o_keep) o_keep[r] = kf;
        s_kf = kf;
        s_oi = o;
    }
    __syncthreads();
    float v = g_masks[(size_t)s_oi * 196 + i];
    float sgm = 1.f / (1.f + expf(-v));
    o_fmsk[(size_t)r * 196 + i] = sgm * s_kf;
}

// ---------------- host ----------------
extern "C" void kernel_launch(void* const* d_in, const int* in_sizes, int n_in,
                              void* d_out, int out_size) {
    const float* x      = (const float*)d_in[0];
    const float* w_bb   = (const float*)d_in[1];
    const float* b_bb   = (const float*)d_in[2];
    const float* w_rpn  = (const float*)d_in[3];
    const float* b_rpn  = (const float*)d_in[4];
    const float* w_cls  = (const float*)d_in[5];
    const float* b_cls  = (const float*)d_in[6];
    const float* w_box  = (const float*)d_in[7];
    const float* b_box  = (const float*)d_in[8];
    const float* w_fc1  = (const float*)d_in[9];
    const float* b_fc1  = (const float*)d_in[10];
    const float* w_fc2  = (const float*)d_in[11];
    const float* b_fc2  = (const float*)d_in[12];
    const float* w_rcls = (const float*)d_in[13];
    const float* b_rcls = (const float*)d_in[14];
    const float* w_rbox = (const float*)d_in[15];
    const float* b_rbox = (const float*)d_in[16];
    const float* w_m1   = (const float*)d_in[17];
    const float* b_m1   = (const float*)d_in[18];
    const float* w_m2   = (const float*)d_in[19];
    const float* b_m2   = (const float*)d_in[20];
    float* out = (float*)d_out;

    const size_t O_RPNL = 0, O_RPND = 4608, O_PROP = 13824, O_ANCH = 21824;
    const size_t O_RLOG = 31040, O_RDEL = 35040, O_RMSK = 43040;
    const size_t O_FDET = 435040, O_FMSK = 443040, O_FSC = 835040, O_KEEP = 837040;

    float *p_scores, *p_s2, *p_flat, *p_h1, *p_h2, *p_dets, *p_boxes;
    int *p_order, *p_order2, *p_keep1, *p_keep2a;
    unsigned long long *p_mask1, *p_mask2;
    __half *p_bh1, *p_bl1, *p_bh2, *p_bl2;
    cudaGetSymbolAddress((void**)&p_scores, g_scores);
    cudaGetSymbolAddress((void**)&p_order, g_order);
    cudaGetSymbolAddress((void**)&p_s2, g_s2);
    cudaGetSymbolAddress((void**)&p_order2, g_order2);
    cudaGetSymbolAddress((void**)&p_flat, g_flat);
    cudaGetSymbolAddress((void**)&p_h1, g_h1);
    cudaGetSymbolAddress((void**)&p_h2, g_h2);
    cudaGetSymbolAddress((void**)&p_dets, g_dets);
    cudaGetSymbolAddress((void**)&p_boxes, g_boxes);
    cudaGetSymbolAddress((void**)&p_keep1, g_keep1);
    cudaGetSymbolAddress((void**)&p_keep2a, g_keep2a);
    cudaGetSymbolAddress((void**)&p_mask1, g_mask1);
    cudaGetSymbolAddress((void**)&p_mask2, g_mask2);
    cudaGetSymbolAddress((void**)&p_bh1, g_bh1);
    cudaGetSymbolAddress((void**)&p_bl1, g_bl1);
    cudaGetSymbolAddress((void**)&p_bh2, g_bh2);
    cudaGetSymbolAddress((void**)&p_bl2, g_bl2);

    cudaFuncSetAttribute(k_roi, cudaFuncAttributeMaxDynamicSharedMemorySize, SMEM_ROI_BYTES);
    cudaFuncSetAttribute(k_roizero, cudaFuncAttributeMaxDynamicSharedMemorySize, SMEM_ROI_BYTES);

    float4* p_sb1; float* p_sa1; float4* p_sb2; float* p_sa2;
    cudaGetSymbolAddress((void**)&p_sb1, g_sb1);
    cudaGetSymbolAddress((void**)&p_sa1, g_sa1);
    cudaGetSymbolAddress((void**)&p_sb2, g_sb2);
    cudaGetSymbolAddress((void**)&p_sa2, g_sa2);

    k_backbone<<<256, 256>>>(x, w_bb, b_bb);
    k_packwh<<<(9 * 64 * 64 + 255) / 256, 256>>>(w_m1);
    k_packw<<<(64 * 64 * 12 + 255) / 256, 256>>>(w_rpn);
    k_packB<<<(3136 * 512 + 255) / 256, 256>>>(w_fc1, p_bh1, p_bl1, 3136, 512);
    k_packB<<<(512 * 512 + 255) / 256, 256>>>(w_fc2, p_bh2, p_bl2, 512, 512);
    k_roizero<<<1, 256, SMEM_ROI_BYTES>>>(b_m1, w_m2, b_m2);
    k_rpnconv<<<256, 256>>>(b_rpn);
    k_heads1<<<18, 128>>>(w_cls, b_cls, w_box, b_box,
                          out + O_RPNL, out + O_RPND, out + O_ANCH);
    k_sort<4096><<<1, 1024>>>(p_scores, NANCH, p_order, p_boxes, p_sb1, p_sa1);
    k_ioumask<NANCH, NW1><<<dim3(NW1, NW1), 64>>>(p_sb1, p_sa1, p_mask1, 0.5f);
    k_nmsreduce<NANCH, NW1><<<1, 32>>>(p_mask1, p_keep1);
    k_select1<<<1, 1024>>>(out + O_PROP);
    k_roi<<<NPROP, 256, SMEM_ROI_BYTES>>>(b_m1, w_m2, b_m2, out + O_RMSK);

    dim3 gfc(8, 32);
    k_gemmh<<<gfc, 256>>>(p_flat, p_bh1, p_bl1, b_fc1, p_h1, NPROP, 512, 3136);
    k_gemmh<<<gfc, 256>>>(p_h1, p_bh2, p_bl2, b_fc2, p_h2, NPROP, 512, 512);
    k_rheads<<<NPROP, 192>>>(w_rcls, b_rcls, w_rbox, b_rbox,
                             out + O_RLOG, out + O_RDEL, p_dets);
    k_sort<2048><<<1, 1024>>>(p_s2, NPROP, p_order2, p_dets, p_sb2, p_sa2);
    k_ioumask<NPROP, NW2><<<dim3(NW2, NW2), 64>>>(p_sb2, p_sa2, p_mask2, 0.3f);
    k_nmsreduce<NPROP, NW2><<<1, 32>>>(p_mask2, p_keep2a);
    float* o_keep = (out_size >= (int)(O_KEEP + NPROP)) ? (out + O_KEEP) : nullptr;
    k_final<<<NPROP, 196>>>(out + O_FDET, out + O_FSC, o_keep, out + O_FMSK);
}

// round 11
// speedup vs baseline: 3.4201x; 1.0474x over previous
#include <cuda_runtime.h>
#include <cuda_fp16.h>
#include <math.h>

#define NANCH 2304
#define NPROP 2000
#define NW1 36
#define NW2 32

// ---------------- scratch (device globals; no allocation) ----------------
__device__ float g_feat[64 * 256];
__device__ float g_featT[256 * 64];
__device__ float g_featP[64 * 18 * 18];
__device__ float g_hrpn[64 * 256];
__device__ float g_scores[NANCH];
__device__ float g_boxes[NANCH * 4];
__device__ int   g_order[NANCH];
__device__ float g_props[NPROP * 4];
__device__ int   g_valid[NPROP];
__device__ float g_flat[NPROP * 3136];
__device__ float g_h1[NPROP * 512];
__device__ float g_h2[NPROP * 512];
__device__ float g_rlogits[NPROP * 2];
__device__ float g_rdeltas[NPROP * 4];
__device__ float g_dscores[NPROP];
__device__ float g_s2[NPROP];
__device__ int   g_order2[NPROP];
__device__ float g_masks[NPROP * 196];
__device__ float g_dets[NPROP * 4];
__device__ unsigned short g_wh[9 * 64 * 64];     // mask-conv weights fp16 [slab][oc][ic]
__device__ float g_wpack[64 * 64 * 12];          // rpn-conv weights float4-aligned
__device__ float g_flatz[3136];
__device__ float g_maskz[196];
// split-fp16 FC weights, transposed [N][K]
__device__ __half g_bh1[512 * 3136];
__device__ __half g_bl1[512 * 3136];
__device__ __half g_bh2[512 * 512];
__device__ __half g_bl2[512 * 512];
// NMS scratch
__device__ float4 g_sb1[NANCH];
__device__ float  g_sa1[NANCH];
__device__ unsigned long long g_mask1[(size_t)NANCH * NW1];
__device__ int    g_keep1[NANCH];
__device__ float4 g_sb2[NPROP];
__device__ float  g_sa2[NPROP];
__device__ unsigned long long g_mask2[(size_t)NPROP * NW2];
__device__ int    g_keep2a[NPROP];

__device__ __forceinline__ void mma_f16(float* c, const unsigned* a,
                                        unsigned b0, unsigned b1) {
    asm volatile(
        "mma.sync.aligned.m16n8k16.row.col.f32.f16.f16.f32 "
        "{%0,%1,%2,%3},{%4,%5,%6,%7},{%8,%9},{%0,%1,%2,%3};"
        : "+f"(c[0]), "+f"(c[1]), "+f"(c[2]), "+f"(c[3])
        : "r"(a[0]), "r"(a[1]), "r"(a[2]), "r"(a[3]), "r"(b0), "r"(b1));
}

// ---------------- backbone ----------------
__global__ void k_backbone(const float* __restrict__ x, const float* __restrict__ w,
                           const float* __restrict__ b) {
    __shared__ float patch[768];
    __shared__ float part[256];
    int pos = blockIdx.x;
    int h = pos >> 4, wq = pos & 15;
    int tid = threadIdx.x;
    for (int k = tid; k < 768; k += 256) {
        int ic = k >> 8, r = k & 255, iy = r >> 4, ix = r & 15;
        patch[k] = x[ic * 65536 + (h * 16 + iy) * 256 + (wq * 16 + ix)];
    }
    __syncthreads();
    int oc = tid & 63, ch = tid >> 6;
    const float* wp = w + oc * 768 + ch * 192;
    const float* pp = patch + ch * 192;
    float a0 = 0.f, a1 = 0.f;
#pragma unroll 8
    for (int k = 0; k < 192; k += 2) { a0 += pp[k] * wp[k]; a1 += pp[k + 1] * wp[k + 1]; }
    part[tid] = a0 + a1;
    __syncthreads();
    if (tid < 64) {
        float s = b[tid] + part[tid] + part[tid + 64] + part[tid + 128] + part[tid + 192];
        float v = fmaxf(s, 0.f);
        g_feat[tid * 256 + pos] = v;
        g_featT[pos * 64 + tid] = v;
        g_featP[tid * 324 + (h + 1) * 18 + (wq + 1)] = v;
    }
}

// -------- pack rpn weights [oc][ic][9] -> [oc][ic][12] (float4-aligned) ----
__global__ void k_packw(const float* __restrict__ w) {
    int i = blockIdx.x * blockDim.x + threadIdx.x;
    if (i >= 64 * 64 * 12) return;
    int pair = i / 12, q = i % 12;
    g_wpack[i] = (q < 9) ? w[pair * 9 + q] : 0.f;
}

// ---------------- rpn conv 3x3 SAME, relu (packed float4 weights) ----------------
__global__ void k_rpnconv(const float* __restrict__ b) {
    __shared__ float s_f[576];
    __shared__ float part[256];
    int pos = blockIdx.x;
    int y = pos >> 4, xq = pos & 15;
    int tid = threadIdx.x;
    for (int k = tid; k < 576; k += 256) {
        int ic = k / 9, r = k % 9, ky = r / 3, kx = r % 3;
        s_f[k] = g_featP[ic * 324 + (y + ky) * 18 + (xq + kx)];
    }
    __syncthreads();
    int oc = tid & 63, ch = tid >> 6;
    const float4* wp4 = (const float4*)g_wpack;
    float acc0 = 0.f, acc1 = 0.f;
    for (int icl = 0; icl < 16; icl += 2) {
        int ic = ch * 16 + icl;
        float4 A0 = wp4[(oc * 64 + ic) * 3], A1 = wp4[(oc * 64 + ic) * 3 + 1],
               A2 = wp4[(oc * 64 + ic) * 3 + 2];
        float4 B0 = wp4[(oc * 64 + ic + 1) * 3], B1 = wp4[(oc * 64 + ic + 1) * 3 + 1],
               B2 = wp4[(oc * 64 + ic + 1) * 3 + 2];
        float wAr[9] = {A0.x, A0.y, A0.z, A0.w, A1.x, A1.y, A1.z, A1.w, A2.x};
        float wBr[9] = {B0.x, B0.y, B0.z, B0.w, B1.x, B1.y, B1.z, B1.w, B2.x};
        const float* f0 = s_f + ic * 9;
#pragma unroll
        for (int k = 0; k < 9; k++) {
            acc0 += f0[k] * wAr[k];
            acc1 += f0[9 + k] * wBr[k];
        }
    }
    part[tid] = acc0 + acc1;
    __syncthreads();
    if (tid < 64) {
        float s = b[tid] + part[tid] + part[tid + 64] + part[tid + 128] + part[tid + 192];
        g_hrpn[tid * 256 + pos] = fmaxf(s, 0.f);
    }
}

// -------- rpn heads (1x1), anchors, softmax score, decode, clip --------
__global__ void k_heads1(const float* __restrict__ wc, const float* __restrict__ bc,
                         const float* __restrict__ wb, const float* __restrict__ bb,
                         float* __restrict__ o_logits, float* __restrict__ o_deltas,
                         float* __restrict__ o_anch) {
    int i = blockIdx.x * blockDim.x + threadIdx.x;
    if (i >= NANCH) return;
    int cell = i / 9, a = i % 9;
    float l0 = bc[a * 2], l1 = bc[a * 2 + 1];
    float d0 = bb[a * 4], d1 = bb[a * 4 + 1], d2 = bb[a * 4 + 2], d3 = bb[a * 4 + 3];
    for (int ic = 0; ic < 64; ic++) {
        float f = g_hrpn[ic * 256 + cell];
        l0 += f * wc[(a * 2) * 64 + ic];
        l1 += f * wc[(a * 2 + 1) * 64 + ic];
        d0 += f * wb[(a * 4) * 64 + ic];
        d1 += f * wb[(a * 4 + 1) * 64 + ic];
        d2 += f * wb[(a * 4 + 2) * 64 + ic];
        d3 += f * wb[(a * 4 + 3) * 64 + ic];
    }
    o_logits[i * 2] = l0; o_logits[i * 2 + 1] = l1;
    o_deltas[i * 4] = d0; o_deltas[i * 4 + 1] = d1;
    o_deltas[i * 4 + 2] = d2; o_deltas[i * 4 + 3] = d3;
    float m = fmaxf(l0, l1);
    float e0 = expf(l0 - m), e1 = expf(l1 - m);
    g_scores[i] = e1 / (e0 + e1);

    const float S[3] = {32.f, 64.f, 128.f};
    const float R[3] = {0.5f, 1.f, 2.f};
    int h = cell >> 4, wq = cell & 15;
    float s = S[a / 3], r = R[a % 3];
    float ws = s * sqrtf(r), hs = s / sqrtf(r);
    float cx = (wq + 0.5f) * 16.f, cy = (h + 0.5f) * 16.f;
    float ax1 = cx - ws * 0.5f, ay1 = cy - hs * 0.5f;
    float ax2 = cx + ws * 0.5f, ay2 = cy + hs * 0.5f;
    o_anch[i * 4] = ax1; o_anch[i * 4 + 1] = ay1;
    o_anch[i * 4 + 2] = ax2; o_anch[i * 4 + 3] = ay2;

    float aw = ax2 - ax1, ah = ay2 - ay1;
    float acx = ax1 + 0.5f * aw, acy = ay1 + 0.5f * ah;
    float ncx = acx + d0 * aw, ncy = acy + d1 * ah;
    float nw = aw * expf(d2), nh = ah * expf(d3);
    g_boxes[i * 4]     = fminf(fmaxf(ncx - 0.5f * nw, 0.f), 255.f);
    g_boxes[i * 4 + 1] = fminf(fmaxf(ncy - 0.5f * nh, 0.f), 255.f);
    g_boxes[i * 4 + 2] = fminf(fmaxf(ncx + 0.5f * nw, 0.f), 255.f);
    g_boxes[i * 4 + 3] = fminf(fmaxf(ncy + 0.5f * nh, 0.f), 255.f);
}

// -------- pack mask-conv weights fp16 [slab][oc][ic] ----
__global__ void k_packwh(const float* __restrict__ w) {
    int i = blockIdx.x * blockDim.x + threadIdx.x;
    if (i >= 9 * 64 * 64) return;
    int slab = i >> 12, r = i & 4095, oc = r >> 6, ic = r & 63;
    g_wh[i] = __half_as_ushort(__float2half_rn(w[oc * 576 + ic * 9 + slab]));
}

// -------- tiled transpose pack: w[K][N] -> Bh/Bl [N][K] split-fp16 ----
__global__ void k_packBt(const float* __restrict__ w, __half* __restrict__ Bh,
                         __half* __restrict__ Bl, int K, int N) {
    __shared__ float tile[32][33];
    int kb = blockIdx.y * 32, nb = blockIdx.x * 32;
    int tx = threadIdx.x, ty = threadIdx.y;   // 32 x 8
#pragma unroll
    for (int i = 0; i < 32; i += 8) {
        int k = kb + ty + i, n = nb + tx;
        tile[ty + i][tx] = (k < K && n < N) ? w[(size_t)k * N + n] : 0.f;
    }
    __syncthreads();
#pragma unroll
    for (int i = 0; i < 32; i += 8) {
        int n = nb + ty + i, k = kb + tx;
        if (n < N && k < K) {
            float x = tile[tx][ty + i];
            __half h = __float2half_rn(x);
            Bh[(size_t)n * K + k] = h;
            Bl[(size_t)n * K + k] = __float2half_rn(x - __half2float(h));
        }
    }
}

// -------- single-block bitonic sort + fused box gather --------
template <int SIZE>
__global__ void k_sort(const float* __restrict__ sc, int n, int* __restrict__ ord,
                       const float* __restrict__ boxes, float4* __restrict__ sb,
                       float* __restrict__ sa) {
    __shared__ unsigned long long k[SIZE];
    int tid = threadIdx.x;
    for (int i = tid; i < SIZE; i += 1024) {
        if (i < n) {
            unsigned u = __float_as_uint(sc[i]);
            unsigned o = (u & 0x80000000u) ? ~u : (u | 0x80000000u);
            k[i] = ((unsigned long long)(~o) << 32) | (unsigned)i;
        } else k[i] = 0xFFFFFFFFFFFFFFFFULL;
    }
    __syncthreads();
    for (int kk = 2; kk <= SIZE; kk <<= 1) {
        for (int j = kk >> 1; j > 0; j >>= 1) {
            for (int i = tid; i < SIZE; i += 1024) {
                int ixj = i ^ j;
                if (ixj > i) {
                    bool up = ((i & kk) == 0);
                    unsigned long long a = k[i], b = k[ixj];
                    if ((a > b) == up) { k[i] = b; k[ixj] = a; }
                }
            }
            __syncthreads();
        }
    }
    for (int i = tid; i < n; i += 1024) {
        int idx = (int)(k[i] & 0xFFFFFFFFu);
        ord[i] = idx;
        float4 b = *(const float4*)&boxes[idx * 4];
        sb[i] = b;
        sa[i] = fmaxf(b.z - b.x, 0.f) * fmaxf(b.w - b.y, 0.f);
    }
}

// -------- IoU bitmask matrix --------
template <int N, int NW>
__global__ void k_ioumask(const float4* __restrict__ sb, const float* __restrict__ sa,
                          unsigned long long* __restrict__ mask, float thr) {
    __shared__ float4 cbx[64];
    __shared__ float car[64];
    int rb = blockIdx.y, cb = blockIdx.x;
    int t = threadIdx.x;
    int j0 = cb * 64;
    if (j0 + t < N) { cbx[t] = sb[j0 + t]; car[t] = sa[j0 + t]; }
    __syncthreads();
    int i = rb * 64 + t;
    if (i >= N) return;
    float4 bi = sb[i];
    float ai = sa[i];
    unsigned long long m = 0;
    int jmax = min(64, N - j0);
    for (int jj = 0; jj < jmax; jj++) {
        int j = j0 + jj;
        if (j <= i) continue;
        float xx1 = fmaxf(bi.x, cbx[jj].x), yy1 = fmaxf(bi.y, cbx[jj].y);
        float xx2 = fminf(bi.z, cbx[jj].z), yy2 = fminf(bi.w, cbx[jj].w);
        float inter = fmaxf(xx2 - xx1, 0.f) * fmaxf(yy2 - yy1, 0.f);
        float iou = inter / (ai + car[jj] - inter + 1e-8f);
        if (iou > thr) m |= 1ULL << jj;
    }
    mask[(size_t)i * NW + cb] = m;
}

// -------- chunked exact greedy reduce --------
template <int N, int NW>
__global__ void k_nmsreduce(const unsigned long long* __restrict__ mask,
                            int* __restrict__ keep) {
    __shared__ unsigned long long s_blk[64];
    int lane = threadIdx.x;
    unsigned long long remv0 = 0ULL, remv1 = 0ULL;
    const int NC = (N + 63) / 64;
    for (int cb = 0; cb < NC; cb++) {
        int j0 = cb * 64;
        int jmax = min(64, N - j0);
        for (int t = lane; t < jmax; t += 32)
            s_blk[t] = mask[(size_t)(j0 + t) * NW + cb];
        __syncwarp();
        int owner = cb & 31;
        unsigned long long r = __shfl_sync(0xffffffffu, (cb < 32) ? remv0 : remv1, owner);
        unsigned long long kept = 0ULL;
        if (lane == 0) {
#pragma unroll 4
            for (int jj = 0; jj < jmax; jj++) {
                if (!((r >> jj) & 1ULL)) {
                    kept |= 1ULL << jj;
                    r |= s_blk[jj];
                }
            }
        }
        kept = __shfl_sync(0xffffffffu, kept, 0);
        r = __shfl_sync(0xffffffffu, r, 0);
        if (lane == owner) { if (cb < 32) remv0 = r; else remv1 = r; }
        for (int t = lane; t < jmax; t += 32)
            keep[j0 + t] = (int)((kept >> t) & 1ULL);
        int w1 = lane, w2 = lane + 32;
        bool u1 = (w1 > cb) && (w1 < NW), u2 = (w2 > cb) && (w2 < NW);
        for (int jj = 0; jj < jmax; jj++) {
            if ((kept >> jj) & 1ULL) {
                const unsigned long long* row = mask + (size_t)(j0 + jj) * NW;
                if (u1) remv0 |= row[w1];
                if (u2) remv1 |= row[w2];
            }
        }
        __syncwarp();
    }
}

// -------- stable kept-first selection --------
__global__ void k_select1(float* __restrict__ o_props) {
    __shared__ int s_src[NPROP];
    int tid = threadIdx.x;
    if (tid < 32) {
        const int CH = NANCH / 32;
        int beg = tid * CH, end = beg + CH;
        int cnt = 0;
        for (int i = beg; i < end; i++) cnt += g_keep1[i];
        int xsc = cnt;
        for (int off = 1; off < 32; off <<= 1) {
            int v = __shfl_up_sync(0xffffffffu, xsc, off);
            if (tid >= off) xsc += v;
        }
        int excl = xsc - cnt;
        int total = __shfl_sync(0xffffffffu, xsc, 31);
        int kpos = excl;
        int npos = total + (beg - excl);
        for (int i = beg; i < end; i++) {
            int pos = g_keep1[i] ? kpos++ : npos++;
            if (pos < NPROP) s_src[pos] = i;
        }
    }
    __syncthreads();
    for (int p = tid; p < NPROP; p += 1024) {
        int i = s_src[p];
        int v = g_keep1[i];
        float4 bb = g_sb1[i];
        float px1 = v ? bb.x : 0.f, py1 = v ? bb.y : 0.f;
        float px2 = v ? bb.z : 0.f, py2 = v ? bb.w : 0.f;
        g_props[p * 4] = px1; g_props[p * 4 + 1] = py1;
        g_props[p * 4 + 2] = px2; g_props[p * 4 + 3] = py2;
        o_props[p * 4] = px1; o_props[p * 4 + 1] = py1;
        o_props[p * 4 + 2] = px2; o_props[p * 4 + 3] = py2;
        g_valid[p] = v;
    }
}

// ===================== ROI body: fp16 MMA implicit GEMM =====================
#define CROPH_H (16 * 16 * 72)
#define WSLAB_H (64 * 72)
#define SMEM_ROI_BYTES (CROPH_H * 2 + WSLAB_H * 2 + (64 + 64 + 28) * 4 + 56 * 4 + 16)

__device__ __forceinline__ void roi_body(
    int tid, float bx1, float by1, float bx2, float by2,
    const float* __restrict__ bm1, const float* __restrict__ wm2,
    const float* __restrict__ bm2,
    float* __restrict__ flat_out, float* __restrict__ maskA, float* __restrict__ maskB,
    __half* smem)
{
    __half* s_ch = smem;
    __half* s_wh = smem + CROPH_H;
    float* s_w2 = (float*)(smem + CROPH_H + WSLAB_H);
    float* s_b1 = s_w2 + 64;
    float* s_wy = s_b1 + 64;
    float* s_wx = s_wy + 14;
    int* s_y0 = (int*)(s_wx + 14);
    int* s_y1 = s_y0 + 14;
    int* s_x0 = s_y1 + 14;
    int* s_x1 = s_x0 + 14;

    int lane = tid & 31, wrp = tid >> 5;

    if (tid < 28) {
        int t = tid % 14;
        float tt = (float)t / 13.0f;
        if (tid < 14) {
            float y1n = by1 / 255.0f, y2n = by2 / 255.0f;
            float fy = (y1n + (y2n - y1n) * tt) * 15.0f;
            float y0f = fminf(fmaxf(floorf(fy), 0.f), 15.f);
            int y0 = (int)y0f;
            s_y0[t] = y0; s_y1[t] = min(y0 + 1, 15); s_wy[t] = fy - y0f;
        } else {
            float x1n = bx1 / 255.0f, x2n = bx2 / 255.0f;
            float fx = (x1n + (x2n - x1n) * tt) * 15.0f;
            float x0f = fminf(fmaxf(floorf(fx), 0.f), 15.f);
            int x0 = (int)x0f;
            s_x0[t] = x0; s_x1[t] = min(x0 + 1, 15); s_wx[t] = fx - x0f;
        }
    }
    if (tid >= 32 && tid < 96) {
        int c = tid - 32;
        s_w2[c] = wm2[c];
        s_b1[c] = bm1[c];
    }
    for (int idx = tid; idx < CROPH_H / 2; idx += 256)
        ((unsigned*)s_ch)[idx] = 0u;
    __syncthreads();

    const float4* ft4 = (const float4*)g_featT;
    for (int task = tid; task < 784; task += 256) {
        int cell = task >> 4, c4 = task & 15;
        int py = cell / 7, px = cell - py * 7;
        float4 v[2][2];
#pragma unroll
        for (int dy = 0; dy < 2; dy++)
#pragma unroll
            for (int dx = 0; dx < 2; dx++) {
                int ty = 2 * py + dy, tx = 2 * px + dx;
                int y0 = s_y0[ty], y1 = s_y1[ty], x0 = s_x0[tx], x1 = s_x1[tx];
                float wy = s_wy[ty], wx = s_wx[tx];
                float4 f00 = ft4[(y0 * 16 + x0) * 16 + c4];
                float4 f01 = ft4[(y0 * 16 + x1) * 16 + c4];
                float4 f10 = ft4[(y1 * 16 + x0) * 16 + c4];
                float4 f11 = ft4[(y1 * 16 + x1) * 16 + c4];
                float4 r;
                { float top = f00.x * (1.f - wx) + f01.x * wx;
                  float bot = f10.x * (1.f - wx) + f11.x * wx;
                  r.x = top * (1.f - wy) + bot * wy; }
                { float top = f00.y * (1.f - wx) + f01.y * wx;
                  float bot = f10.y * (1.f - wx) + f11.y * wx;
                  r.y = top * (1.f - wy) + bot * wy; }
                { float top = f00.z * (1.f - wx) + f01.z * wx;
                  float bot = f10.z * (1.f - wx) + f11.z * wx;
                  r.z = top * (1.f - wy) + bot * wy; }
                { float top = f00.w * (1.f - wx) + f01.w * wx;
                  float bot = f10.w * (1.f - wx) + f11.w * wx;
                  r.w = top * (1.f - wy) + bot * wy; }
                v[dy][dx] = r;
                __half2* dst = (__half2*)&s_ch[((ty + 1) * 16 + (tx + 1)) * 72 + c4 * 4];
                dst[0] = __floats2half2_rn(r.x, r.y);
                dst[1] = __floats2half2_rn(r.z, r.w);
            }
        flat_out[(c4 * 4 + 0) * 49 + cell] =
            fmaxf(fmaxf(v[0][0].x, v[0][1].x), fmaxf(v[1][0].x, v[1][1].x));
        flat_out[(c4 * 4 + 1) * 49 + cell] =
            fmaxf(fmaxf(v[0][0].y, v[0][1].y), fmaxf(v[1][0].y, v[1][1].y));
        flat_out[(c4 * 4 + 2) * 49 + cell] =
            fmaxf(fmaxf(v[0][0].z, v[0][1].z), fmaxf(v[1][0].z, v[1][1].z));
        flat_out[(c4 * 4 + 3) * 49 + cell] =
            fmaxf(fmaxf(v[0][0].w, v[0][1].w), fmaxf(v[1][0].w, v[1][1].w));
    }

    int g = lane >> 2, q = lane & 3;
    int pb[2][2];
#pragma unroll
    for (int mt = 0; mt < 2; mt++)
#pragma unroll
        for (int hh = 0; hh < 2; hh++) {
            int p = wrp * 32 + mt * 16 + g + hh * 8;
            if (p < 196) {
                int y = p / 14, xx = p % 14;
                pb[mt][hh] = (y * 16 + xx) * 72;
            } else pb[mt][hh] = 0;
        }

    float c[2][8][4];
#pragma unroll
    for (int mt = 0; mt < 2; mt++)
#pragma unroll
        for (int nt = 0; nt < 8; nt++)
#pragma unroll
            for (int j = 0; j < 4; j++) c[mt][nt][j] = 0.f;

    const unsigned* gwu = (const unsigned*)g_wh;
    for (int slab = 0; slab < 9; slab++) {
        __syncthreads();
        for (int f = tid; f < 2304; f += 256) {
            int oc = f / 36, icu = f - oc * 36;
            ((unsigned*)s_wh)[oc * 36 + icu] =
                (icu < 32) ? gwu[slab * 2048 + oc * 32 + icu] : 0u;
        }
        __syncthreads();
        int ky = slab / 3, kx = slab % 3;
        int off = (ky * 16 + kx) * 72;
#pragma unroll
        for (int kT = 0; kT < 4; kT++) {
            int ab = off + kT * 16 + 2 * q;
            unsigned a[2][4];
#pragma unroll
            for (int mt = 0; mt < 2; mt++) {
                a[mt][0] = *(const unsigned*)&s_ch[pb[mt][0] + ab];
                a[mt][1] = *(const unsigned*)&s_ch[pb[mt][1] + ab];
                a[mt][2] = *(const unsigned*)&s_ch[pb[mt][0] + ab + 8];
                a[mt][3] = *(const unsigned*)&s_ch[pb[mt][1] + ab + 8];
            }
            int bbase = kT * 16 + 2 * q;
#pragma unroll
            for (int nt = 0; nt < 8; nt++) {
                int oc = nt * 8 + g;
                unsigned b0 = *(const unsigned*)&s_wh[oc * 72 + bbase];
                unsigned b1 = *(const unsigned*)&s_wh[oc * 72 + bbase + 8];
                mma_f16(c[0][nt], a[0], b0, b1);
                mma_f16(c[1][nt], a[1], b0, b1);
            }
        }
    }

    float part[2][2] = {{0.f, 0.f}, {0.f, 0.f}};
#pragma unroll
    for (int nt = 0; nt < 8; nt++) {
        int col0 = nt * 8 + q * 2, col1 = col0 + 1;
        float bA = s_b1[col0], bB = s_b1[col1];
        float w20 = s_w2[col0], w21 = s_w2[col1];
#pragma unroll
        for (int mt = 0; mt < 2; mt++) {
            part[mt][0] += fmaxf(c[mt][nt][0] + bA, 0.f) * w20
                         + fmaxf(c[mt][nt][1] + bB, 0.f) * w21;
            part[mt][1] += fmaxf(c[mt][nt][2] + bA, 0.f) * w20
                         + fmaxf(c[mt][nt][3] + bB, 0.f) * w21;
        }
    }
    float b2 = bm2[0];
#pragma unroll
    for (int mt = 0; mt < 2; mt++)
#pragma unroll
        for (int hh = 0; hh < 2; hh++) {
            float v = part[mt][hh];
            v += __shfl_xor_sync(0xffffffffu, v, 1);
            v += __shfl_xor_sync(0xffffffffu, v, 2);
            int p = wrp * 32 + mt * 16 + g + hh * 8;
            if (q == 0 && p < 196) {
                float logit = b2 + v;
                maskA[p] = logit;
                maskB[p] = logit;
            }
        }
}

__global__ void __launch_bounds__(256, 2)
k_roizero(const float* __restrict__ bm1, const float* __restrict__ wm2,
          const float* __restrict__ bm2) {
    extern __shared__ __half smem_h[];
    roi_body(threadIdx.x, 0.f, 0.f, 0.f, 0.f, bm1, wm2, bm2,
             g_flatz, g_maskz, g_maskz, smem_h);
}

__global__ void __launch_bounds__(256, 2)
k_roi(const float* __restrict__ bm1, const float* __restrict__ wm2,
      const float* __restrict__ bm2, float* __restrict__ omask) {
    extern __shared__ __half smem_h[];
    int p = blockIdx.x, tid = threadIdx.x;
    if (!g_valid[p]) {
        float* fo = g_flat + (size_t)p * 3136;
        for (int idx = tid; idx < 784; idx += 256)
            ((float4*)fo)[idx] = ((const float4*)g_flatz)[idx];
        for (int pos = tid; pos < 196; pos += 256) {
            float v = g_maskz[pos];
            omask[(size_t)p * 196 + pos] = v;
            g_masks[(size_t)p * 196 + pos] = v;
        }
        return;
    }
    roi_body(tid, g_props[p * 4], g_props[p * 4 + 1], g_props[p * 4 + 2], g_props[p * 4 + 3],
             bm1, wm2, bm2,
             g_flat + (size_t)p * 3136, omask + (size_t)p * 196,
             g_masks + (size_t)p * 196, smem_h);
}

// ===== split-fp16 GEMM, double-buffered: C = relu(A·B + bias) =====
// 256 thr = 8 warps, tile 64x64, k-chunk 32; warp = (m16, n32); 1 sync/iter
__global__ void __launch_bounds__(256, 2)
k_gemmh(const float* __restrict__ A, const __half* __restrict__ Bh,
        const __half* __restrict__ Bl, const float* __restrict__ bias,
        float* __restrict__ C, int M, int N, int K) {
    __shared__ __half sAh[2][64][40], sAl[2][64][40], sBh[2][64][40], sBl[2][64][40];
    int tid = threadIdx.x;
    int lane = tid & 31, wrp = tid >> 5;
    int wm = wrp >> 1, wn = wrp & 1;
    int g = lane >> 2, q = lane & 3;
    int bm = blockIdx.y * 64, bn = blockIdx.x * 64;

    float acc[4][4];
#pragma unroll
    for (int nt = 0; nt < 4; nt++)
#pragma unroll
        for (int j = 0; j < 4; j++) acc[nt][j] = 0.f;

    int lr = tid >> 2, lc = (tid & 3) * 8;
    int arow = bm + lr;
    bool aok = arow < M;
    const __half* bhrow = Bh + (size_t)(bn + lr) * K;
    const __half* blrow = Bl + (size_t)(bn + lr) * K;
    const int nk = K / 32;

    // fill stage 0
    {
        float4 v0 = make_float4(0.f, 0.f, 0.f, 0.f), v1 = v0;
        if (aok) {
            v0 = *(const float4*)&A[(size_t)arow * K + lc];
            v1 = *(const float4*)&A[(size_t)arow * K + lc + 4];
        }
        float vf[8] = {v0.x, v0.y, v0.z, v0.w, v1.x, v1.y, v1.z, v1.w};
#pragma unroll
        for (int j = 0; j < 8; j++) {
            __half h = __float2half_rn(vf[j]);
            sAh[0][lr][lc + j] = h;
            sAl[0][lr][lc + j] = __float2half_rn(vf[j] - __half2float(h));
        }
        *(uint4*)&sBh[0][lr][lc] = *(const uint4*)&bhrow[lc];
        *(uint4*)&sBl[0][lr][lc] = *(const uint4*)&blrow[lc];
    }
    __syncthreads();

    for (int t = 0; t < nk; t++) {
        int cur = t & 1, nxt = cur ^ 1;
        // prefetch next chunk to registers (overlaps with MMA below)
        float4 v0, v1;
        uint4 wbh, wbl;
        bool havenext = (t + 1 < nk);
        if (havenext) {
            int k0 = (t + 1) * 32;
            v0 = make_float4(0.f, 0.f, 0.f, 0.f); v1 = v0;
            if (aok) {
                v0 = *(const float4*)&A[(size_t)arow * K + k0 + lc];
                v1 = *(const float4*)&A[(size_t)arow * K + k0 + lc + 4];
            }
            wbh = *(const uint4*)&bhrow[k0 + lc];
            wbl = *(const uint4*)&blrow[k0 + lc];
        }
        // compute current stage
#pragma unroll
        for (int kT = 0; kT < 2; kT++) {
            int kb = kT * 16 + 2 * q;
            int m0 = wm * 16 + g;
            unsigned ah[4], al[4];
            ah[0] = *(const unsigned*)&sAh[cur][m0][kb];
            ah[1] = *(const unsigned*)&sAh[cur][m0 + 8][kb];
            ah[2] = *(const unsigned*)&sAh[cur][m0][kb + 8];
            ah[3] = *(const unsigned*)&sAh[cur][m0 + 8][kb + 8];
            al[0] = *(const unsigned*)&sAl[cur][m0][kb];
            al[1] = *(const unsigned*)&sAl[cur][m0 + 8][kb];
            al[2] = *(const unsigned*)&sAl[cur][m0][kb + 8];
            al[3] = *(const unsigned*)&sAl[cur][m0 + 8][kb + 8];
#pragma unroll
            for (int nt = 0; nt < 4; nt++) {
                int n = wn * 32 + nt * 8 + g;
                unsigned bh0 = *(const unsigned*)&sBh[cur][n][kb];
                unsigned bh1 = *(const unsigned*)&sBh[cur][n][kb + 8];
                unsigned bl0 = *(const unsigned*)&sBl[cur][n][kb];
                unsigned bl1 = *(const unsigned*)&sBl[cur][n][kb + 8];
                mma_f16(acc[nt], ah, bh0, bh1);
                mma_f16(acc[nt], ah, bl0, bl1);
                mma_f16(acc[nt], al, bh0, bh1);
            }
        }
        // store prefetched chunk to other stage
        if (havenext) {
            float vf[8] = {v0.x, v0.y, v0.z, v0.w, v1.x, v1.y, v1.z, v1.w};
#pragma unroll
            for (int j = 0; j < 8; j++) {
                __half h = __float2half_rn(vf[j]);
                sAh[nxt][lr][lc + j] = h;
                sAl[nxt][lr][lc + j] = __float2half_rn(vf[j] - __half2float(h));
            }
            *(uint4*)&sBh[nxt][lr][lc] = wbh;
            *(uint4*)&sBl[nxt][lr][lc] = wbl;
        }
        __syncthreads();
    }
#pragma unroll
    for (int nt = 0; nt < 4; nt++) {
        int col0 = bn + wn * 32 + nt * 8 + 2 * q;
        float b0 = bias[col0], b1 = bias[col0 + 1];
        int r0 = bm + wm * 16 + g, r1 = r0 + 8;
        if (r0 < M) {
            C[(size_t)r0 * N + col0]     = fmaxf(acc[nt][0] + b0, 0.f);
            C[(size_t)r0 * N + col0 + 1] = fmaxf(acc[nt][1] + b1, 0.f);
        }
        if (r1 < M) {
            C[(size_t)r1 * N + col0]     = fmaxf(acc[nt][2] + b0, 0.f);
            C[(size_t)r1 * N + col0 + 1] = fmaxf(acc[nt][3] + b1, 0.f);
        }
    }
}

// -------- rcnn cls/box heads + fused stage-2 decode --------
__global__ void k_rheads(const float* __restrict__ wrc, const float* __restrict__ brc,
                         const float* __restrict__ wrb, const float* __restrict__ brb,
                         float* __restrict__ o_log, float* __restrict__ o_del,
                         float* __restrict__ dets) {
    __shared__ float s6[6];
    int p = blockIdx.x;
    int w = threadIdx.x >> 5, lane = threadIdx.x & 31;
    const float* hp = g_h2 + (size_t)p * 512;
    float s = 0.f;
    if (w < 2) {
        for (int k = lane; k < 512; k += 32) s += hp[k] * wrc[k * 2 + w];
    } else {
        int j = w - 2;
        for (int k = lane; k < 512; k += 32) s += hp[k] * wrb[k * 4 + j];
    }
    for (int off = 16; off > 0; off >>= 1) s += __shfl_down_sync(0xffffffffu, s, off);
    if (lane == 0) {
        if (w < 2) {
            float v = s + brc[w];
            o_log[p * 2 + w] = v;
            g_rlogits[p * 2 + w] = v;
            s6[w] = v;
        } else {
            int j = w - 2;
            float v = s + brb[j];
            o_del[p * 4 + j] = v;
            g_rdeltas[p * 4 + j] = v;
            s6[w] = v;
        }
    }
    __syncthreads();
    if (threadIdx.x == 0) {
        float l0 = s6[0], l1 = s6[1];
        float m = fmaxf(l0, l1);
        float e0 = expf(l0 - m), e1 = expf(l1 - m);
        float sc = e1 / (e0 + e1);
        g_dscores[p] = sc;
        float x1 = g_props[p * 4], y1 = g_props[p * 4 + 1];
        float x2 = g_props[p * 4 + 2], y2 = g_props[p * 4 + 3];
        float wd = x2 - x1, h = y2 - y1;
        float cx = x1 + 0.5f * wd, cy = y1 + 0.5f * h;
        float d0 = s6[2], d1 = s6[3], d2 = s6[4], d3 = s6[5];
        float ncx = cx + d0 * wd, ncy = cy + d1 * h;
        float nw = wd * expf(d2), nh = h * expf(d3);
        dets[p * 4]     = fminf(fmaxf(ncx - 0.5f * nw, 0.f), 255.f);
        dets[p * 4 + 1] = fminf(fmaxf(ncy - 0.5f * nh, 0.f), 255.f);
        dets[p * 4 + 2] = fminf(fmaxf(ncx + 0.5f * nw, 0.f), 255.f);
        dets[p * 4 + 3] = fminf(fmaxf(ncy + 0.5f * nh, 0.f), 255.f);
        g_s2[p] = g_valid[p] ? sc : -1.0f;
    }
}

// -------- final dets/scores/keep2 + masks (fused) --------
__global__ void k_final(float* __restrict__ o_fdets, float* __restrict__ o_fsc,
                        float* __restrict__ o_keep, float* __restrict__ o_fmsk) {
    __shared__ float s_kf;
    __shared__ int s_oi;
    int r = blockIdx.x, i = threadIdx.x;
    if (i == 0) {
        int o = g_order2[r];
        int k2 = g_keep2a[r] && g_valid[o];
        float kf = k2 ? 1.f : 0.f;
        float4 d = g_sb2[r];
        o_fdets[r * 4]     = k2 ? d.x : 0.f;
        o_fdets[r * 4 + 1] = k2 ? d.y : 0.f;
        o_fdets[r * 4 + 2] = k2 ? d.z : 0.f;
        o_fdets[r * 4 + 3] = k2 ? d.w : 0.f;
        o_fsc[r] = k2 ? g_dscores[o] : 0.f;
        if (o_keep) o_keep[r] = kf;
        s_kf = kf;
        s_oi = o;
    }
    __syncthreads();
    float v = g_masks[(size_t)s_oi * 196 + i];
    float sgm = 1.f / (1.f + expf(-v));
    o_fmsk[(size_t)r * 196 + i] = sgm * s_kf;
}

// ---------------- host ----------------
extern "C" void kernel_launch(void* const* d_in, const int* in_sizes, int n_in,
                              void* d_out, int out_size) {
    const float* x      = (const float*)d_in[0];
    const float* w_bb   = (const float*)d_in[1];
    const float* b_bb   = (const float*)d_in[2];
    const float* w_rpn  = (const float*)d_in[3];
    const float* b_rpn  = (const float*)d_in[4];
    const float* w_cls  = (const float*)d_in[5];
    const float* b_cls  = (const float*)d_in[6];
    const float* w_box  = (const float*)d_in[7];
    const float* b_box  = (const float*)d_in[8];
    const float* w_fc1  = (const float*)d_in[9];
    const float* b_fc1  = (const float*)d_in[10];
    const float* w_fc2  = (const float*)d_in[11];
    const float* b_fc2  = (const float*)d_in[12];
    const float* w_rcls = (const float*)d_in[13];
    const float* b_rcls = (const float*)d_in[14];
    const float* w_rbox = (const float*)d_in[15];
    const float* b_rbox = (const float*)d_in[16];
    const float* w_m1   = (const float*)d_in[17];
    const float* b_m1   = (const float*)d_in[18];
    const float* w_m2   = (const float*)d_in[19];
    const float* b_m2   = (const float*)d_in[20];
    float* out = (float*)d_out;

    const size_t O_RPNL = 0, O_RPND = 4608, O_PROP = 13824, O_ANCH = 21824;
    const size_t O_RLOG = 31040, O_RDEL = 35040, O_RMSK = 43040;
    const size_t O_FDET = 435040, O_FMSK = 443040, O_FSC = 835040, O_KEEP = 837040;

    float *p_scores, *p_s2, *p_flat, *p_h1, *p_h2, *p_dets, *p_boxes;
    int *p_order, *p_order2, *p_keep1, *p_keep2a;
    unsigned long long *p_mask1, *p_mask2;
    __half *p_bh1, *p_bl1, *p_bh2, *p_bl2;
    cudaGetSymbolAddress((void**)&p_scores, g_scores);
    cudaGetSymbolAddress((void**)&p_order, g_order);
    cudaGetSymbolAddress((void**)&p_s2, g_s2);
    cudaGetSymbolAddress((void**)&p_order2, g_order2);
    cudaGetSymbolAddress((void**)&p_flat, g_flat);
    cudaGetSymbolAddress((void**)&p_h1, g_h1);
    cudaGetSymbolAddress((void**)&p_h2, g_h2);
    cudaGetSymbolAddress((void**)&p_dets, g_dets);
    cudaGetSymbolAddress((void**)&p_boxes, g_boxes);
    cudaGetSymbolAddress((void**)&p_keep1, g_keep1);
    cudaGetSymbolAddress((void**)&p_keep2a, g_keep2a);
    cudaGetSymbolAddress((void**)&p_mask1, g_mask1);
    cudaGetSymbolAddress((void**)&p_mask2, g_mask2);
    cudaGetSymbolAddress((void**)&p_bh1, g_bh1);
    cudaGetSymbolAddress((void**)&p_bl1, g_bl1);
    cudaGetSymbolAddress((void**)&p_bh2, g_bh2);
    cudaGetSymbolAddress((void**)&p_bl2, g_bl2);

    cudaFuncSetAttribute(k_roi, cudaFuncAttributeMaxDynamicSharedMemorySize, SMEM_ROI_BYTES);
    cudaFuncSetAttribute(k_roizero, cudaFuncAttributeMaxDynamicSharedMemorySize, SMEM_ROI_BYTES);

    float4* p_sb1; float* p_sa1; float4* p_sb2; float* p_sa2;
    cudaGetSymbolAddress((void**)&p_sb1, g_sb1);
    cudaGetSymbolAddress((void**)&p_sa1, g_sa1);
    cudaGetSymbolAddress((void**)&p_sb2, g_sb2);
    cudaGetSymbolAddress((void**)&p_sa2, g_sa2);

    k_backbone<<<256, 256>>>(x, w_bb, b_bb);
    k_packwh<<<(9 * 64 * 64 + 255) / 256, 256>>>(w_m1);
    k_packw<<<(64 * 64 * 12 + 255) / 256, 256>>>(w_rpn);
    {
        dim3 tb(32, 8);
        k_packBt<<<dim3(512 / 32, 3136 / 32), tb>>>(w_fc1, p_bh1, p_bl1, 3136, 512);
        k_packBt<<<dim3(512 / 32, 512 / 32), tb>>>(w_fc2, p_bh2, p_bl2, 512, 512);
    }
    k_roizero<<<1, 256, SMEM_ROI_BYTES>>>(b_m1, w_m2, b_m2);
    k_rpnconv<<<256, 256>>>(b_rpn);
    k_heads1<<<18, 128>>>(w_cls, b_cls, w_box, b_box,
                          out + O_RPNL, out + O_RPND, out + O_ANCH);
    k_sort<4096><<<1, 1024>>>(p_scores, NANCH, p_order, p_boxes, p_sb1, p_sa1);
    k_ioumask<NANCH, NW1><<<dim3(NW1, NW1), 64>>>(p_sb1, p_sa1, p_mask1, 0.5f);
    k_nmsreduce<NANCH, NW1><<<1, 32>>>(p_mask1, p_keep1);
    k_select1<<<1, 1024>>>(out + O_PROP);
    k_roi<<<NPROP, 256, SMEM_ROI_BYTES>>>(b_m1, w_m2, b_m2, out + O_RMSK);

    dim3 gfc(8, 32);
    k_gemmh<<<gfc, 256>>>(p_flat, p_bh1, p_bl1, b_fc1, p_h1, NPROP, 512, 3136);
    k_gemmh<<<gfc, 256>>>(p_h1, p_bh2, p_bl2, b_fc2, p_h2, NPROP, 512, 512);
    k_rheads<<<NPROP, 192>>>(w_rcls, b_rcls, w_rbox, b_rbox,
                             out + O_RLOG, out + O_RDEL, p_dets);
    k_sort<2048><<<1, 1024>>>(p_s2, NPROP, p_order2, p_dets, p_sb2, p_sa2);
    k_ioumask<NPROP, NW2><<<dim3(NW2, NW2), 64>>>(p_sb2, p_sa2, p_mask2, 0.3f);
    k_nmsreduce<NPROP, NW2><<<1, 32>>>(p_mask2, p_keep2a);
    float* o_keep = (out_size >= (int)(O_KEEP + NPROP)) ? (out + O_KEEP) : nullptr;
    k_final<<<NPROP, 196>>>(out + O_FDET, out + O_FSC, o_keep, out + O_FMSK);
}